// round 1
// baseline (speedup 1.0000x reference)
#include <cuda_runtime.h>
#include <cuda_bf16.h>

#define NN 50000
#define NE 800000

// ---------------- device scratch (static, no runtime alloc) ----------------
__device__ float g_h  [NN * 256];
__device__ float g_t  [NN * 256];
__device__ float g_x2 [NN * 256];
__device__ float g_res[NN * 256];
__device__ float g_x3 [NN * 64];
__device__ float g_x4 [NN * 16];
__device__ float g_dinv[NN];
__device__ int   g_indeg[NN];
__device__ int   g_rowstart[NN + 1];
__device__ int   g_cursor[NN];
__device__ int   g_esrc[NE];
__device__ float g_als[NN * 4];
__device__ float g_ald[NN * 4];
__device__ double g_bnsum[256];
__device__ double g_bnsq [256];
__device__ float g_mu  [256];
__device__ float g_rstd[256];
__device__ int   g_e64;

// ---------------- edge dtype detect ----------------
__global__ void detect_kernel(const void* edges) {
    const int2* q = (const int2*)edges;
    int all0 = 1;
    for (int k = 0; k < 64; k++) {
        if (q[k * 12497 + 3].y != 0) { all0 = 0; break; }
    }
    g_e64 = all0;
}

__global__ void zero_indeg() {
    int i = blockIdx.x * blockDim.x + threadIdx.x;
    if (i < NN) g_indeg[i] = 0;
}

__global__ void csr_count(const void* edges) {
    int e = blockIdx.x * blockDim.x + threadIdx.x;
    if (e >= NE) return;
    int d;
    if (g_e64) d = (int)((const long long*)edges)[NE + e];
    else       d = ((const int*)edges)[NE + e];
    atomicAdd(&g_indeg[d], 1);
}

// one-block scan: rowstart (exclusive), cursor copy, dinv
__global__ void csr_scan() {
    __shared__ int part[1024];
    const int CH = (NN + 1023) / 1024;
    int t = threadIdx.x;
    int base = t * CH;
    int s = 0;
    for (int i = 0; i < CH; i++) { int idx = base + i; if (idx < NN) s += g_indeg[idx]; }
    part[t] = s;
    __syncthreads();
    for (int off = 1; off < 1024; off <<= 1) {
        int v = (t >= off) ? part[t - off] : 0;
        __syncthreads();
        part[t] += v;
        __syncthreads();
    }
    int run = (t == 0) ? 0 : part[t - 1];
    for (int i = 0; i < CH; i++) {
        int idx = base + i;
        if (idx < NN) {
            g_rowstart[idx] = run;
            g_cursor[idx] = run;
            g_dinv[idx] = rsqrtf((float)g_indeg[idx] + 1.0f);
            run += g_indeg[idx];
        } else if (idx == NN) {
            g_rowstart[NN] = run;
        }
    }
}

__global__ void csr_place(const void* edges) {
    int e = blockIdx.x * blockDim.x + threadIdx.x;
    if (e >= NE) return;
    int s, d;
    if (g_e64) {
        s = (int)((const long long*)edges)[e];
        d = (int)((const long long*)edges)[NE + e];
    } else {
        s = ((const int*)edges)[e];
        d = ((const int*)edges)[NE + e];
    }
    int pos = atomicAdd(&g_cursor[d], 1);
    g_esrc[pos] = s;
}

// ---------------- SGEMM: C[M,Nn] = A[M,K] @ B[K,Nn] (+ bias[col]) ----------
// BM=BN=128, BK=8, TM=TN=8, 256 threads. K must be a multiple of 8.
__global__ void sgemm_kernel(const float* __restrict__ A, const float* __restrict__ B,
                             const float* __restrict__ bias, float* __restrict__ C,
                             int M, int Nn, int K) {
    __shared__ float As[8][128];
    __shared__ float Bs[8][128];
    const int tid = threadIdx.x;
    const int tr = tid >> 4, tc = tid & 15;
    const int aRow = tid >> 1, aCol = (tid & 1) << 2;
    const int bRow = tid >> 5, bCol = (tid & 31) << 2;
    const int rowBase = blockIdx.y * 128;
    const int colBase = blockIdx.x * 128;
    float acc[8][8];
#pragma unroll
    for (int i = 0; i < 8; i++)
#pragma unroll
        for (int j = 0; j < 8; j++) acc[i][j] = 0.0f;

    const int gArow = rowBase + aRow;
    const int gBcol = colBase + bCol;

    for (int k0 = 0; k0 < K; k0 += 8) {
        float4 av = make_float4(0.f, 0.f, 0.f, 0.f);
        if (gArow < M) av = *(const float4*)(A + (size_t)gArow * K + k0 + aCol);
        As[aCol + 0][aRow] = av.x;
        As[aCol + 1][aRow] = av.y;
        As[aCol + 2][aRow] = av.z;
        As[aCol + 3][aRow] = av.w;
        float4 bv = make_float4(0.f, 0.f, 0.f, 0.f);
        if (gBcol < Nn) bv = *(const float4*)(B + (size_t)(k0 + bRow) * Nn + gBcol);
        *(float4*)&Bs[bRow][bCol] = bv;
        __syncthreads();
#pragma unroll
        for (int k = 0; k < 8; k++) {
            float ar[8], br[8];
#pragma unroll
            for (int i = 0; i < 8; i++) ar[i] = As[k][tr * 8 + i];
#pragma unroll
            for (int j = 0; j < 8; j++) br[j] = Bs[k][tc * 8 + j];
#pragma unroll
            for (int i = 0; i < 8; i++)
#pragma unroll
                for (int j = 0; j < 8; j++) acc[i][j] = fmaf(ar[i], br[j], acc[i][j]);
        }
        __syncthreads();
    }
#pragma unroll
    for (int i = 0; i < 8; i++) {
        int r = rowBase + tr * 8 + i;
        if (r >= M) continue;
#pragma unroll
        for (int j = 0; j < 8; j++) {
            int c = colBase + tc * 8 + j;
            if (c < Nn) C[(size_t)r * Nn + c] = acc[i][j] + (bias ? bias[c] : 0.0f);
        }
    }
}

// ---------------- GCN gather: warp per node, C in {64,256} ------------------
template <int C>
__global__ void gcn_gather(const float* __restrict__ h, const float* __restrict__ bias,
                           float* __restrict__ out) {
    int warp = (blockIdx.x * blockDim.x + threadIdx.x) >> 5;
    int lane = threadIdx.x & 31;
    if (warp >= NN) return;
    constexpr int R = C / 32;
    float acc[R];
#pragma unroll
    for (int j = 0; j < R; j++) acc[j] = 0.0f;
    float dv = g_dinv[warp];
    int s0 = g_rowstart[warp], s1 = g_rowstart[warp + 1];
    for (int p = s0; p < s1; p++) {
        int s = g_esrc[p];
        float norm = g_dinv[s] * dv;
        const float* hp = h + (size_t)s * C;
#pragma unroll
        for (int j = 0; j < R; j++) acc[j] = fmaf(norm, hp[j * 32 + lane], acc[j]);
    }
    const float* hd = h + (size_t)warp * C;
    float self = dv * dv;
#pragma unroll
    for (int j = 0; j < R; j++) {
        int c = j * 32 + lane;
        out[(size_t)warp * C + c] = acc[j] + self * hd[c] + bias[c];
    }
}

// C=16: 4 threads per node (float4 each)
__global__ void gcn_gather16(const float* __restrict__ h, const float* __restrict__ bias,
                             float* __restrict__ out) {
    int idx = blockIdx.x * blockDim.x + threadIdx.x;
    int node = idx >> 2, q = idx & 3;
    if (node >= NN) return;
    float ax = 0.f, ay = 0.f, az = 0.f, aw = 0.f;
    float dv = g_dinv[node];
    int s0 = g_rowstart[node], s1 = g_rowstart[node + 1];
    for (int p = s0; p < s1; p++) {
        int s = g_esrc[p];
        float norm = g_dinv[s] * dv;
        float4 v = *(const float4*)(h + (size_t)s * 16 + q * 4);
        ax = fmaf(norm, v.x, ax); ay = fmaf(norm, v.y, ay);
        az = fmaf(norm, v.z, az); aw = fmaf(norm, v.w, aw);
    }
    float4 hv = *(const float4*)(h + (size_t)node * 16 + q * 4);
    float4 bv = *(const float4*)(bias + q * 4);
    float self = dv * dv;
    float4 o;
    o.x = ax + self * hv.x + bv.x;
    o.y = ay + self * hv.y + bv.y;
    o.z = az + self * hv.z + bv.z;
    o.w = aw + self * hv.w + bv.w;
    *(float4*)(out + (size_t)node * 16 + q * 4) = o;
}

// ---------------- GAT: alpha dot per node (warp per node) -------------------
__global__ void gat_alpha(const float* __restrict__ h2, const float* __restrict__ a_s,
                          const float* __restrict__ a_d) {
    __shared__ float s_as[256], s_ad[256];
    int tid = threadIdx.x;  // 128
    s_as[tid] = a_s[tid]; s_ad[tid] = a_d[tid];
    s_as[tid + 128] = a_s[tid + 128]; s_ad[tid + 128] = a_d[tid + 128];
    __syncthreads();
    int w = tid >> 5, lane = tid & 31;
    int n = blockIdx.x * 4 + w;
    if (n >= NN) return;
    float ps[4] = {0.f, 0.f, 0.f, 0.f}, pd[4] = {0.f, 0.f, 0.f, 0.f};
    const float* hp = h2 + (size_t)n * 256;
#pragma unroll
    for (int j = 0; j < 8; j++) {
        int c = j * 32 + lane;
        float v = hp[c];
        ps[j >> 1] = fmaf(v, s_as[c], ps[j >> 1]);
        pd[j >> 1] = fmaf(v, s_ad[c], pd[j >> 1]);
    }
#pragma unroll
    for (int hh = 0; hh < 4; hh++) {
#pragma unroll
        for (int off = 16; off > 0; off >>= 1) {
            ps[hh] += __shfl_xor_sync(0xffffffffu, ps[hh], off);
            pd[hh] += __shfl_xor_sync(0xffffffffu, pd[hh], off);
        }
    }
    if (lane == 0) {
        float4 a = make_float4(ps[0], ps[1], ps[2], ps[3]);
        *(float4*)(g_als + (size_t)n * 4) = a;
        float4 b = make_float4(pd[0], pd[1], pd[2], pd[3]);
        *(float4*)(g_ald + (size_t)n * 4) = b;
    }
}

// ---------------- GAT gather: warp per node, fused softmax+agg+mean ---------
__global__ void gat_gather(const float* __restrict__ h2, const float* __restrict__ bg,
                           float* __restrict__ out) {
    int warp = (blockIdx.x * blockDim.x + threadIdx.x) >> 5;
    int lane = threadIdx.x & 31;
    if (warp >= NN) return;
    float4 adv = *(const float4*)(g_ald + (size_t)warp * 4);
    float4 asv = *(const float4*)(g_als + (size_t)warp * 4);
    float ad[4] = {adv.x, adv.y, adv.z, adv.w};
    float eself[4];
    {
        float as_[4] = {asv.x, asv.y, asv.z, asv.w};
#pragma unroll
        for (int hh = 0; hh < 4; hh++) {
            float lg = as_[hh] + ad[hh];
            eself[hh] = lg > 0.f ? lg : 0.2f * lg;
        }
    }
    int s0 = g_rowstart[warp], s1 = g_rowstart[warp + 1];
    // pass A: max logit per head (incl. self)
    float m[4] = {eself[0], eself[1], eself[2], eself[3]};
    for (int p = s0 + lane; p < s1; p += 32) {
        int s = g_esrc[p];
        float4 a = *(const float4*)(g_als + (size_t)s * 4);
        float lg;
        lg = a.x + ad[0]; m[0] = fmaxf(m[0], lg > 0.f ? lg : 0.2f * lg);
        lg = a.y + ad[1]; m[1] = fmaxf(m[1], lg > 0.f ? lg : 0.2f * lg);
        lg = a.z + ad[2]; m[2] = fmaxf(m[2], lg > 0.f ? lg : 0.2f * lg);
        lg = a.w + ad[3]; m[3] = fmaxf(m[3], lg > 0.f ? lg : 0.2f * lg);
    }
#pragma unroll
    for (int hh = 0; hh < 4; hh++)
#pragma unroll
        for (int off = 16; off > 0; off >>= 1)
            m[hh] = fmaxf(m[hh], __shfl_xor_sync(0xffffffffu, m[hh], off));

    // pass B: exp-weighted aggregation (exp only on lanes 0..3, broadcast)
    float adL = ad[0], mL = m[0];
    if (lane == 1) { adL = ad[1]; mL = m[1]; }
    else if (lane == 2) { adL = ad[2]; mL = m[2]; }
    else if (lane == 3) { adL = ad[3]; mL = m[3]; }
    float acc[8] = {0.f, 0.f, 0.f, 0.f, 0.f, 0.f, 0.f, 0.f};
    float denL = 0.f;
    for (int p = s0; p < s1; p++) {
        int s = g_esrc[p];
        float ee = 0.f;
        if (lane < 4) {
            float a = g_als[(size_t)s * 4 + lane];
            float lg = a + adL;
            lg = lg > 0.f ? lg : 0.2f * lg;
            ee = __expf(lg - mL);
            denL += ee;
        }
        float ee0 = __shfl_sync(0xffffffffu, ee, 0);
        float ee1 = __shfl_sync(0xffffffffu, ee, 1);
        float ee2 = __shfl_sync(0xffffffffu, ee, 2);
        float ee3 = __shfl_sync(0xffffffffu, ee, 3);
        const float* hp = h2 + (size_t)s * 256;
        acc[0] = fmaf(ee0, hp[lane], acc[0]);
        acc[1] = fmaf(ee0, hp[32 + lane], acc[1]);
        acc[2] = fmaf(ee1, hp[64 + lane], acc[2]);
        acc[3] = fmaf(ee1, hp[96 + lane], acc[3]);
        acc[4] = fmaf(ee2, hp[128 + lane], acc[4]);
        acc[5] = fmaf(ee2, hp[160 + lane], acc[5]);
        acc[6] = fmaf(ee3, hp[192 + lane], acc[6]);
        acc[7] = fmaf(ee3, hp[224 + lane], acc[7]);
    }
    float es[4], den[4];
#pragma unroll
    for (int hh = 0; hh < 4; hh++) {
        es[hh] = __expf(eself[hh] - m[hh]);
        den[hh] = __shfl_sync(0xffffffffu, denL, hh) + es[hh];
    }
    const float* hd = h2 + (size_t)warp * 256;
    float o0 = 0.f, o1 = 0.f;
#pragma unroll
    for (int hh = 0; hh < 4; hh++) {
        o0 += (acc[2 * hh]     + es[hh] * hd[hh * 64 + lane])      / den[hh];
        o1 += (acc[2 * hh + 1] + es[hh] * hd[hh * 64 + 32 + lane]) / den[hh];
    }
    out[(size_t)warp * 64 + lane]      = 0.25f * o0 + bg[lane];
    out[(size_t)warp * 64 + 32 + lane] = 0.25f * o1 + bg[32 + lane];
}

// ---------------- BatchNorm ----------------
__global__ void bn_zero() {
    int t = threadIdx.x;
    g_bnsum[t] = 0.0;
    g_bnsq[t] = 0.0;
}

template <int C>
__global__ void bn_stats(const float* __restrict__ x) {
    const int R = 256 / C;
    int c = threadIdx.x % C, sub = threadIdx.x / C;
    double s = 0.0, s2 = 0.0;
    for (int r = blockIdx.x * R + sub; r < NN; r += gridDim.x * R) {
        float v = x[(size_t)r * C + c];
        s += (double)v;
        s2 += (double)v * (double)v;
    }
    __shared__ double sh[256], sh2[256];
    sh[threadIdx.x] = s;
    sh2[threadIdx.x] = s2;
    __syncthreads();
    if (sub == 0) {
        for (int i = 1; i < R; i++) { s += sh[i * C + c]; s2 += sh2[i * C + c]; }
        atomicAdd(&g_bnsum[c], s);
        atomicAdd(&g_bnsq[c], s2);
    }
}

__global__ void bn_final(int C, float invN) {
    int c = threadIdx.x;
    if (c >= C) return;
    double m = g_bnsum[c] * (double)invN;
    double v = g_bnsq[c] * (double)invN - m * m;
    g_mu[c] = (float)m;
    g_rstd[c] = rsqrtf((float)v + 1e-5f);
}

// BN + leaky(0.01) + residual add
template <int C>
__global__ void fuse_bn_res(const float* __restrict__ t, const float* __restrict__ res,
                            const float* __restrict__ g, const float* __restrict__ be,
                            float* __restrict__ out) {
    int idx = blockIdx.x * blockDim.x + threadIdx.x;
    if (idx >= NN * C) return;
    int c = idx % C;
    float v = (t[idx] - g_mu[c]) * g_rstd[c] * g[c] + be[c];
    v = v > 0.f ? v : 0.01f * v;
    out[idx] = v + res[idx];
}

// ---------------- host ----------------
static inline int cdiv(int a, int b) { return (a + b - 1) / b; }

extern "C" void kernel_launch(void* const* d_in, const int* in_sizes, int n_in,
                              void* d_out, int out_size) {
    const float* x    = (const float*)d_in[0];
    const void*  edges = d_in[1];
    const float* W1   = (const float*)d_in[2];
    const float* b1   = (const float*)d_in[3];
    const float* g1   = (const float*)d_in[4];
    const float* be1  = (const float*)d_in[5];
    const float* Wg   = (const float*)d_in[6];
    const float* a_src = (const float*)d_in[7];
    const float* a_dst = (const float*)d_in[8];
    const float* bg   = (const float*)d_in[9];
    const float* g2   = (const float*)d_in[10];
    const float* be2  = (const float*)d_in[11];
    const float* W3   = (const float*)d_in[12];
    const float* b3   = (const float*)d_in[13];
    const float* g3   = (const float*)d_in[14];
    const float* be3  = (const float*)d_in[15];
    const float* W4   = (const float*)d_in[16];
    const float* b4   = (const float*)d_in[17];
    const float* r1W  = (const float*)d_in[18];
    const float* r1b  = (const float*)d_in[19];
    const float* r2W  = (const float*)d_in[20];
    const float* r2b  = (const float*)d_in[21];
    const float* r3W  = (const float*)d_in[22];
    const float* r3b  = (const float*)d_in[23];
    const float* pW   = (const float*)d_in[24];
    const float* pb   = (const float*)d_in[25];
    float* out = (float*)d_out;

    float *h, *t, *x2, *res, *x3, *x4;
    cudaGetSymbolAddress((void**)&h,   g_h);
    cudaGetSymbolAddress((void**)&t,   g_t);
    cudaGetSymbolAddress((void**)&x2,  g_x2);
    cudaGetSymbolAddress((void**)&res, g_res);
    cudaGetSymbolAddress((void**)&x3,  g_x3);
    cudaGetSymbolAddress((void**)&x4,  g_x4);

    const float invN = 1.0f / (float)NN;

    // ---- CSR build (per launch; edges static) ----
    detect_kernel<<<1, 1>>>(edges);
    zero_indeg<<<cdiv(NN, 256), 256>>>();
    csr_count<<<cdiv(NE, 256), 256>>>(edges);
    csr_scan<<<1, 1024>>>();
    csr_place<<<cdiv(NE, 256), 256>>>(edges);

    // ---- Stage 1: GCN(256->256) + BN + leaky + residual ----
    sgemm_kernel<<<dim3(2, cdiv(NN, 128)), 256>>>(x, W1, nullptr, h, NN, 256, 256);
    gcn_gather<256><<<cdiv(NN * 32, 256), 256>>>(h, b1, t);
    bn_zero<<<1, 256>>>();
    bn_stats<256><<<500, 256>>>(t);
    bn_final<<<1, 256>>>(256, invN);
    sgemm_kernel<<<dim3(2, cdiv(NN, 128)), 256>>>(x, r1W, r1b, res, NN, 256, 256);
    fuse_bn_res<256><<<cdiv(NN * 256, 256), 256>>>(t, res, g1, be1, x2);

    // ---- Stage 2: GAT(4 heads, mean) + BN + leaky + residual ----
    sgemm_kernel<<<dim3(2, cdiv(NN, 128)), 256>>>(x2, Wg, nullptr, h, NN, 256, 256);
    gat_alpha<<<cdiv(NN, 4), 128>>>(h, a_src, a_dst);
    gat_gather<<<cdiv(NN * 32, 256), 256>>>(h, bg, t);
    bn_zero<<<1, 256>>>();
    bn_stats<64><<<500, 256>>>(t);
    bn_final<<<1, 256>>>(64, invN);
    sgemm_kernel<<<dim3(1, cdiv(NN, 128)), 256>>>(x2, r2W, r2b, res, NN, 64, 256);
    fuse_bn_res<64><<<cdiv(NN * 64, 256), 256>>>(t, res, g2, be2, x3);

    // ---- Stage 3: GCN(64->16) + BN + leaky + residual ----
    sgemm_kernel<<<dim3(1, cdiv(NN, 128)), 256>>>(x3, W3, nullptr, h, NN, 16, 64);
    gcn_gather16<<<cdiv(NN * 4, 256), 256>>>(h, b3, t);
    bn_zero<<<1, 256>>>();
    bn_stats<16><<<500, 256>>>(t);
    bn_final<<<1, 256>>>(16, invN);
    sgemm_kernel<<<dim3(1, cdiv(NN, 128)), 256>>>(x3, r3W, r3b, res, NN, 16, 64);
    fuse_bn_res<16><<<cdiv(NN * 16, 256), 256>>>(t, res, g3, be3, x4);

    // ---- Stage 4: GCN(16->64), then final linear ----
    sgemm_kernel<<<dim3(1, cdiv(NN, 128)), 256>>>(x4, W4, nullptr, h, NN, 64, 16);
    gcn_gather<64><<<cdiv(NN * 32, 256), 256>>>(h, b4, t);
    sgemm_kernel<<<dim3(1, cdiv(NN, 128)), 256>>>(t, pW, pb, out, NN, 64, 64);
}

// round 3
// speedup vs baseline: 1.7296x; 1.7296x over previous
#include <cuda_runtime.h>
#include <cuda_bf16.h>
#include <cstdint>

#define NN 50000
#define NE 800000
#define NB196 196   // ceil(NN/256)

// ---------------- device scratch (static, no runtime alloc) ----------------
__device__ float g_h  [NN * 256];
__device__ float g_t  [NN * 256];
__device__ float g_x2 [NN * 256];
__device__ float g_res[NN * 256];
__device__ float g_x3 [NN * 64];
__device__ float g_x4 [NN * 16];
__device__ float g_dinv[NN];
__device__ int   g_indeg[NN];
__device__ int   g_rowstart[NN + 1];
__device__ int   g_cursor[NN];
__device__ int   g_esrc[NE];
__device__ int   g_scanpart[NN];
__device__ int   g_blocksum[NB196];
__device__ int   g_blockoff[NB196];
__device__ float g_als[NN * 4];
__device__ float g_ald[NN * 4];
__device__ double g_bnsum[256];
__device__ double g_bnsq [256];
__device__ float g_mu  [256];
__device__ float g_rstd[256];
__device__ int   g_e64;

// ---------------- edge dtype detect ----------------
__global__ void detect_kernel(const void* edges) {
    const int2* q = (const int2*)edges;
    int all0 = 1;
    for (int k = 0; k < 64; k++) {
        if (q[k * 12497 + 3].y != 0) { all0 = 0; break; }
    }
    g_e64 = all0;
}

__global__ void zero_indeg() {
    int i = blockIdx.x * blockDim.x + threadIdx.x;
    if (i < NN) g_indeg[i] = 0;
}

__global__ void csr_count(const void* edges) {
    int e = blockIdx.x * blockDim.x + threadIdx.x;
    if (e >= NE) return;
    int d;
    if (g_e64) d = (int)((const long long*)edges)[NE + e];
    else       d = ((const int*)edges)[NE + e];
    atomicAdd(&g_indeg[d], 1);
}

// ---------------- parallel exclusive scan over indeg (3 kernels) -----------
__global__ void scan1() {
    int b = blockIdx.x, t = threadIdx.x;
    int i = b * 256 + t;
    int d = (i < NN) ? g_indeg[i] : 0;
    int lane = t & 31, w = t >> 5;
    int v = d;
#pragma unroll
    for (int off = 1; off < 32; off <<= 1) {
        int u = __shfl_up_sync(0xffffffffu, v, off);
        if (lane >= off) v += u;
    }
    __shared__ int ws[8];
    if (lane == 31) ws[w] = v;
    __syncthreads();
    if (t == 0) {
        int run = 0;
        for (int j = 0; j < 8; j++) { int x = ws[j]; ws[j] = run; run += x; }
    }
    __syncthreads();
    v += ws[w];
    if (i < NN) g_scanpart[i] = v;          // inclusive within block
    if (t == 255) g_blocksum[b] = v;        // block total
}

__global__ void scan2() {
    int t = threadIdx.x;
    int d = (t < NB196) ? g_blocksum[t] : 0;
    int lane = t & 31, w = t >> 5;
    int v = d;
#pragma unroll
    for (int off = 1; off < 32; off <<= 1) {
        int u = __shfl_up_sync(0xffffffffu, v, off);
        if (lane >= off) v += u;
    }
    __shared__ int ws[8];
    if (lane == 31) ws[w] = v;
    __syncthreads();
    if (t == 0) {
        int run = 0;
        for (int j = 0; j < 8; j++) { int x = ws[j]; ws[j] = run; run += x; }
    }
    __syncthreads();
    v += ws[w];
    if (t < NB196) g_blockoff[t] = v - d;   // exclusive block offset
}

__global__ void scan3() {
    int i = blockIdx.x * blockDim.x + threadIdx.x;
    if (i < NN) {
        int deg = g_indeg[i];
        int excl = g_blockoff[blockIdx.x] + g_scanpart[i] - deg;
        g_rowstart[i] = excl;
        g_cursor[i] = excl;
        g_dinv[i] = rsqrtf((float)deg + 1.0f);
    }
    if (i == 0) g_rowstart[NN] = NE;
}

__global__ void csr_place(const void* edges) {
    int e = blockIdx.x * blockDim.x + threadIdx.x;
    if (e >= NE) return;
    int s, d;
    if (g_e64) {
        s = (int)((const long long*)edges)[e];
        d = (int)((const long long*)edges)[NE + e];
    } else {
        s = ((const int*)edges)[e];
        d = ((const int*)edges)[NE + e];
    }
    int pos = atomicAdd(&g_cursor[d], 1);
    g_esrc[pos] = s;
}

// ---------------- tf32 tensor-core GEMM -------------------------------------
// C[M,Nn] = A[M,K] @ B[K,Nn] (+bias). K % 32 == 0. Block tile 128x128x32.
// 256 threads = 8 warps in 4(M) x 2(N); warp tile 32x64; mma m16n8k8 tf32.
__device__ __forceinline__ uint32_t f2tf32(float x) {
    uint32_t r;
    asm("cvt.rna.tf32.f32 %0, %1;" : "=r"(r) : "f"(x));
    return r;
}

__global__ __launch_bounds__(256, 2)
void tf32_gemm(const float* __restrict__ A, const float* __restrict__ B,
               const float* __restrict__ bias, float* __restrict__ C,
               int M, int Nn, int K) {
    __shared__ uint32_t As[128 * 36];   // row stride 36 (32 + pad 4)
    __shared__ uint32_t Bs[32 * 136];   // row stride 136 (128 + pad 8)
    const int tid = threadIdx.x;
    const int warp = tid >> 5, lane = tid & 31;
    const int wm = warp >> 1, wn = warp & 1;
    const int g = lane >> 2, t4 = lane & 3;
    const int rowBase = blockIdx.y * 128;
    const int colBase = blockIdx.x * 128;

    float acc[2][8][4];
#pragma unroll
    for (int mi = 0; mi < 2; mi++)
#pragma unroll
        for (int ni = 0; ni < 8; ni++)
#pragma unroll
            for (int j = 0; j < 4; j++) acc[mi][ni][j] = 0.0f;

    for (int k0 = 0; k0 < K; k0 += 32) {
        // load A tile 128x32
#pragma unroll
        for (int i = 0; i < 4; i++) {
            int idx = i * 256 + tid;
            int r = idx >> 3, c4 = (idx & 7) * 4;
            float4 v = make_float4(0.f, 0.f, 0.f, 0.f);
            if (rowBase + r < M) v = *(const float4*)(A + (size_t)(rowBase + r) * K + k0 + c4);
            uint4 w;
            w.x = f2tf32(v.x); w.y = f2tf32(v.y); w.z = f2tf32(v.z); w.w = f2tf32(v.w);
            *(uint4*)&As[r * 36 + c4] = w;
        }
        // load B tile 32x128
#pragma unroll
        for (int i = 0; i < 4; i++) {
            int idx = i * 256 + tid;
            int r = idx >> 5, c4 = (idx & 31) * 4;
            float4 v = make_float4(0.f, 0.f, 0.f, 0.f);
            if (colBase + c4 < Nn) v = *(const float4*)(B + (size_t)(k0 + r) * Nn + colBase + c4);
            uint4 w;
            w.x = f2tf32(v.x); w.y = f2tf32(v.y); w.z = f2tf32(v.z); w.w = f2tf32(v.w);
            *(uint4*)&Bs[r * 136 + c4] = w;
        }
        __syncthreads();

#pragma unroll
        for (int kk = 0; kk < 32; kk += 8) {
            uint32_t af[2][4];
#pragma unroll
            for (int mi = 0; mi < 2; mi++) {
                int r = wm * 32 + mi * 16;
                af[mi][0] = As[(r + g) * 36 + kk + t4];
                af[mi][1] = As[(r + g + 8) * 36 + kk + t4];
                af[mi][2] = As[(r + g) * 36 + kk + t4 + 4];
                af[mi][3] = As[(r + g + 8) * 36 + kk + t4 + 4];
            }
            uint32_t bf[8][2];
#pragma unroll
            for (int ni = 0; ni < 8; ni++) {
                int c = wn * 64 + ni * 8 + g;
                bf[ni][0] = Bs[(kk + t4) * 136 + c];
                bf[ni][1] = Bs[(kk + t4 + 4) * 136 + c];
            }
#pragma unroll
            for (int mi = 0; mi < 2; mi++)
#pragma unroll
                for (int ni = 0; ni < 8; ni++) {
                    asm volatile(
                        "mma.sync.aligned.m16n8k8.row.col.f32.tf32.tf32.f32 "
                        "{%0,%1,%2,%3}, {%4,%5,%6,%7}, {%8,%9}, {%0,%1,%2,%3};"
                        : "+f"(acc[mi][ni][0]), "+f"(acc[mi][ni][1]),
                          "+f"(acc[mi][ni][2]), "+f"(acc[mi][ni][3])
                        : "r"(af[mi][0]), "r"(af[mi][1]), "r"(af[mi][2]), "r"(af[mi][3]),
                          "r"(bf[ni][0]), "r"(bf[ni][1]));
                }
        }
        __syncthreads();
    }

    // epilogue
#pragma unroll
    for (int mi = 0; mi < 2; mi++) {
#pragma unroll
        for (int ni = 0; ni < 8; ni++) {
            int r0 = rowBase + wm * 32 + mi * 16 + g;
            int c0 = colBase + wn * 64 + ni * 8 + t4 * 2;
            if (c0 >= Nn) continue;
            float bx = bias ? bias[c0] : 0.0f;
            float by = bias ? bias[c0 + 1] : 0.0f;
            if (r0 < M) {
                float2 o = make_float2(acc[mi][ni][0] + bx, acc[mi][ni][1] + by);
                *(float2*)(C + (size_t)r0 * Nn + c0) = o;
            }
            if (r0 + 8 < M) {
                float2 o = make_float2(acc[mi][ni][2] + bx, acc[mi][ni][3] + by);
                *(float2*)(C + (size_t)(r0 + 8) * Nn + c0) = o;
            }
        }
    }
}

// ---------------- SGEMM (FFMA) for small layers ----------------------------
__global__ void sgemm_kernel(const float* __restrict__ A, const float* __restrict__ B,
                             const float* __restrict__ bias, float* __restrict__ C,
                             int M, int Nn, int K) {
    __shared__ float As[8][128];
    __shared__ float Bs[8][128];
    const int tid = threadIdx.x;
    const int tr = tid >> 4, tc = tid & 15;
    const int aRow = tid >> 1, aCol = (tid & 1) << 2;
    const int bRow = tid >> 5, bCol = (tid & 31) << 2;
    const int rowBase = blockIdx.y * 128;
    const int colBase = blockIdx.x * 128;
    float acc[8][8];
#pragma unroll
    for (int i = 0; i < 8; i++)
#pragma unroll
        for (int j = 0; j < 8; j++) acc[i][j] = 0.0f;

    const int gArow = rowBase + aRow;
    const int gBcol = colBase + bCol;

    for (int k0 = 0; k0 < K; k0 += 8) {
        float4 av = make_float4(0.f, 0.f, 0.f, 0.f);
        if (gArow < M) av = *(const float4*)(A + (size_t)gArow * K + k0 + aCol);
        As[aCol + 0][aRow] = av.x;
        As[aCol + 1][aRow] = av.y;
        As[aCol + 2][aRow] = av.z;
        As[aCol + 3][aRow] = av.w;
        float4 bv = make_float4(0.f, 0.f, 0.f, 0.f);
        if (gBcol < Nn) bv = *(const float4*)(B + (size_t)(k0 + bRow) * Nn + gBcol);
        *(float4*)&Bs[bRow][bCol] = bv;
        __syncthreads();
#pragma unroll
        for (int k = 0; k < 8; k++) {
            float ar[8], br[8];
#pragma unroll
            for (int i = 0; i < 8; i++) ar[i] = As[k][tr * 8 + i];
#pragma unroll
            for (int j = 0; j < 8; j++) br[j] = Bs[k][tc * 8 + j];
#pragma unroll
            for (int i = 0; i < 8; i++)
#pragma unroll
                for (int j = 0; j < 8; j++) acc[i][j] = fmaf(ar[i], br[j], acc[i][j]);
        }
        __syncthreads();
    }
#pragma unroll
    for (int i = 0; i < 8; i++) {
        int r = rowBase + tr * 8 + i;
        if (r >= M) continue;
#pragma unroll
        for (int j = 0; j < 8; j++) {
            int c = colBase + tc * 8 + j;
            if (c < Nn) C[(size_t)r * Nn + c] = acc[i][j] + (bias ? bias[c] : 0.0f);
        }
    }
}

// ---------------- GCN gather: warp per node, C in {64,256} ------------------
template <int C>
__global__ void gcn_gather(const float* __restrict__ h, const float* __restrict__ bias,
                           float* __restrict__ out) {
    int warp = (blockIdx.x * blockDim.x + threadIdx.x) >> 5;
    int lane = threadIdx.x & 31;
    if (warp >= NN) return;
    constexpr int R = C / 32;
    float acc[R];
#pragma unroll
    for (int j = 0; j < R; j++) acc[j] = 0.0f;
    float dv = g_dinv[warp];
    int s0 = g_rowstart[warp], s1 = g_rowstart[warp + 1];
    for (int p = s0; p < s1; p++) {
        int s = g_esrc[p];
        float norm = g_dinv[s] * dv;
        const float* hp = h + (size_t)s * C;
#pragma unroll
        for (int j = 0; j < R; j++) acc[j] = fmaf(norm, hp[j * 32 + lane], acc[j]);
    }
    const float* hd = h + (size_t)warp * C;
    float self = dv * dv;
#pragma unroll
    for (int j = 0; j < R; j++) {
        int c = j * 32 + lane;
        out[(size_t)warp * C + c] = acc[j] + self * hd[c] + bias[c];
    }
}

// C=16: 4 threads per node (float4 each)
__global__ void gcn_gather16(const float* __restrict__ h, const float* __restrict__ bias,
                             float* __restrict__ out) {
    int idx = blockIdx.x * blockDim.x + threadIdx.x;
    int node = idx >> 2, q = idx & 3;
    if (node >= NN) return;
    float ax = 0.f, ay = 0.f, az = 0.f, aw = 0.f;
    float dv = g_dinv[node];
    int s0 = g_rowstart[node], s1 = g_rowstart[node + 1];
    for (int p = s0; p < s1; p++) {
        int s = g_esrc[p];
        float norm = g_dinv[s] * dv;
        float4 v = *(const float4*)(h + (size_t)s * 16 + q * 4);
        ax = fmaf(norm, v.x, ax); ay = fmaf(norm, v.y, ay);
        az = fmaf(norm, v.z, az); aw = fmaf(norm, v.w, aw);
    }
    float4 hv = *(const float4*)(h + (size_t)node * 16 + q * 4);
    float4 bv = *(const float4*)(bias + q * 4);
    float self = dv * dv;
    float4 o;
    o.x = ax + self * hv.x + bv.x;
    o.y = ay + self * hv.y + bv.y;
    o.z = az + self * hv.z + bv.z;
    o.w = aw + self * hv.w + bv.w;
    *(float4*)(out + (size_t)node * 16 + q * 4) = o;
}

// ---------------- GAT: alpha dot per node (warp per node) -------------------
__global__ void gat_alpha(const float* __restrict__ h2, const float* __restrict__ a_s,
                          const float* __restrict__ a_d) {
    __shared__ float s_as[256], s_ad[256];
    int tid = threadIdx.x;  // 128
    s_as[tid] = a_s[tid]; s_ad[tid] = a_d[tid];
    s_as[tid + 128] = a_s[tid + 128]; s_ad[tid + 128] = a_d[tid + 128];
    __syncthreads();
    int w = tid >> 5, lane = tid & 31;
    int n = blockIdx.x * 4 + w;
    if (n >= NN) return;
    float ps[4] = {0.f, 0.f, 0.f, 0.f}, pd[4] = {0.f, 0.f, 0.f, 0.f};
    const float* hp = h2 + (size_t)n * 256;
#pragma unroll
    for (int j = 0; j < 8; j++) {
        int c = j * 32 + lane;
        float v = hp[c];
        ps[j >> 1] = fmaf(v, s_as[c], ps[j >> 1]);
        pd[j >> 1] = fmaf(v, s_ad[c], pd[j >> 1]);
    }
#pragma unroll
    for (int hh = 0; hh < 4; hh++) {
#pragma unroll
        for (int off = 16; off > 0; off >>= 1) {
            ps[hh] += __shfl_xor_sync(0xffffffffu, ps[hh], off);
            pd[hh] += __shfl_xor_sync(0xffffffffu, pd[hh], off);
        }
    }
    if (lane == 0) {
        float4 a = make_float4(ps[0], ps[1], ps[2], ps[3]);
        *(float4*)(g_als + (size_t)n * 4) = a;
        float4 b = make_float4(pd[0], pd[1], pd[2], pd[3]);
        *(float4*)(g_ald + (size_t)n * 4) = b;
    }
}

// ---------------- GAT gather: warp per node, fused softmax+agg+mean ---------
__global__ void gat_gather(const float* __restrict__ h2, const float* __restrict__ bg,
                           float* __restrict__ out) {
    int warp = (blockIdx.x * blockDim.x + threadIdx.x) >> 5;
    int lane = threadIdx.x & 31;
    if (warp >= NN) return;
    float4 adv = *(const float4*)(g_ald + (size_t)warp * 4);
    float4 asv = *(const float4*)(g_als + (size_t)warp * 4);
    float ad[4] = {adv.x, adv.y, adv.z, adv.w};
    float eself[4];
    {
        float as_[4] = {asv.x, asv.y, asv.z, asv.w};
#pragma unroll
        for (int hh = 0; hh < 4; hh++) {
            float lg = as_[hh] + ad[hh];
            eself[hh] = lg > 0.f ? lg : 0.2f * lg;
        }
    }
    int s0 = g_rowstart[warp], s1 = g_rowstart[warp + 1];
    // pass A: max logit per head (incl. self)
    float m[4] = {eself[0], eself[1], eself[2], eself[3]};
    for (int p = s0 + lane; p < s1; p += 32) {
        int s = g_esrc[p];
        float4 a = *(const float4*)(g_als + (size_t)s * 4);
        float lg;
        lg = a.x + ad[0]; m[0] = fmaxf(m[0], lg > 0.f ? lg : 0.2f * lg);
        lg = a.y + ad[1]; m[1] = fmaxf(m[1], lg > 0.f ? lg : 0.2f * lg);
        lg = a.z + ad[2]; m[2] = fmaxf(m[2], lg > 0.f ? lg : 0.2f * lg);
        lg = a.w + ad[3]; m[3] = fmaxf(m[3], lg > 0.f ? lg : 0.2f * lg);
    }
#pragma unroll
    for (int hh = 0; hh < 4; hh++)
#pragma unroll
        for (int off = 16; off > 0; off >>= 1)
            m[hh] = fmaxf(m[hh], __shfl_xor_sync(0xffffffffu, m[hh], off));

    // pass B: exp-weighted aggregation (exp only on lanes 0..3, broadcast)
    float adL = ad[0], mL = m[0];
    if (lane == 1) { adL = ad[1]; mL = m[1]; }
    else if (lane == 2) { adL = ad[2]; mL = m[2]; }
    else if (lane == 3) { adL = ad[3]; mL = m[3]; }
    float acc[8] = {0.f, 0.f, 0.f, 0.f, 0.f, 0.f, 0.f, 0.f};
    float denL = 0.f;
    for (int p = s0; p < s1; p++) {
        int s = g_esrc[p];
        float ee = 0.f;
        if (lane < 4) {
            float a = g_als[(size_t)s * 4 + lane];
            float lg = a + adL;
            lg = lg > 0.f ? lg : 0.2f * lg;
            ee = __expf(lg - mL);
            denL += ee;
        }
        float ee0 = __shfl_sync(0xffffffffu, ee, 0);
        float ee1 = __shfl_sync(0xffffffffu, ee, 1);
        float ee2 = __shfl_sync(0xffffffffu, ee, 2);
        float ee3 = __shfl_sync(0xffffffffu, ee, 3);
        const float* hp = h2 + (size_t)s * 256;
        acc[0] = fmaf(ee0, hp[lane], acc[0]);
        acc[1] = fmaf(ee0, hp[32 + lane], acc[1]);
        acc[2] = fmaf(ee1, hp[64 + lane], acc[2]);
        acc[3] = fmaf(ee1, hp[96 + lane], acc[3]);
        acc[4] = fmaf(ee2, hp[128 + lane], acc[4]);
        acc[5] = fmaf(ee2, hp[160 + lane], acc[5]);
        acc[6] = fmaf(ee3, hp[192 + lane], acc[6]);
        acc[7] = fmaf(ee3, hp[224 + lane], acc[7]);
    }
    float es[4], den[4];
#pragma unroll
    for (int hh = 0; hh < 4; hh++) {
        es[hh] = __expf(eself[hh] - m[hh]);
        den[hh] = __shfl_sync(0xffffffffu, denL, hh) + es[hh];
    }
    const float* hd = h2 + (size_t)warp * 256;
    float o0 = 0.f, o1 = 0.f;
#pragma unroll
    for (int hh = 0; hh < 4; hh++) {
        o0 += (acc[2 * hh]     + es[hh] * hd[hh * 64 + lane])      / den[hh];
        o1 += (acc[2 * hh + 1] + es[hh] * hd[hh * 64 + 32 + lane]) / den[hh];
    }
    out[(size_t)warp * 64 + lane]      = 0.25f * o0 + bg[lane];
    out[(size_t)warp * 64 + 32 + lane] = 0.25f * o1 + bg[32 + lane];
}

// ---------------- BatchNorm ----------------
__global__ void bn_zero() {
    int t = threadIdx.x;
    g_bnsum[t] = 0.0;
    g_bnsq[t] = 0.0;
}

template <int C>
__global__ void bn_stats(const float* __restrict__ x) {
    const int R = 256 / C;
    int c = threadIdx.x % C, sub = threadIdx.x / C;
    double s = 0.0, s2 = 0.0;
    for (int r = blockIdx.x * R + sub; r < NN; r += gridDim.x * R) {
        float v = x[(size_t)r * C + c];
        s += (double)v;
        s2 += (double)v * (double)v;
    }
    __shared__ double sh[256], sh2[256];
    sh[threadIdx.x] = s;
    sh2[threadIdx.x] = s2;
    __syncthreads();
    if (sub == 0) {
        for (int i = 1; i < R; i++) { s += sh[i * C + c]; s2 += sh2[i * C + c]; }
        atomicAdd(&g_bnsum[c], s);
        atomicAdd(&g_bnsq[c], s2);
    }
}

__global__ void bn_final(int C, float invN) {
    int c = threadIdx.x;
    if (c >= C) return;
    double m = g_bnsum[c] * (double)invN;
    double v = g_bnsq[c] * (double)invN - m * m;
    g_mu[c] = (float)m;
    g_rstd[c] = rsqrtf((float)v + 1e-5f);
}

// BN + leaky(0.01) + residual add
template <int C>
__global__ void fuse_bn_res(const float* __restrict__ t, const float* __restrict__ res,
                            const float* __restrict__ g, const float* __restrict__ be,
                            float* __restrict__ out) {
    int idx = blockIdx.x * blockDim.x + threadIdx.x;
    if (idx >= NN * C) return;
    int c = idx % C;
    float v = (t[idx] - g_mu[c]) * g_rstd[c] * g[c] + be[c];
    v = v > 0.f ? v : 0.01f * v;
    out[idx] = v + res[idx];
}

// ---------------- host ----------------
static inline int cdiv(int a, int b) { return (a + b - 1) / b; }

extern "C" void kernel_launch(void* const* d_in, const int* in_sizes, int n_in,
                              void* d_out, int out_size) {
    const float* x    = (const float*)d_in[0];
    const void*  edges = d_in[1];
    const float* W1   = (const float*)d_in[2];
    const float* b1   = (const float*)d_in[3];
    const float* g1   = (const float*)d_in[4];
    const float* be1  = (const float*)d_in[5];
    const float* Wg   = (const float*)d_in[6];
    const float* a_src = (const float*)d_in[7];
    const float* a_dst = (const float*)d_in[8];
    const float* bg   = (const float*)d_in[9];
    const float* g2   = (const float*)d_in[10];
    const float* be2  = (const float*)d_in[11];
    const float* W3   = (const float*)d_in[12];
    const float* b3   = (const float*)d_in[13];
    const float* g3   = (const float*)d_in[14];
    const float* be3  = (const float*)d_in[15];
    const float* W4   = (const float*)d_in[16];
    const float* b4   = (const float*)d_in[17];
    const float* r1W  = (const float*)d_in[18];
    const float* r1b  = (const float*)d_in[19];
    const float* r2W  = (const float*)d_in[20];
    const float* r2b  = (const float*)d_in[21];
    const float* r3W  = (const float*)d_in[22];
    const float* r3b  = (const float*)d_in[23];
    const float* pW   = (const float*)d_in[24];
    const float* pb   = (const float*)d_in[25];
    float* out = (float*)d_out;

    float *h, *t, *x2, *res, *x3, *x4;
    cudaGetSymbolAddress((void**)&h,   g_h);
    cudaGetSymbolAddress((void**)&t,   g_t);
    cudaGetSymbolAddress((void**)&x2,  g_x2);
    cudaGetSymbolAddress((void**)&res, g_res);
    cudaGetSymbolAddress((void**)&x3,  g_x3);
    cudaGetSymbolAddress((void**)&x4,  g_x4);

    const float invN = 1.0f / (float)NN;
    const int MB = cdiv(NN, 128);  // 391

    // ---- CSR build (per launch; edges static) ----
    detect_kernel<<<1, 1>>>(edges);
    zero_indeg<<<cdiv(NN, 256), 256>>>();
    csr_count<<<cdiv(NE, 256), 256>>>(edges);
    scan1<<<NB196, 256>>>();
    scan2<<<1, 256>>>();
    scan3<<<NB196, 256>>>();
    csr_place<<<cdiv(NE, 256), 256>>>(edges);

    // ---- Stage 1: GCN(256->256) + BN + leaky + residual ----
    tf32_gemm<<<dim3(2, MB), 256>>>(x, W1, nullptr, h, NN, 256, 256);
    gcn_gather<256><<<cdiv(NN * 32, 256), 256>>>(h, b1, t);
    bn_zero<<<1, 256>>>();
    bn_stats<256><<<500, 256>>>(t);
    bn_final<<<1, 256>>>(256, invN);
    tf32_gemm<<<dim3(2, MB), 256>>>(x, r1W, r1b, res, NN, 256, 256);
    fuse_bn_res<256><<<cdiv(NN * 256, 256), 256>>>(t, res, g1, be1, x2);

    // ---- Stage 2: GAT(4 heads, mean) + BN + leaky + residual ----
    tf32_gemm<<<dim3(2, MB), 256>>>(x2, Wg, nullptr, h, NN, 256, 256);
    gat_alpha<<<cdiv(NN, 4), 128>>>(h, a_src, a_dst);
    gat_gather<<<cdiv(NN * 32, 256), 256>>>(h, bg, t);
    bn_zero<<<1, 256>>>();
    bn_stats<64><<<500, 256>>>(t);
    bn_final<<<1, 256>>>(64, invN);
    tf32_gemm<<<dim3(1, MB), 256>>>(x2, r2W, r2b, res, NN, 64, 256);
    fuse_bn_res<64><<<cdiv(NN * 64, 256), 256>>>(t, res, g2, be2, x3);

    // ---- Stage 3: GCN(64->16) + BN + leaky + residual ----
    sgemm_kernel<<<dim3(1, MB), 256>>>(x3, W3, nullptr, h, NN, 16, 64);
    gcn_gather16<<<cdiv(NN * 4, 256), 256>>>(h, b3, t);
    bn_zero<<<1, 256>>>();
    bn_stats<16><<<500, 256>>>(t);
    bn_final<<<1, 256>>>(16, invN);
    sgemm_kernel<<<dim3(1, MB), 256>>>(x3, r3W, r3b, res, NN, 16, 64);
    fuse_bn_res<16><<<cdiv(NN * 16, 256), 256>>>(t, res, g3, be3, x4);

    // ---- Stage 4: GCN(16->64), then final linear ----
    sgemm_kernel<<<dim3(1, MB), 256>>>(x4, W4, nullptr, h, NN, 64, 16);
    gcn_gather<64><<<cdiv(NN * 32, 256), 256>>>(h, b4, t);
    sgemm_kernel<<<dim3(1, MB), 256>>>(t, pW, pb, out, NN, 64, 64);
}

// round 5
// speedup vs baseline: 1.9624x; 1.1346x over previous
#include <cuda_runtime.h>
#include <cuda_bf16.h>
#include <cstdint>

#define NN 50000
#define NE 800000
#define NB196 196   // ceil(NN/256)
#define GB1 6250    // gather blocks, stages 1/2 (NN*32/256)
#define GB3 782     // ceil(NN*4/256)

// ---------------- device scratch (static, no runtime alloc) ----------------
__device__ float g_h  [NN * 256];
__device__ float g_t  [NN * 256];
__device__ float g_x2 [NN * 256];
__device__ float g_x3 [NN * 64];
__device__ float g_x4 [NN * 16];
__device__ float g_dinv[NN];
__device__ int   g_indeg[NN];
__device__ int   g_rowstart[NN + 1];
__device__ int   g_cursor[NN];
__device__ int   g_esrc[NE];
__device__ int   g_scanpart[NN];
__device__ int   g_blocksum[NB196];
__device__ int   g_blockoff[NB196];
__device__ float g_als[NN * 4];
__device__ float g_ald[NN * 4];
__device__ float g_bnp1[GB1 * 256];
__device__ float g_bnp2[GB1 * 256];
__device__ float g_mu  [256];
__device__ float g_rstd[256];
__device__ int   g_e64;

// ---------------- edge dtype detect ----------------
__global__ void detect_kernel(const void* edges) {
    const int2* q = (const int2*)edges;
    int all0 = 1;
    for (int k = 0; k < 64; k++) {
        if (q[k * 12497 + 3].y != 0) { all0 = 0; break; }
    }
    g_e64 = all0;
}

__global__ void zero_indeg() {
    int i = blockIdx.x * blockDim.x + threadIdx.x;
    if (i < NN) g_indeg[i] = 0;
}

__global__ void csr_count(const void* edges) {
    int e = blockIdx.x * blockDim.x + threadIdx.x;
    if (e >= NE) return;
    int d;
    if (g_e64) d = (int)((const long long*)edges)[NE + e];
    else       d = ((const int*)edges)[NE + e];
    atomicAdd(&g_indeg[d], 1);
}

// ---------------- parallel exclusive scan over indeg (3 kernels) -----------
__global__ void scan1() {
    int b = blockIdx.x, t = threadIdx.x;
    int i = b * 256 + t;
    int d = (i < NN) ? g_indeg[i] : 0;
    int lane = t & 31, w = t >> 5;
    int v = d;
#pragma unroll
    for (int off = 1; off < 32; off <<= 1) {
        int u = __shfl_up_sync(0xffffffffu, v, off);
        if (lane >= off) v += u;
    }
    __shared__ int ws[8];
    if (lane == 31) ws[w] = v;
    __syncthreads();
    if (t == 0) {
        int run = 0;
        for (int j = 0; j < 8; j++) { int x = ws[j]; ws[j] = run; run += x; }
    }
    __syncthreads();
    v += ws[w];
    if (i < NN) g_scanpart[i] = v;
    if (t == 255) g_blocksum[b] = v;
}

__global__ void scan2() {
    int t = threadIdx.x;
    int d = (t < NB196) ? g_blocksum[t] : 0;
    int lane = t & 31, w = t >> 5;
    int v = d;
#pragma unroll
    for (int off = 1; off < 32; off <<= 1) {
        int u = __shfl_up_sync(0xffffffffu, v, off);
        if (lane >= off) v += u;
    }
    __shared__ int ws[8];
    if (lane == 31) ws[w] = v;
    __syncthreads();
    if (t == 0) {
        int run = 0;
        for (int j = 0; j < 8; j++) { int x = ws[j]; ws[j] = run; run += x; }
    }
    __syncthreads();
    v += ws[w];
    if (t < NB196) g_blockoff[t] = v - d;
}

__global__ void scan3() {
    int i = blockIdx.x * blockDim.x + threadIdx.x;
    if (i < NN) {
        int deg = g_indeg[i];
        int excl = g_blockoff[blockIdx.x] + g_scanpart[i] - deg;
        g_rowstart[i] = excl;
        g_cursor[i] = excl;
        g_dinv[i] = rsqrtf((float)deg + 1.0f);
    }
    if (i == 0) g_rowstart[NN] = NE;
}

__global__ void csr_place(const void* edges) {
    int e = blockIdx.x * blockDim.x + threadIdx.x;
    if (e >= NE) return;
    int s, d;
    if (g_e64) {
        s = (int)((const long long*)edges)[e];
        d = (int)((const long long*)edges)[NE + e];
    } else {
        s = ((const int*)edges)[e];
        d = ((const int*)edges)[NE + e];
    }
    int pos = atomicAdd(&g_cursor[d], 1);
    g_esrc[pos] = s;
}

// ---------------- BN partial reduce ----------------------------------------
template <int C>
__global__ void bn_reduce(int nblocks, float invN) {
    int c = blockIdx.x, t = threadIdx.x;
    double s = 0.0, q = 0.0;
    for (int b = t; b < nblocks; b += 256) {
        s += (double)g_bnp1[(size_t)b * C + c];
        q += (double)g_bnp2[(size_t)b * C + c];
    }
    __shared__ double sh[256], sh2[256];
    sh[t] = s; sh2[t] = q;
    __syncthreads();
    for (int off = 128; off; off >>= 1) {
        if (t < off) { sh[t] += sh[t + off]; sh2[t] += sh2[t + off]; }
        __syncthreads();
    }
    if (t == 0) {
        double m = sh[0] * (double)invN;
        double v = sh2[0] * (double)invN - m * m;
        g_mu[c] = (float)m;
        g_rstd[c] = rsqrtf((float)v + 1e-5f);
    }
}

// ---------------- tf32 tensor-core GEMM -------------------------------------
__device__ __forceinline__ uint32_t f2tf32(float x) {
    uint32_t r;
    asm("cvt.rna.tf32.f32 %0, %1;" : "=r"(r) : "f"(x));
    return r;
}

// FUSE=false: C = A@B + bias.  FUSE=true: C = leaky(BN(T)) + A@B + bias.
template <bool FUSE>
__global__ __launch_bounds__(256, 2)
void tf32_gemm_t(const float* __restrict__ A, const float* __restrict__ B,
                 const float* __restrict__ bias, float* __restrict__ C,
                 int M, int Nn, int K,
                 const float* __restrict__ T, const float* __restrict__ gam,
                 const float* __restrict__ bet) {
    __shared__ uint32_t As[128 * 36];
    __shared__ uint32_t Bs[32 * 136];
    const int tid = threadIdx.x;
    const int warp = tid >> 5, lane = tid & 31;
    const int wm = warp >> 1, wn = warp & 1;
    const int g = lane >> 2, t4 = lane & 3;
    const int rowBase = blockIdx.y * 128;
    const int colBase = blockIdx.x * 128;

    float acc[2][8][4];
#pragma unroll
    for (int mi = 0; mi < 2; mi++)
#pragma unroll
        for (int ni = 0; ni < 8; ni++)
#pragma unroll
            for (int j = 0; j < 4; j++) acc[mi][ni][j] = 0.0f;

    for (int k0 = 0; k0 < K; k0 += 32) {
#pragma unroll
        for (int i = 0; i < 4; i++) {
            int idx = i * 256 + tid;
            int r = idx >> 3, c4 = (idx & 7) * 4;
            float4 v = make_float4(0.f, 0.f, 0.f, 0.f);
            if (rowBase + r < M) v = *(const float4*)(A + (size_t)(rowBase + r) * K + k0 + c4);
            uint4 w;
            w.x = f2tf32(v.x); w.y = f2tf32(v.y); w.z = f2tf32(v.z); w.w = f2tf32(v.w);
            *(uint4*)&As[r * 36 + c4] = w;
        }
#pragma unroll
        for (int i = 0; i < 4; i++) {
            int idx = i * 256 + tid;
            int r = idx >> 5, c4 = (idx & 31) * 4;
            float4 v = make_float4(0.f, 0.f, 0.f, 0.f);
            if (colBase + c4 < Nn) v = *(const float4*)(B + (size_t)(k0 + r) * Nn + colBase + c4);
            uint4 w;
            w.x = f2tf32(v.x); w.y = f2tf32(v.y); w.z = f2tf32(v.z); w.w = f2tf32(v.w);
            *(uint4*)&Bs[r * 136 + c4] = w;
        }
        __syncthreads();

#pragma unroll
        for (int kk = 0; kk < 32; kk += 8) {
            uint32_t af[2][4];
#pragma unroll
            for (int mi = 0; mi < 2; mi++) {
                int r = wm * 32 + mi * 16;
                af[mi][0] = As[(r + g) * 36 + kk + t4];
                af[mi][1] = As[(r + g + 8) * 36 + kk + t4];
                af[mi][2] = As[(r + g) * 36 + kk + t4 + 4];
                af[mi][3] = As[(r + g + 8) * 36 + kk + t4 + 4];
            }
            uint32_t bf[8][2];
#pragma unroll
            for (int ni = 0; ni < 8; ni++) {
                int c = wn * 64 + ni * 8 + g;
                bf[ni][0] = Bs[(kk + t4) * 136 + c];
                bf[ni][1] = Bs[(kk + t4 + 4) * 136 + c];
            }
#pragma unroll
            for (int mi = 0; mi < 2; mi++)
#pragma unroll
                for (int ni = 0; ni < 8; ni++) {
                    asm volatile(
                        "mma.sync.aligned.m16n8k8.row.col.f32.tf32.tf32.f32 "
                        "{%0,%1,%2,%3}, {%4,%5,%6,%7}, {%8,%9}, {%0,%1,%2,%3};"
                        : "+f"(acc[mi][ni][0]), "+f"(acc[mi][ni][1]),
                          "+f"(acc[mi][ni][2]), "+f"(acc[mi][ni][3])
                        : "r"(af[mi][0]), "r"(af[mi][1]), "r"(af[mi][2]), "r"(af[mi][3]),
                          "r"(bf[ni][0]), "r"(bf[ni][1]));
                }
        }
        __syncthreads();
    }

#pragma unroll
    for (int mi = 0; mi < 2; mi++) {
#pragma unroll
        for (int ni = 0; ni < 8; ni++) {
            int r0 = rowBase + wm * 32 + mi * 16 + g;
            int c0 = colBase + wn * 64 + ni * 8 + t4 * 2;
            if (c0 >= Nn) continue;
            float bx = bias ? bias[c0] : 0.0f;
            float by = bias ? bias[c0 + 1] : 0.0f;
#pragma unroll
            for (int half = 0; half < 2; half++) {
                int r = r0 + half * 8;
                if (r >= M) continue;
                float vx = acc[mi][ni][half * 2] + bx;
                float vy = acc[mi][ni][half * 2 + 1] + by;
                if (FUSE) {
                    float2 tv = *(const float2*)(T + (size_t)r * Nn + c0);
                    float ux = (tv.x - g_mu[c0]) * g_rstd[c0] * gam[c0] + bet[c0];
                    float uy = (tv.y - g_mu[c0 + 1]) * g_rstd[c0 + 1] * gam[c0 + 1] + bet[c0 + 1];
                    ux = ux > 0.f ? ux : 0.01f * ux;
                    uy = uy > 0.f ? uy : 0.01f * uy;
                    vx += ux; vy += uy;
                }
                *(float2*)(C + (size_t)r * Nn + c0) = make_float2(vx, vy);
            }
        }
    }
}

// ---------------- SGEMM (FFMA) for small layers -----------------------------
template <bool FUSE>
__global__ void sgemm_t(const float* __restrict__ A, const float* __restrict__ B,
                        const float* __restrict__ bias, float* __restrict__ C,
                        int M, int Nn, int K,
                        const float* __restrict__ T, const float* __restrict__ gam,
                        const float* __restrict__ bet) {
    __shared__ float As[8][128];
    __shared__ float Bs[8][128];
    const int tid = threadIdx.x;
    const int tr = tid >> 4, tc = tid & 15;
    const int aRow = tid >> 1, aCol = (tid & 1) << 2;
    const int bRow = tid >> 5, bCol = (tid & 31) << 2;
    const int rowBase = blockIdx.y * 128;
    const int colBase = blockIdx.x * 128;
    float acc[8][8];
#pragma unroll
    for (int i = 0; i < 8; i++)
#pragma unroll
        for (int j = 0; j < 8; j++) acc[i][j] = 0.0f;

    const int gArow = rowBase + aRow;
    const int gBcol = colBase + bCol;

    for (int k0 = 0; k0 < K; k0 += 8) {
        float4 av = make_float4(0.f, 0.f, 0.f, 0.f);
        if (gArow < M) av = *(const float4*)(A + (size_t)gArow * K + k0 + aCol);
        As[aCol + 0][aRow] = av.x;
        As[aCol + 1][aRow] = av.y;
        As[aCol + 2][aRow] = av.z;
        As[aCol + 3][aRow] = av.w;
        float4 bv = make_float4(0.f, 0.f, 0.f, 0.f);
        if (gBcol < Nn) bv = *(const float4*)(B + (size_t)(k0 + bRow) * Nn + gBcol);
        *(float4*)&Bs[bRow][bCol] = bv;
        __syncthreads();
#pragma unroll
        for (int k = 0; k < 8; k++) {
            float ar[8], br[8];
#pragma unroll
            for (int i = 0; i < 8; i++) ar[i] = As[k][tr * 8 + i];
#pragma unroll
            for (int j = 0; j < 8; j++) br[j] = Bs[k][tc * 8 + j];
#pragma unroll
            for (int i = 0; i < 8; i++)
#pragma unroll
                for (int j = 0; j < 8; j++) acc[i][j] = fmaf(ar[i], br[j], acc[i][j]);
        }
        __syncthreads();
    }
#pragma unroll
    for (int i = 0; i < 8; i++) {
        int r = rowBase + tr * 8 + i;
        if (r >= M) continue;
#pragma unroll
        for (int j = 0; j < 8; j++) {
            int c = colBase + tc * 8 + j;
            if (c >= Nn) continue;
            float v = acc[i][j] + (bias ? bias[c] : 0.0f);
            if (FUSE) {
                float tv = T[(size_t)r * Nn + c];
                float u = (tv - g_mu[c]) * g_rstd[c] * gam[c] + bet[c];
                u = u > 0.f ? u : 0.01f * u;
                v += u;
            }
            C[(size_t)r * Nn + c] = v;
        }
    }
}

// ---------------- GCN gather + fused BN partials ----------------------------
// 256 threads = 8 warps = 8 nodes. Exact grid GB1 (NN*32/256).
__global__ void gcn_gather_bn256(const float* __restrict__ h, const float* __restrict__ bias,
                                 float* __restrict__ out) {
    __shared__ float ss[2048], sq[2048];
    int tid = threadIdx.x, w = tid >> 5, lane = tid & 31;
    int node = blockIdx.x * 8 + w;
    float acc[8];
#pragma unroll
    for (int j = 0; j < 8; j++) acc[j] = 0.0f;
    float dv = g_dinv[node];
    int s0 = g_rowstart[node], s1 = g_rowstart[node + 1];
    for (int p = s0; p < s1; p++) {
        int s = g_esrc[p];
        float norm = g_dinv[s] * dv;
        const float* hp = h + (size_t)s * 256;
#pragma unroll
        for (int j = 0; j < 8; j++) acc[j] = fmaf(norm, hp[j * 32 + lane], acc[j]);
    }
    const float* hd = h + (size_t)node * 256;
    float self = dv * dv;
#pragma unroll
    for (int j = 0; j < 8; j++) {
        int c = j * 32 + lane;
        float v = acc[j] + self * hd[c] + bias[c];
        out[(size_t)node * 256 + c] = v;
        ss[w * 256 + c] = v;
        sq[w * 256 + c] = v * v;
    }
    __syncthreads();
    float s = 0.f, q = 0.f;
#pragma unroll
    for (int w2 = 0; w2 < 8; w2++) { s += ss[w2 * 256 + tid]; q += sq[w2 * 256 + tid]; }
    g_bnp1[(size_t)blockIdx.x * 256 + tid] = s;
    g_bnp2[(size_t)blockIdx.x * 256 + tid] = q;
}

// plain warp-per-node gather, C=64 (stage 4, no BN)
__global__ void gcn_gather64(const float* __restrict__ h, const float* __restrict__ bias,
                             float* __restrict__ out) {
    int warp = (blockIdx.x * blockDim.x + threadIdx.x) >> 5;
    int lane = threadIdx.x & 31;
    if (warp >= NN) return;
    float a0 = 0.f, a1 = 0.f;
    float dv = g_dinv[warp];
    int s0 = g_rowstart[warp], s1 = g_rowstart[warp + 1];
    for (int p = s0; p < s1; p++) {
        int s = g_esrc[p];
        float norm = g_dinv[s] * dv;
        const float* hp = h + (size_t)s * 64;
        a0 = fmaf(norm, hp[lane], a0);
        a1 = fmaf(norm, hp[32 + lane], a1);
    }
    const float* hd = h + (size_t)warp * 64;
    float self = dv * dv;
    out[(size_t)warp * 64 + lane]      = a0 + self * hd[lane] + bias[lane];
    out[(size_t)warp * 64 + 32 + lane] = a1 + self * hd[32 + lane] + bias[32 + lane];
}

// C=16 gather + BN partials: 256 threads = 64 nodes (4 threads/node)
__global__ void gcn_gather16_bn(const float* __restrict__ h, const float* __restrict__ bias,
                                float* __restrict__ out) {
    __shared__ float ss[1024], sq[1024];
    int tid = threadIdx.x;
    int idx = blockIdx.x * 256 + tid;
    int node = idx >> 2, q4 = idx & 3;
    float ox = 0.f, oy = 0.f, oz = 0.f, ow = 0.f;
    if (node < NN) {
        float ax = 0.f, ay = 0.f, az = 0.f, aw = 0.f;
        float dv = g_dinv[node];
        int s0 = g_rowstart[node], s1 = g_rowstart[node + 1];
        for (int p = s0; p < s1; p++) {
            int s = g_esrc[p];
            float norm = g_dinv[s] * dv;
            float4 v = *(const float4*)(h + (size_t)s * 16 + q4 * 4);
            ax = fmaf(norm, v.x, ax); ay = fmaf(norm, v.y, ay);
            az = fmaf(norm, v.z, az); aw = fmaf(norm, v.w, aw);
        }
        float4 hv = *(const float4*)(h + (size_t)node * 16 + q4 * 4);
        float4 bv = *(const float4*)(bias + q4 * 4);
        float self = dv * dv;
        ox = ax + self * hv.x + bv.x;
        oy = ay + self * hv.y + bv.y;
        oz = az + self * hv.z + bv.z;
        ow = aw + self * hv.w + bv.w;
        *(float4*)(out + (size_t)node * 16 + q4 * 4) = make_float4(ox, oy, oz, ow);
    }
    ss[tid * 4 + 0] = ox; sq[tid * 4 + 0] = ox * ox;
    ss[tid * 4 + 1] = oy; sq[tid * 4 + 1] = oy * oy;
    ss[tid * 4 + 2] = oz; sq[tid * 4 + 2] = oz * oz;
    ss[tid * 4 + 3] = ow; sq[tid * 4 + 3] = ow * ow;
    __syncthreads();
    if (tid < 16) {
        int qq = tid >> 2, ii = tid & 3;
        float s = 0.f, q = 0.f;
        for (int nl = 0; nl < 64; nl++) {
            s += ss[(nl * 4 + qq) * 4 + ii];
            q += sq[(nl * 4 + qq) * 4 + ii];
        }
        g_bnp1[(size_t)blockIdx.x * 16 + tid] = s;
        g_bnp2[(size_t)blockIdx.x * 16 + tid] = q;
    }
}

// ---------------- GAT: alpha dot per node (warp per node) -------------------
__global__ void gat_alpha(const float* __restrict__ h2, const float* __restrict__ a_s,
                          const float* __restrict__ a_d) {
    __shared__ float s_as[256], s_ad[256];
    int tid = threadIdx.x;  // 128
    s_as[tid] = a_s[tid]; s_ad[tid] = a_d[tid];
    s_as[tid + 128] = a_s[tid + 128]; s_ad[tid + 128] = a_d[tid + 128];
    __syncthreads();
    int w = tid >> 5, lane = tid & 31;
    int n = blockIdx.x * 4 + w;
    if (n >= NN) return;
    float ps[4] = {0.f, 0.f, 0.f, 0.f}, pd[4] = {0.f, 0.f, 0.f, 0.f};
    const float* hp = h2 + (size_t)n * 256;
#pragma unroll
    for (int j = 0; j < 8; j++) {
        int c = j * 32 + lane;
        float v = hp[c];
        ps[j >> 1] = fmaf(v, s_as[c], ps[j >> 1]);
        pd[j >> 1] = fmaf(v, s_ad[c], pd[j >> 1]);
    }
#pragma unroll
    for (int hh = 0; hh < 4; hh++) {
#pragma unroll
        for (int off = 16; off > 0; off >>= 1) {
            ps[hh] += __shfl_xor_sync(0xffffffffu, ps[hh], off);
            pd[hh] += __shfl_xor_sync(0xffffffffu, pd[hh], off);
        }
    }
    if (lane == 0) {
        *(float4*)(g_als + (size_t)n * 4) = make_float4(ps[0], ps[1], ps[2], ps[3]);
        *(float4*)(g_ald + (size_t)n * 4) = make_float4(pd[0], pd[1], pd[2], pd[3]);
    }
}

// ---------------- GAT gather + fused BN partials ----------------------------
__global__ void gat_gather_bn(const float* __restrict__ h2, const float* __restrict__ bg,
                              float* __restrict__ out) {
    __shared__ float ss[512], sq[512];
    int tid = threadIdx.x, w = tid >> 5, lane = tid & 31;
    int node = blockIdx.x * 8 + w;
    float4 adv = *(const float4*)(g_ald + (size_t)node * 4);
    float4 asv = *(const float4*)(g_als + (size_t)node * 4);
    float ad[4] = {adv.x, adv.y, adv.z, adv.w};
    float eself[4];
    {
        float as_[4] = {asv.x, asv.y, asv.z, asv.w};
#pragma unroll
        for (int hh = 0; hh < 4; hh++) {
            float lg = as_[hh] + ad[hh];
            eself[hh] = lg > 0.f ? lg : 0.2f * lg;
        }
    }
    int s0 = g_rowstart[node], s1 = g_rowstart[node + 1];
    float m[4] = {eself[0], eself[1], eself[2], eself[3]};
    for (int p = s0 + lane; p < s1; p += 32) {
        int s = g_esrc[p];
        float4 a = *(const float4*)(g_als + (size_t)s * 4);
        float lg;
        lg = a.x + ad[0]; m[0] = fmaxf(m[0], lg > 0.f ? lg : 0.2f * lg);
        lg = a.y + ad[1]; m[1] = fmaxf(m[1], lg > 0.f ? lg : 0.2f * lg);
        lg = a.z + ad[2]; m[2] = fmaxf(m[2], lg > 0.f ? lg : 0.2f * lg);
        lg = a.w + ad[3]; m[3] = fmaxf(m[3], lg > 0.f ? lg : 0.2f * lg);
    }
#pragma unroll
    for (int hh = 0; hh < 4; hh++)
#pragma unroll
        for (int off = 16; off > 0; off >>= 1)
            m[hh] = fmaxf(m[hh], __shfl_xor_sync(0xffffffffu, m[hh], off));

    float adL = ad[0], mL = m[0];
    if (lane == 1) { adL = ad[1]; mL = m[1]; }
    else if (lane == 2) { adL = ad[2]; mL = m[2]; }
    else if (lane == 3) { adL = ad[3]; mL = m[3]; }
    float acc[8] = {0.f, 0.f, 0.f, 0.f, 0.f, 0.f, 0.f, 0.f};
    float denL = 0.f;
    for (int p = s0; p < s1; p++) {
        int s = g_esrc[p];
        float ee = 0.f;
        if (lane < 4) {
            float a = g_als[(size_t)s * 4 + lane];
            float lg = a + adL;
            lg = lg > 0.f ? lg : 0.2f * lg;
            ee = __expf(lg - mL);
            denL += ee;
        }
        float ee0 = __shfl_sync(0xffffffffu, ee, 0);
        float ee1 = __shfl_sync(0xffffffffu, ee, 1);
        float ee2 = __shfl_sync(0xffffffffu, ee, 2);
        float ee3 = __shfl_sync(0xffffffffu, ee, 3);
        const float* hp = h2 + (size_t)s * 256;
        acc[0] = fmaf(ee0, hp[lane], acc[0]);
        acc[1] = fmaf(ee0, hp[32 + lane], acc[1]);
        acc[2] = fmaf(ee1, hp[64 + lane], acc[2]);
        acc[3] = fmaf(ee1, hp[96 + lane], acc[3]);
        acc[4] = fmaf(ee2, hp[128 + lane], acc[4]);
        acc[5] = fmaf(ee2, hp[160 + lane], acc[5]);
        acc[6] = fmaf(ee3, hp[192 + lane], acc[6]);
        acc[7] = fmaf(ee3, hp[224 + lane], acc[7]);
    }
    float es[4], den[4];
#pragma unroll
    for (int hh = 0; hh < 4; hh++) {
        es[hh] = __expf(eself[hh] - m[hh]);
        den[hh] = __shfl_sync(0xffffffffu, denL, hh) + es[hh];
    }
    const float* hd = h2 + (size_t)node * 256;
    float o0 = 0.f, o1 = 0.f;
#pragma unroll
    for (int hh = 0; hh < 4; hh++) {
        o0 += (acc[2 * hh]     + es[hh] * hd[hh * 64 + lane])      / den[hh];
        o1 += (acc[2 * hh + 1] + es[hh] * hd[hh * 64 + 32 + lane]) / den[hh];
    }
    float t0 = 0.25f * o0 + bg[lane];
    float t1 = 0.25f * o1 + bg[32 + lane];
    out[(size_t)node * 64 + lane]      = t0;
    out[(size_t)node * 64 + 32 + lane] = t1;
    ss[w * 64 + lane] = t0;        sq[w * 64 + lane] = t0 * t0;
    ss[w * 64 + 32 + lane] = t1;   sq[w * 64 + 32 + lane] = t1 * t1;
    __syncthreads();
    if (tid < 64) {
        float s = 0.f, q = 0.f;
#pragma unroll
        for (int w2 = 0; w2 < 8; w2++) { s += ss[w2 * 64 + tid]; q += sq[w2 * 64 + tid]; }
        g_bnp1[(size_t)blockIdx.x * 64 + tid] = s;
        g_bnp2[(size_t)blockIdx.x * 64 + tid] = q;
    }
}

// ---------------- host ----------------
static inline int cdiv(int a, int b) { return (a + b - 1) / b; }

extern "C" void kernel_launch(void* const* d_in, const int* in_sizes, int n_in,
                              void* d_out, int out_size) {
    const float* x    = (const float*)d_in[0];
    const void*  edges = d_in[1];
    const float* W1   = (const float*)d_in[2];
    const float* b1   = (const float*)d_in[3];
    const float* g1   = (const float*)d_in[4];
    const float* be1  = (const float*)d_in[5];
    const float* Wg   = (const float*)d_in[6];
    const float* a_src = (const float*)d_in[7];
    const float* a_dst = (const float*)d_in[8];
    const float* bg   = (const float*)d_in[9];
    const float* g2   = (const float*)d_in[10];
    const float* be2  = (const float*)d_in[11];
    const float* W3   = (const float*)d_in[12];
    const float* b3   = (const float*)d_in[13];
    const float* g3   = (const float*)d_in[14];
    const float* be3  = (const float*)d_in[15];
    const float* W4   = (const float*)d_in[16];
    const float* b4   = (const float*)d_in[17];
    const float* r1W  = (const float*)d_in[18];
    const float* r1b  = (const float*)d_in[19];
    const float* r2W  = (const float*)d_in[20];
    const float* r2b  = (const float*)d_in[21];
    const float* r3W  = (const float*)d_in[22];
    const float* r3b  = (const float*)d_in[23];
    const float* pW   = (const float*)d_in[24];
    const float* pb   = (const float*)d_in[25];
    float* out = (float*)d_out;

    float *h, *t, *x2, *x3, *x4;
    cudaGetSymbolAddress((void**)&h,  g_h);
    cudaGetSymbolAddress((void**)&t,  g_t);
    cudaGetSymbolAddress((void**)&x2, g_x2);
    cudaGetSymbolAddress((void**)&x3, g_x3);
    cudaGetSymbolAddress((void**)&x4, g_x4);

    const float invN = 1.0f / (float)NN;
    const int MB = cdiv(NN, 128);  // 391

    // ---- CSR build ----
    detect_kernel<<<1, 1>>>(edges);
    zero_indeg<<<cdiv(NN, 256), 256>>>();
    csr_count<<<cdiv(NE, 256), 256>>>(edges);
    scan1<<<NB196, 256>>>();
    scan2<<<1, 256>>>();
    scan3<<<NB196, 256>>>();
    csr_place<<<cdiv(NE, 256), 256>>>(edges);

    // ---- Stage 1: GCN(256->256) + BN + leaky + residual ----
    tf32_gemm_t<false><<<dim3(2, MB), 256>>>(x, W1, nullptr, h, NN, 256, 256,
                                             nullptr, nullptr, nullptr);
    gcn_gather_bn256<<<GB1, 256>>>(h, b1, t);
    bn_reduce<256><<<256, 256>>>(GB1, invN);
    tf32_gemm_t<true><<<dim3(2, MB), 256>>>(x, r1W, r1b, x2, NN, 256, 256,
                                            t, g1, be1);

    // ---- Stage 2: GAT(4 heads, mean) + BN + leaky + residual ----
    tf32_gemm_t<false><<<dim3(2, MB), 256>>>(x2, Wg, nullptr, h, NN, 256, 256,
                                             nullptr, nullptr, nullptr);
    gat_alpha<<<cdiv(NN, 4), 128>>>(h, a_src, a_dst);
    gat_gather_bn<<<GB1, 256>>>(h, bg, t);
    bn_reduce<64><<<64, 256>>>(GB1, invN);
    tf32_gemm_t<true><<<dim3(1, MB), 256>>>(x2, r2W, r2b, x3, NN, 64, 256,
                                            t, g2, be2);

    // ---- Stage 3: GCN(64->16) + BN + leaky + residual ----
    sgemm_t<false><<<dim3(1, MB), 256>>>(x3, W3, nullptr, h, NN, 16, 64,
                                         nullptr, nullptr, nullptr);
    gcn_gather16_bn<<<GB3, 256>>>(h, b3, t);
    bn_reduce<16><<<16, 256>>>(GB3, invN);
    sgemm_t<true><<<dim3(1, MB), 256>>>(x3, r3W, r3b, x4, NN, 16, 64,
                                        t, g3, be3);

    // ---- Stage 4: GCN(16->64), then final linear ----
    sgemm_t<false><<<dim3(1, MB), 256>>>(x4, W4, nullptr, h, NN, 64, 16,
                                         nullptr, nullptr, nullptr);
    gcn_gather64<<<cdiv(NN * 32, 256), 256>>>(h, b4, t);
    sgemm_t<false><<<dim3(1, MB), 256>>>(t, pW, pb, out, NN, 64, 64,
                                         nullptr, nullptr, nullptr);
}

// round 6
// speedup vs baseline: 2.3451x; 1.1951x over previous
#include <cuda_runtime.h>
#include <cuda_bf16.h>
#include <cstdint>

#define NN 50000
#define NE 800000
#define NB196 196   // ceil(NN/256)
#define GB1 6250    // gather blocks, stages 1/2 (NN*32/256)
#define GB3 782     // ceil(NN*4/256)
#define WRTOT 219136

// ---------------- device scratch (static, no runtime alloc) ----------------
__device__ float g_h  [NN * 256];
__device__ float g_t  [NN * 256];
__device__ float g_x2 [NN * 256];
__device__ float g_xr [NN * 256];
__device__ float g_x3 [NN * 64];
__device__ float g_x4 [NN * 16];
__device__ float g_wr [WRTOT];
__device__ float g_dinv[NN];
__device__ int   g_indeg[NN];
__device__ int   g_rowstart[NN + 1];
__device__ int   g_cursor[NN];
__device__ int   g_esrc[NE];
__device__ int   g_scanpart[NN];
__device__ int   g_blocksum[NB196];
__device__ int   g_blockoff[NB196];
__device__ float g_als[NN * 4];
__device__ float g_ald[NN * 4];
__device__ float g_bnp1[GB1 * 256];
__device__ float g_bnp2[GB1 * 256];
__device__ float g_mu  [256];
__device__ float g_rstd[256];
__device__ int   g_e64;

__device__ __forceinline__ uint32_t f2tf32(float x) {
    uint32_t r;
    asm("cvt.rna.tf32.f32 %0, %1;" : "=r"(r) : "f"(x));
    return r;
}
__device__ __forceinline__ float f2tf32f(float x) { return __uint_as_float(f2tf32(x)); }

// ---------------- edge dtype detect ----------------
__global__ void detect_kernel(const void* edges) {
    const int2* q = (const int2*)edges;
    int all0 = 1;
    for (int k = 0; k < 64; k++) {
        if (q[k * 12497 + 3].y != 0) { all0 = 0; break; }
    }
    g_e64 = all0;
}

__global__ void zero_indeg() {
    int i = blockIdx.x * blockDim.x + threadIdx.x;
    if (i < NN) g_indeg[i] = 0;
}

__global__ void csr_count(const void* edges) {
    int e = blockIdx.x * blockDim.x + threadIdx.x;
    if (e >= NE) return;
    int d;
    if (g_e64) d = (int)((const long long*)edges)[NE + e];
    else       d = ((const int*)edges)[NE + e];
    atomicAdd(&g_indeg[d], 1);
}

// ---------------- parallel exclusive scan over indeg ------------------------
__global__ void scan1() {
    int b = blockIdx.x, t = threadIdx.x;
    int i = b * 256 + t;
    int d = (i < NN) ? g_indeg[i] : 0;
    int lane = t & 31, w = t >> 5;
    int v = d;
#pragma unroll
    for (int off = 1; off < 32; off <<= 1) {
        int u = __shfl_up_sync(0xffffffffu, v, off);
        if (lane >= off) v += u;
    }
    __shared__ int ws[8];
    if (lane == 31) ws[w] = v;
    __syncthreads();
    if (t == 0) {
        int run = 0;
        for (int j = 0; j < 8; j++) { int x = ws[j]; ws[j] = run; run += x; }
    }
    __syncthreads();
    v += ws[w];
    if (i < NN) g_scanpart[i] = v;
    if (t == 255) g_blocksum[b] = v;
}

__global__ void scan2() {
    int t = threadIdx.x;
    int d = (t < NB196) ? g_blocksum[t] : 0;
    int lane = t & 31, w = t >> 5;
    int v = d;
#pragma unroll
    for (int off = 1; off < 32; off <<= 1) {
        int u = __shfl_up_sync(0xffffffffu, v, off);
        if (lane >= off) v += u;
    }
    __shared__ int ws[8];
    if (lane == 31) ws[w] = v;
    __syncthreads();
    if (t == 0) {
        int run = 0;
        for (int j = 0; j < 8; j++) { int x = ws[j]; ws[j] = run; run += x; }
    }
    __syncthreads();
    v += ws[w];
    if (t < NB196) g_blockoff[t] = v - d;
}

__global__ void scan3() {
    int i = blockIdx.x * blockDim.x + threadIdx.x;
    if (i < NN) {
        int deg = g_indeg[i];
        int excl = g_blockoff[blockIdx.x] + g_scanpart[i] - deg;
        g_rowstart[i] = excl;
        g_cursor[i] = excl;
        g_dinv[i] = rsqrtf((float)deg + 1.0f);
    }
    if (i == 0) g_rowstart[NN] = NE;
}

__global__ void csr_place(const void* edges) {
    int e = blockIdx.x * blockDim.x + threadIdx.x;
    if (e >= NE) return;
    int s, d;
    if (g_e64) {
        s = (int)((const long long*)edges)[e];
        d = (int)((const long long*)edges)[NE + e];
    } else {
        s = ((const int*)edges)[e];
        d = ((const int*)edges)[NE + e];
    }
    int pos = atomicAdd(&g_cursor[d], 1);
    g_esrc[pos] = s;
}

// ---------------- operand pre-rounding (tf32 RN) ----------------------------
__global__ void round_x(const float4* __restrict__ x) {
    int i = blockIdx.x * 256 + threadIdx.x;   // 3,200,000 float4
    if (i >= NN * 64) return;
    float4 v = x[i];
    v.x = f2tf32f(v.x); v.y = f2tf32f(v.y); v.z = f2tf32f(v.z); v.w = f2tf32f(v.w);
    ((float4*)g_xr)[i] = v;
}

__global__ void round_weights(const float4* W1, const float4* r1W, const float4* Wg,
                              const float4* r2W, const float4* W3, const float4* r3W,
                              const float4* pW) {
    int i = blockIdx.x * 256 + threadIdx.x;   // 54784 float4
    if (i >= 54784) return;
    const float4* s; int b;
    if      (i < 16384) { s = W1;  b = 0; }
    else if (i < 32768) { s = r1W; b = 16384; }
    else if (i < 49152) { s = Wg;  b = 32768; }
    else if (i < 53248) { s = r2W; b = 49152; }
    else if (i < 53504) { s = W3;  b = 53248; }
    else if (i < 53760) { s = r3W; b = 53504; }
    else                { s = pW;  b = 53760; }
    float4 v = s[i - b];
    v.x = f2tf32f(v.x); v.y = f2tf32f(v.y); v.z = f2tf32f(v.z); v.w = f2tf32f(v.w);
    ((float4*)g_wr)[i] = v;
}

// ---------------- BN partial reduce ----------------------------------------
template <int C>
__global__ void bn_reduce(int nblocks, float invN) {
    int c = blockIdx.x, t = threadIdx.x;
    double s = 0.0, q = 0.0;
    for (int b = t; b < nblocks; b += 256) {
        s += (double)g_bnp1[(size_t)b * C + c];
        q += (double)g_bnp2[(size_t)b * C + c];
    }
    __shared__ double sh[256], sh2[256];
    sh[t] = s; sh2[t] = q;
    __syncthreads();
    for (int off = 128; off; off >>= 1) {
        if (t < off) { sh[t] += sh[t + off]; sh2[t] += sh2[t + off]; }
        __syncthreads();
    }
    if (t == 0) {
        double m = sh[0] * (double)invN;
        double v = sh2[0] * (double)invN - m * m;
        g_mu[c] = (float)m;
        g_rstd[c] = rsqrtf((float)v + 1e-5f);
    }
}

// ---------------- tf32 tensor-core GEMM, cp.async double-buffered ----------
// Inputs A,B must be pre-rounded to tf32. Block tile 128x128x32, 2 stages.
// FUSE: C = leaky(BN(T)) + A@B + bias.  ROUND: round output to tf32.
#define ASTRIDE 36
#define BSTRIDE 136
#define ASZ (128 * ASTRIDE)      // 4608 words per stage
#define BSZ (32 * BSTRIDE)       // 4352 words per stage
#define SMEM_WORDS (2 * ASZ + 2 * BSZ)

template <bool FUSE, bool ROUND>
__global__ __launch_bounds__(256, 2)
void tf32_gemm_ca(const float* __restrict__ A, const float* __restrict__ B,
                  const float* __restrict__ bias, float* __restrict__ C,
                  int M, int Nn, int K,
                  const float* __restrict__ T, const float* __restrict__ gam,
                  const float* __restrict__ bet) {
    extern __shared__ uint32_t sm[];
    const int tid = threadIdx.x;
    const int warp = tid >> 5, lane = tid & 31;
    const int wm = warp >> 1, wn = warp & 1;
    const int g = lane >> 2, t4 = lane & 3;
    const int rowBase = blockIdx.y * 128;
    const int colBase = blockIdx.x * 128;
    const uint32_t sbase = (uint32_t)__cvta_generic_to_shared(sm);

    const int arow = tid >> 3, ac4 = (tid & 7) * 4;     // A: +q*32 rows
    const int brow = tid >> 5, bc4 = (tid & 31) * 4;    // B: +q*8 rows

    float acc[2][8][4];
#pragma unroll
    for (int mi = 0; mi < 2; mi++)
#pragma unroll
        for (int ni = 0; ni < 8; ni++)
#pragma unroll
            for (int j = 0; j < 4; j++) acc[mi][ni][j] = 0.0f;

    const int nk = K >> 5;

    auto loadTile = [&](int k0i, int buf) {
        int k0 = k0i << 5;
#pragma unroll
        for (int q = 0; q < 4; q++) {
            int r = q * 32 + arow;
            const float* src = A + (size_t)(rowBase + r) * K + k0 + ac4;
            uint32_t dst = sbase + (uint32_t)(buf * ASZ + r * ASTRIDE + ac4) * 4u;
            int sz = (rowBase + r < M) ? 16 : 0;
            asm volatile("cp.async.cg.shared.global [%0], [%1], 16, %2;\n"
                         :: "r"(dst), "l"(src), "r"(sz));
        }
#pragma unroll
        for (int q = 0; q < 4; q++) {
            int r = q * 8 + brow;
            const float* src = B + (size_t)(k0 + r) * Nn + colBase + bc4;
            uint32_t dst = sbase + (uint32_t)(2 * ASZ + buf * BSZ + r * BSTRIDE + bc4) * 4u;
            int sz = (colBase + bc4 + 4 <= Nn) ? 16 : 0;
            asm volatile("cp.async.cg.shared.global [%0], [%1], 16, %2;\n"
                         :: "r"(dst), "l"(src), "r"(sz));
        }
        asm volatile("cp.async.commit_group;\n");
    };

    loadTile(0, 0);

    for (int k0i = 0; k0i < nk; k0i++) {
        if (k0i + 1 < nk) {
            loadTile(k0i + 1, (k0i + 1) & 1);
            asm volatile("cp.async.wait_group 1;\n");
        } else {
            asm volatile("cp.async.wait_group 0;\n");
        }
        __syncthreads();

        const uint32_t* As = sm + (k0i & 1) * ASZ;
        const uint32_t* Bs = sm + 2 * ASZ + (k0i & 1) * BSZ;

#pragma unroll
        for (int kk = 0; kk < 32; kk += 8) {
            uint32_t af[2][4];
#pragma unroll
            for (int mi = 0; mi < 2; mi++) {
                int r = wm * 32 + mi * 16;
                af[mi][0] = As[(r + g) * ASTRIDE + kk + t4];
                af[mi][1] = As[(r + g + 8) * ASTRIDE + kk + t4];
                af[mi][2] = As[(r + g) * ASTRIDE + kk + t4 + 4];
                af[mi][3] = As[(r + g + 8) * ASTRIDE + kk + t4 + 4];
            }
            uint32_t bf[8][2];
#pragma unroll
            for (int ni = 0; ni < 8; ni++) {
                int c = wn * 64 + ni * 8 + g;
                bf[ni][0] = Bs[(kk + t4) * BSTRIDE + c];
                bf[ni][1] = Bs[(kk + t4 + 4) * BSTRIDE + c];
            }
#pragma unroll
            for (int mi = 0; mi < 2; mi++)
#pragma unroll
                for (int ni = 0; ni < 8; ni++) {
                    asm volatile(
                        "mma.sync.aligned.m16n8k8.row.col.f32.tf32.tf32.f32 "
                        "{%0,%1,%2,%3}, {%4,%5,%6,%7}, {%8,%9}, {%0,%1,%2,%3};"
                        : "+f"(acc[mi][ni][0]), "+f"(acc[mi][ni][1]),
                          "+f"(acc[mi][ni][2]), "+f"(acc[mi][ni][3])
                        : "r"(af[mi][0]), "r"(af[mi][1]), "r"(af[mi][2]), "r"(af[mi][3]),
                          "r"(bf[ni][0]), "r"(bf[ni][1]));
                }
        }
        __syncthreads();
    }

#pragma unroll
    for (int mi = 0; mi < 2; mi++) {
#pragma unroll
        for (int ni = 0; ni < 8; ni++) {
            int r0 = rowBase + wm * 32 + mi * 16 + g;
            int c0 = colBase + wn * 64 + ni * 8 + t4 * 2;
            if (c0 >= Nn) continue;
            float bx = bias ? bias[c0] : 0.0f;
            float by = bias ? bias[c0 + 1] : 0.0f;
#pragma unroll
            for (int half = 0; half < 2; half++) {
                int r = r0 + half * 8;
                if (r >= M) continue;
                float vx = acc[mi][ni][half * 2] + bx;
                float vy = acc[mi][ni][half * 2 + 1] + by;
                if (FUSE) {
                    float2 tv = *(const float2*)(T + (size_t)r * Nn + c0);
                    float ux = (tv.x - g_mu[c0]) * g_rstd[c0] * gam[c0] + bet[c0];
                    float uy = (tv.y - g_mu[c0 + 1]) * g_rstd[c0 + 1] * gam[c0 + 1] + bet[c0 + 1];
                    ux = ux > 0.f ? ux : 0.01f * ux;
                    uy = uy > 0.f ? uy : 0.01f * uy;
                    vx += ux; vy += uy;
                }
                if (ROUND) { vx = f2tf32f(vx); vy = f2tf32f(vy); }
                *(float2*)(C + (size_t)r * Nn + c0) = make_float2(vx, vy);
            }
        }
    }
}

// ---------------- narrow FFMA GEMM: M x 64, K=16 (stage-4 W4) ---------------
__global__ void gemm_k16(const float* __restrict__ A, const float* __restrict__ B,
                         float* __restrict__ C) {
    __shared__ float Bs[16 * 64];
    int tid = threadIdx.x;
    ((float4*)Bs)[tid] = ((const float4*)B)[tid];  // 256 * 16B = 4KB
    __syncthreads();
    int row = blockIdx.x * 256 + tid;
    if (row >= NN) return;
    float a[16];
#pragma unroll
    for (int q = 0; q < 4; q++) {
        float4 v = *(const float4*)(A + (size_t)row * 16 + q * 4);
        a[q * 4] = v.x; a[q * 4 + 1] = v.y; a[q * 4 + 2] = v.z; a[q * 4 + 3] = v.w;
    }
    float acc[64];
#pragma unroll
    for (int c = 0; c < 64; c++) acc[c] = 0.0f;
#pragma unroll
    for (int k = 0; k < 16; k++) {
        float av = a[k];
#pragma unroll
        for (int c = 0; c < 64; c++) acc[c] = fmaf(av, Bs[k * 64 + c], acc[c]);
    }
#pragma unroll
    for (int q = 0; q < 16; q++) {
        *(float4*)(C + (size_t)row * 64 + q * 4) =
            make_float4(acc[q * 4], acc[q * 4 + 1], acc[q * 4 + 2], acc[q * 4 + 3]);
    }
}

// ---------------- GCN gather + fused BN partials ----------------------------
__global__ void gcn_gather_bn256(const float* __restrict__ h, const float* __restrict__ bias,
                                 float* __restrict__ out) {
    __shared__ float ss[2048], sq[2048];
    int tid = threadIdx.x, w = tid >> 5, lane = tid & 31;
    int node = blockIdx.x * 8 + w;
    float acc[8];
#pragma unroll
    for (int j = 0; j < 8; j++) acc[j] = 0.0f;
    float dv = g_dinv[node];
    int s0 = g_rowstart[node], s1 = g_rowstart[node + 1];
    for (int p = s0; p < s1; p++) {
        int s = g_esrc[p];
        float norm = g_dinv[s] * dv;
        const float* hp = h + (size_t)s * 256;
#pragma unroll
        for (int j = 0; j < 8; j++) acc[j] = fmaf(norm, hp[j * 32 + lane], acc[j]);
    }
    const float* hd = h + (size_t)node * 256;
    float self = dv * dv;
#pragma unroll
    for (int j = 0; j < 8; j++) {
        int c = j * 32 + lane;
        float v = acc[j] + self * hd[c] + bias[c];
        out[(size_t)node * 256 + c] = v;
        ss[w * 256 + c] = v;
        sq[w * 256 + c] = v * v;
    }
    __syncthreads();
    float s = 0.f, q = 0.f;
#pragma unroll
    for (int w2 = 0; w2 < 8; w2++) { s += ss[w2 * 256 + tid]; q += sq[w2 * 256 + tid]; }
    g_bnp1[(size_t)blockIdx.x * 256 + tid] = s;
    g_bnp2[(size_t)blockIdx.x * 256 + tid] = q;
}

// stage-4 gather, C=64; output rounded to tf32 (feeds pW tf32 GEMM)
__global__ void gcn_gather64(const float* __restrict__ h, const float* __restrict__ bias,
                             float* __restrict__ out) {
    int warp = (blockIdx.x * blockDim.x + threadIdx.x) >> 5;
    int lane = threadIdx.x & 31;
    if (warp >= NN) return;
    float a0 = 0.f, a1 = 0.f;
    float dv = g_dinv[warp];
    int s0 = g_rowstart[warp], s1 = g_rowstart[warp + 1];
    for (int p = s0; p < s1; p++) {
        int s = g_esrc[p];
        float norm = g_dinv[s] * dv;
        const float* hp = h + (size_t)s * 64;
        a0 = fmaf(norm, hp[lane], a0);
        a1 = fmaf(norm, hp[32 + lane], a1);
    }
    const float* hd = h + (size_t)warp * 64;
    float self = dv * dv;
    out[(size_t)warp * 64 + lane]      = f2tf32f(a0 + self * hd[lane] + bias[lane]);
    out[(size_t)warp * 64 + 32 + lane] = f2tf32f(a1 + self * hd[32 + lane] + bias[32 + lane]);
}

// C=16 gather + BN partials: 256 threads = 64 nodes (4 threads/node)
__global__ void gcn_gather16_bn(const float* __restrict__ h, const float* __restrict__ bias,
                                float* __restrict__ out) {
    __shared__ float ss[1024], sq[1024];
    int tid = threadIdx.x;
    int idx = blockIdx.x * 256 + tid;
    int node = idx >> 2, q4 = idx & 3;
    float ox = 0.f, oy = 0.f, oz = 0.f, ow = 0.f;
    if (node < NN) {
        float ax = 0.f, ay = 0.f, az = 0.f, aw = 0.f;
        float dv = g_dinv[node];
        int s0 = g_rowstart[node], s1 = g_rowstart[node + 1];
        for (int p = s0; p < s1; p++) {
            int s = g_esrc[p];
            float norm = g_dinv[s] * dv;
            float4 v = *(const float4*)(h + (size_t)s * 16 + q4 * 4);
            ax = fmaf(norm, v.x, ax); ay = fmaf(norm, v.y, ay);
            az = fmaf(norm, v.z, az); aw = fmaf(norm, v.w, aw);
        }
        float4 hv = *(const float4*)(h + (size_t)node * 16 + q4 * 4);
        float4 bv = *(const float4*)(bias + q4 * 4);
        float self = dv * dv;
        ox = ax + self * hv.x + bv.x;
        oy = ay + self * hv.y + bv.y;
        oz = az + self * hv.z + bv.z;
        ow = aw + self * hv.w + bv.w;
        *(float4*)(out + (size_t)node * 16 + q4 * 4) = make_float4(ox, oy, oz, ow);
    }
    ss[tid * 4 + 0] = ox; sq[tid * 4 + 0] = ox * ox;
    ss[tid * 4 + 1] = oy; sq[tid * 4 + 1] = oy * oy;
    ss[tid * 4 + 2] = oz; sq[tid * 4 + 2] = oz * oz;
    ss[tid * 4 + 3] = ow; sq[tid * 4 + 3] = ow * ow;
    __syncthreads();
    if (tid < 16) {
        int qq = tid >> 2, ii = tid & 3;
        float s = 0.f, q = 0.f;
        for (int nl = 0; nl < 64; nl++) {
            s += ss[(nl * 4 + qq) * 4 + ii];
            q += sq[(nl * 4 + qq) * 4 + ii];
        }
        g_bnp1[(size_t)blockIdx.x * 16 + tid] = s;
        g_bnp2[(size_t)blockIdx.x * 16 + tid] = q;
    }
}

// ---------------- GAT: alpha dot per node (warp per node) -------------------
__global__ void gat_alpha(const float* __restrict__ h2, const float* __restrict__ a_s,
                          const float* __restrict__ a_d) {
    __shared__ float s_as[256], s_ad[256];
    int tid = threadIdx.x;  // 128
    s_as[tid] = a_s[tid]; s_ad[tid] = a_d[tid];
    s_as[tid + 128] = a_s[tid + 128]; s_ad[tid + 128] = a_d[tid + 128];
    __syncthreads();
    int w = tid >> 5, lane = tid & 31;
    int n = blockIdx.x * 4 + w;
    if (n >= NN) return;
    float ps[4] = {0.f, 0.f, 0.f, 0.f}, pd[4] = {0.f, 0.f, 0.f, 0.f};
    const float* hp = h2 + (size_t)n * 256;
#pragma unroll
    for (int j = 0; j < 8; j++) {
        int c = j * 32 + lane;
        float v = hp[c];
        ps[j >> 1] = fmaf(v, s_as[c], ps[j >> 1]);
        pd[j >> 1] = fmaf(v, s_ad[c], pd[j >> 1]);
    }
#pragma unroll
    for (int hh = 0; hh < 4; hh++) {
#pragma unroll
        for (int off = 16; off > 0; off >>= 1) {
            ps[hh] += __shfl_xor_sync(0xffffffffu, ps[hh], off);
            pd[hh] += __shfl_xor_sync(0xffffffffu, pd[hh], off);
        }
    }
    if (lane == 0) {
        *(float4*)(g_als + (size_t)n * 4) = make_float4(ps[0], ps[1], ps[2], ps[3]);
        *(float4*)(g_ald + (size_t)n * 4) = make_float4(pd[0], pd[1], pd[2], pd[3]);
    }
}

// ---------------- GAT gather + fused BN partials ----------------------------
__global__ void gat_gather_bn(const float* __restrict__ h2, const float* __restrict__ bg,
                              float* __restrict__ out) {
    __shared__ float ss[512], sq[512];
    int tid = threadIdx.x, w = tid >> 5, lane = tid & 31;
    int node = blockIdx.x * 8 + w;
    float4 adv = *(const float4*)(g_ald + (size_t)node * 4);
    float4 asv = *(const float4*)(g_als + (size_t)node * 4);
    float ad[4] = {adv.x, adv.y, adv.z, adv.w};
    float eself[4];
    {
        float as_[4] = {asv.x, asv.y, asv.z, asv.w};
#pragma unroll
        for (int hh = 0; hh < 4; hh++) {
            float lg = as_[hh] + ad[hh];
            eself[hh] = lg > 0.f ? lg : 0.2f * lg;
        }
    }
    int s0 = g_rowstart[node], s1 = g_rowstart[node + 1];
    float m[4] = {eself[0], eself[1], eself[2], eself[3]};
    for (int p = s0 + lane; p < s1; p += 32) {
        int s = g_esrc[p];
        float4 a = *(const float4*)(g_als + (size_t)s * 4);
        float lg;
        lg = a.x + ad[0]; m[0] = fmaxf(m[0], lg > 0.f ? lg : 0.2f * lg);
        lg = a.y + ad[1]; m[1] = fmaxf(m[1], lg > 0.f ? lg : 0.2f * lg);
        lg = a.z + ad[2]; m[2] = fmaxf(m[2], lg > 0.f ? lg : 0.2f * lg);
        lg = a.w + ad[3]; m[3] = fmaxf(m[3], lg > 0.f ? lg : 0.2f * lg);
    }
#pragma unroll
    for (int hh = 0; hh < 4; hh++)
#pragma unroll
        for (int off = 16; off > 0; off >>= 1)
            m[hh] = fmaxf(m[hh], __shfl_xor_sync(0xffffffffu, m[hh], off));

    float adL = ad[0], mL = m[0];
    if (lane == 1) { adL = ad[1]; mL = m[1]; }
    else if (lane == 2) { adL = ad[2]; mL = m[2]; }
    else if (lane == 3) { adL = ad[3]; mL = m[3]; }
    float acc[8] = {0.f, 0.f, 0.f, 0.f, 0.f, 0.f, 0.f, 0.f};
    float denL = 0.f;
    for (int p = s0; p < s1; p++) {
        int s = g_esrc[p];
        float ee = 0.f;
        if (lane < 4) {
            float a = g_als[(size_t)s * 4 + lane];
            float lg = a + adL;
            lg = lg > 0.f ? lg : 0.2f * lg;
            ee = __expf(lg - mL);
            denL += ee;
        }
        float ee0 = __shfl_sync(0xffffffffu, ee, 0);
        float ee1 = __shfl_sync(0xffffffffu, ee, 1);
        float ee2 = __shfl_sync(0xffffffffu, ee, 2);
        float ee3 = __shfl_sync(0xffffffffu, ee, 3);
        const float* hp = h2 + (size_t)s * 256;
        acc[0] = fmaf(ee0, hp[lane], acc[0]);
        acc[1] = fmaf(ee0, hp[32 + lane], acc[1]);
        acc[2] = fmaf(ee1, hp[64 + lane], acc[2]);
        acc[3] = fmaf(ee1, hp[96 + lane], acc[3]);
        acc[4] = fmaf(ee2, hp[128 + lane], acc[4]);
        acc[5] = fmaf(ee2, hp[160 + lane], acc[5]);
        acc[6] = fmaf(ee3, hp[192 + lane], acc[6]);
        acc[7] = fmaf(ee3, hp[224 + lane], acc[7]);
    }
    float es[4], den[4];
#pragma unroll
    for (int hh = 0; hh < 4; hh++) {
        es[hh] = __expf(eself[hh] - m[hh]);
        den[hh] = __shfl_sync(0xffffffffu, denL, hh) + es[hh];
    }
    const float* hd = h2 + (size_t)node * 256;
    float o0 = 0.f, o1 = 0.f;
#pragma unroll
    for (int hh = 0; hh < 4; hh++) {
        o0 += (acc[2 * hh]     + es[hh] * hd[hh * 64 + lane])      / den[hh];
        o1 += (acc[2 * hh + 1] + es[hh] * hd[hh * 64 + 32 + lane]) / den[hh];
    }
    float t0 = 0.25f * o0 + bg[lane];
    float t1 = 0.25f * o1 + bg[32 + lane];
    out[(size_t)node * 64 + lane]      = t0;
    out[(size_t)node * 64 + 32 + lane] = t1;
    ss[w * 64 + lane] = t0;        sq[w * 64 + lane] = t0 * t0;
    ss[w * 64 + 32 + lane] = t1;   sq[w * 64 + 32 + lane] = t1 * t1;
    __syncthreads();
    if (tid < 64) {
        float s = 0.f, q = 0.f;
#pragma unroll
        for (int w2 = 0; w2 < 8; w2++) { s += ss[w2 * 64 + tid]; q += sq[w2 * 64 + tid]; }
        g_bnp1[(size_t)blockIdx.x * 64 + tid] = s;
        g_bnp2[(size_t)blockIdx.x * 64 + tid] = q;
    }
}

// ---------------- host ----------------
static inline int cdiv(int a, int b) { return (a + b - 1) / b; }

extern "C" void kernel_launch(void* const* d_in, const int* in_sizes, int n_in,
                              void* d_out, int out_size) {
    const float* x    = (const float*)d_in[0];
    const void*  edges = d_in[1];
    const float* W1   = (const float*)d_in[2];
    const float* b1   = (const float*)d_in[3];
    const float* g1   = (const float*)d_in[4];
    const float* be1  = (const float*)d_in[5];
    const float* Wg   = (const float*)d_in[6];
    const float* a_src = (const float*)d_in[7];
    const float* a_dst = (const float*)d_in[8];
    const float* bg   = (const float*)d_in[9];
    const float* g2   = (const float*)d_in[10];
    const float* be2  = (const float*)d_in[11];
    const float* W3   = (const float*)d_in[12];
    const float* b3   = (const float*)d_in[13];
    const float* g3   = (const float*)d_in[14];
    const float* be3  = (const float*)d_in[15];
    const float* W4   = (const float*)d_in[16];
    const float* b4   = (const float*)d_in[17];
    const float* r1W  = (const float*)d_in[18];
    const float* r1b  = (const float*)d_in[19];
    const float* r2W  = (const float*)d_in[20];
    const float* r2b  = (const float*)d_in[21];
    const float* r3W  = (const float*)d_in[22];
    const float* r3b  = (const float*)d_in[23];
    const float* pW   = (const float*)d_in[24];
    const float* pb   = (const float*)d_in[25];
    float* out = (float*)d_out;

    float *h, *t, *x2, *xr, *x3, *x4, *wr;
    cudaGetSymbolAddress((void**)&h,  g_h);
    cudaGetSymbolAddress((void**)&t,  g_t);
    cudaGetSymbolAddress((void**)&x2, g_x2);
    cudaGetSymbolAddress((void**)&xr, g_xr);
    cudaGetSymbolAddress((void**)&x3, g_x3);
    cudaGetSymbolAddress((void**)&x4, g_x4);
    cudaGetSymbolAddress((void**)&wr, g_wr);

    const int SMEMB = SMEM_WORDS * 4;  // 71680
    cudaFuncSetAttribute(tf32_gemm_ca<false, false>,
                         cudaFuncAttributeMaxDynamicSharedMemorySize, SMEMB);
    cudaFuncSetAttribute(tf32_gemm_ca<true, true>,
                         cudaFuncAttributeMaxDynamicSharedMemorySize, SMEMB);
    cudaFuncSetAttribute(tf32_gemm_ca<true, false>,
                         cudaFuncAttributeMaxDynamicSharedMemorySize, SMEMB);

    const float invN = 1.0f / (float)NN;
    const int MB = cdiv(NN, 128);  // 391

    // weight offsets in g_wr (floats)
    float* wW1  = wr + 0;
    float* wr1W = wr + 65536;
    float* wWg  = wr + 131072;
    float* wr2W = wr + 196608;
    float* wW3  = wr + 212992;
    float* wr3W = wr + 214016;
    float* wpW  = wr + 215040;

    // ---- operand pre-rounding + CSR build ----
    round_weights<<<214, 256>>>((const float4*)W1, (const float4*)r1W, (const float4*)Wg,
                                (const float4*)r2W, (const float4*)W3, (const float4*)r3W,
                                (const float4*)pW);
    round_x<<<12500, 256>>>((const float4*)x);
    detect_kernel<<<1, 1>>>(edges);
    zero_indeg<<<cdiv(NN, 256), 256>>>();
    csr_count<<<cdiv(NE, 256), 256>>>(edges);
    scan1<<<NB196, 256>>>();
    scan2<<<1, 256>>>();
    scan3<<<NB196, 256>>>();
    csr_place<<<cdiv(NE, 256), 256>>>(edges);

    // ---- Stage 1: GCN(256->256) + BN + leaky + residual ----
    tf32_gemm_ca<false, false><<<dim3(2, MB), 256, SMEMB>>>(
        xr, wW1, nullptr, h, NN, 256, 256, nullptr, nullptr, nullptr);
    gcn_gather_bn256<<<GB1, 256>>>(h, b1, t);
    bn_reduce<256><<<256, 256>>>(GB1, invN);
    tf32_gemm_ca<true, true><<<dim3(2, MB), 256, SMEMB>>>(
        xr, wr1W, r1b, x2, NN, 256, 256, t, g1, be1);   // x2 written tf32-rounded

    // ---- Stage 2: GAT(4 heads, mean) + BN + leaky + residual ----
    tf32_gemm_ca<false, false><<<dim3(2, MB), 256, SMEMB>>>(
        x2, wWg, nullptr, h, NN, 256, 256, nullptr, nullptr, nullptr);
    gat_alpha<<<cdiv(NN, 4), 128>>>(h, a_src, a_dst);
    gat_gather_bn<<<GB1, 256>>>(h, bg, t);
    bn_reduce<64><<<64, 256>>>(GB1, invN);
    tf32_gemm_ca<true, true><<<dim3(1, MB), 256, SMEMB>>>(
        x2, wr2W, r2b, x3, NN, 64, 256, t, g2, be2);    // x3 written tf32-rounded

    // ---- Stage 3: GCN(64->16) + BN + leaky + residual ----
    tf32_gemm_ca<false, false><<<dim3(1, MB), 256, SMEMB>>>(
        x3, wW3, nullptr, h, NN, 16, 64, nullptr, nullptr, nullptr);
    gcn_gather16_bn<<<GB3, 256>>>(h, b3, t);
    bn_reduce<16><<<16, 256>>>(GB3, invN);
    tf32_gemm_ca<true, false><<<dim3(1, MB), 256, SMEMB>>>(
        x3, wr3W, r3b, x4, NN, 16, 64, t, g3, be3);     // x4 full fp32 (K=16 FFMA next)

    // ---- Stage 4: GCN(16->64), then final linear ----
    gemm_k16<<<NB196, 256>>>(x4, W4, h);
    gcn_gather64<<<cdiv(NN * 32, 256), 256>>>(h, b4, t);  // t written tf32-rounded
    tf32_gemm_ca<false, false><<<dim3(1, MB), 256, SMEMB>>>(
        t, wpW, pb, out, NN, 64, 64, nullptr, nullptr, nullptr);
}

// round 7
// speedup vs baseline: 2.4382x; 1.0397x over previous
#include <cuda_runtime.h>
#include <cuda_bf16.h>
#include <cstdint>

#define NN 50000
#define NE 800000
#define NB196 196   // ceil(NN/256)
#define GB1 6250    // gather blocks, stages 1/2 (NN*32/256)
#define GB3 782     // ceil(NN*4/256)
#define WRTOT 219136

// ---------------- device scratch (static, no runtime alloc) ----------------
__device__ float g_h  [NN * 256];
__device__ float g_t  [NN * 256];
__device__ float g_x2 [NN * 256];
__device__ float g_xr [NN * 256];
__device__ float g_res[NN * 256];
__device__ float g_x3 [NN * 64];
__device__ float g_x4 [NN * 16];
__device__ float g_wr [WRTOT];
__device__ float g_dinv[NN];
__device__ int   g_indeg[NN];
__device__ int   g_rowstart[NN + 1];
__device__ int   g_cursor[NN];
__device__ int   g_esrc[NE];
__device__ float g_enorm[NE];
__device__ int   g_scanpart[NN];
__device__ int   g_blocksum[NB196];
__device__ int   g_blockoff[NB196];
__device__ float g_als[NN * 4];
__device__ float g_ald[NN * 4];
__device__ float g_bnp1[GB1 * 256];
__device__ float g_bnp2[GB1 * 256];
__device__ float g_mu  [256];
__device__ float g_rstd[256];
__device__ int   g_e64;

__device__ __forceinline__ uint32_t f2tf32(float x) {
    uint32_t r;
    asm("cvt.rna.tf32.f32 %0, %1;" : "=r"(r) : "f"(x));
    return r;
}
__device__ __forceinline__ float f2tf32f(float x) { return __uint_as_float(f2tf32(x)); }

// ---------------- edge dtype detect ----------------
__global__ void detect_kernel(const void* edges) {
    const int2* q = (const int2*)edges;
    int all0 = 1;
    for (int k = 0; k < 64; k++) {
        if (q[k * 12497 + 3].y != 0) { all0 = 0; break; }
    }
    g_e64 = all0;
}

__global__ void zero_indeg() {
    int i = blockIdx.x * blockDim.x + threadIdx.x;
    if (i < NN) g_indeg[i] = 0;
}

__global__ void csr_count(const void* edges) {
    int e = blockIdx.x * blockDim.x + threadIdx.x;
    if (e >= NE) return;
    int d;
    if (g_e64) d = (int)((const long long*)edges)[NE + e];
    else       d = ((const int*)edges)[NE + e];
    atomicAdd(&g_indeg[d], 1);
}

// ---------------- parallel exclusive scan over indeg ------------------------
__global__ void scan1() {
    int b = blockIdx.x, t = threadIdx.x;
    int i = b * 256 + t;
    int d = (i < NN) ? g_indeg[i] : 0;
    int lane = t & 31, w = t >> 5;
    int v = d;
#pragma unroll
    for (int off = 1; off < 32; off <<= 1) {
        int u = __shfl_up_sync(0xffffffffu, v, off);
        if (lane >= off) v += u;
    }
    __shared__ int ws[8];
    if (lane == 31) ws[w] = v;
    __syncthreads();
    if (t == 0) {
        int run = 0;
        for (int j = 0; j < 8; j++) { int x = ws[j]; ws[j] = run; run += x; }
    }
    __syncthreads();
    v += ws[w];
    if (i < NN) g_scanpart[i] = v;
    if (t == 255) g_blocksum[b] = v;
}

__global__ void scan2() {
    int t = threadIdx.x;
    int d = (t < NB196) ? g_blocksum[t] : 0;
    int lane = t & 31, w = t >> 5;
    int v = d;
#pragma unroll
    for (int off = 1; off < 32; off <<= 1) {
        int u = __shfl_up_sync(0xffffffffu, v, off);
        if (lane >= off) v += u;
    }
    __shared__ int ws[8];
    if (lane == 31) ws[w] = v;
    __syncthreads();
    if (t == 0) {
        int run = 0;
        for (int j = 0; j < 8; j++) { int x = ws[j]; ws[j] = run; run += x; }
    }
    __syncthreads();
    v += ws[w];
    if (t < NB196) g_blockoff[t] = v - d;
}

__global__ void scan3() {
    int i = blockIdx.x * blockDim.x + threadIdx.x;
    if (i < NN) {
        int deg = g_indeg[i];
        int excl = g_blockoff[blockIdx.x] + g_scanpart[i] - deg;
        g_rowstart[i] = excl;
        g_cursor[i] = excl;
        g_dinv[i] = rsqrtf((float)deg + 1.0f);
    }
    if (i == 0) g_rowstart[NN] = NE;
}

__global__ void csr_place(const void* edges) {
    int e = blockIdx.x * blockDim.x + threadIdx.x;
    if (e >= NE) return;
    int s, d;
    if (g_e64) {
        s = (int)((const long long*)edges)[e];
        d = (int)((const long long*)edges)[NE + e];
    } else {
        s = ((const int*)edges)[e];
        d = ((const int*)edges)[NE + e];
    }
    int pos = atomicAdd(&g_cursor[d], 1);
    g_esrc[pos] = s;
    g_enorm[pos] = g_dinv[s] * g_dinv[d];
}

// ---------------- operand pre-rounding (tf32 RN) ----------------------------
__global__ void round_x(const float4* __restrict__ x) {
    int i = blockIdx.x * 256 + threadIdx.x;   // 3,200,000 float4
    if (i >= NN * 64) return;
    float4 v = x[i];
    v.x = f2tf32f(v.x); v.y = f2tf32f(v.y); v.z = f2tf32f(v.z); v.w = f2tf32f(v.w);
    ((float4*)g_xr)[i] = v;
}

__global__ void round_weights(const float4* W1, const float4* r1W, const float4* Wg,
                              const float4* r2W, const float4* W3, const float4* r3W,
                              const float4* pW) {
    int i = blockIdx.x * 256 + threadIdx.x;   // 54784 float4
    if (i >= 54784) return;
    const float4* s; int b;
    if      (i < 16384) { s = W1;  b = 0; }
    else if (i < 32768) { s = r1W; b = 16384; }
    else if (i < 49152) { s = Wg;  b = 32768; }
    else if (i < 53248) { s = r2W; b = 49152; }
    else if (i < 53504) { s = W3;  b = 53248; }
    else if (i < 53760) { s = r3W; b = 53504; }
    else                { s = pW;  b = 53760; }
    float4 v = s[i - b];
    v.x = f2tf32f(v.x); v.y = f2tf32f(v.y); v.z = f2tf32f(v.z); v.w = f2tf32f(v.w);
    ((float4*)g_wr)[i] = v;
}

// ---------------- BN partial reduce ----------------------------------------
template <int C>
__global__ void bn_reduce(int nblocks, float invN) {
    int c = blockIdx.x, t = threadIdx.x;
    double s = 0.0, q = 0.0;
    for (int b = t; b < nblocks; b += 256) {
        s += (double)g_bnp1[(size_t)b * C + c];
        q += (double)g_bnp2[(size_t)b * C + c];
    }
    __shared__ double sh[256], sh2[256];
    sh[t] = s; sh2[t] = q;
    __syncthreads();
    for (int off = 128; off; off >>= 1) {
        if (t < off) { sh[t] += sh[t + off]; sh2[t] += sh2[t + off]; }
        __syncthreads();
    }
    if (t == 0) {
        double m = sh[0] * (double)invN;
        double v = sh2[0] * (double)invN - m * m;
        g_mu[c] = (float)m;
        g_rstd[c] = rsqrtf((float)v + 1e-5f);
    }
}

// ---------------- BN+leaky+residual fuse (elementwise), tf32-rounded out ---
template <int C>
__global__ void fuse_res(const float4* __restrict__ t, const float4* __restrict__ res,
                         const float* __restrict__ g, const float* __restrict__ be,
                         float4* __restrict__ out, int n4) {
    int i = blockIdx.x * 256 + threadIdx.x;
    if (i >= n4) return;
    int c0 = (i * 4) & (C - 1);
    float4 tv = t[i], rv = res[i];
    float4 o;
    float u;
    u = (tv.x - g_mu[c0    ]) * g_rstd[c0    ] * g[c0    ] + be[c0    ];
    o.x = f2tf32f((u > 0.f ? u : 0.01f * u) + rv.x);
    u = (tv.y - g_mu[c0 + 1]) * g_rstd[c0 + 1] * g[c0 + 1] + be[c0 + 1];
    o.y = f2tf32f((u > 0.f ? u : 0.01f * u) + rv.y);
    u = (tv.z - g_mu[c0 + 2]) * g_rstd[c0 + 2] * g[c0 + 2] + be[c0 + 2];
    o.z = f2tf32f((u > 0.f ? u : 0.01f * u) + rv.z);
    u = (tv.w - g_mu[c0 + 3]) * g_rstd[c0 + 3] * g[c0 + 3] + be[c0 + 3];
    o.w = f2tf32f((u > 0.f ? u : 0.01f * u) + rv.w);
    out[i] = o;
}

// ---------------- tf32 tensor-core GEMM, 3-stage cp.async -------------------
// Inputs A,B pre-rounded tf32. Block tile 128x128x32.
// FUSE: C = leaky(BN(T)) + A@B + bias.  ROUND: round output to tf32.
#define ASTRIDE 36
#define BSTRIDE 136
#define ASZ (128 * ASTRIDE)      // 4608 words
#define BSZ (32 * BSTRIDE)       // 4352 words
#define STG (ASZ + BSZ)          // 8960 words per stage
#define SMEM_WORDS (3 * STG)     // 26880 words = 107520 B

template <bool FUSE, bool ROUND>
__global__ __launch_bounds__(256, 2)
void tf32_gemm_ca(const float* __restrict__ A, const float* __restrict__ B,
                  const float* __restrict__ bias, float* __restrict__ C,
                  int M, int Nn, int K,
                  const float* __restrict__ T, const float* __restrict__ gam,
                  const float* __restrict__ bet) {
    extern __shared__ uint32_t sm[];
    const int tid = threadIdx.x;
    const int warp = tid >> 5, lane = tid & 31;
    const int wm = warp >> 1, wn = warp & 1;
    const int g = lane >> 2, t4 = lane & 3;
    const int rowBase = blockIdx.y * 128;
    const int colBase = blockIdx.x * 128;
    const uint32_t sbase = (uint32_t)__cvta_generic_to_shared(sm);

    const int arow = tid >> 3, ac4 = (tid & 7) * 4;
    const int brow = tid >> 5, bc4 = (tid & 31) * 4;

    float acc[2][8][4];
#pragma unroll
    for (int mi = 0; mi < 2; mi++)
#pragma unroll
        for (int ni = 0; ni < 8; ni++)
#pragma unroll
            for (int j = 0; j < 4; j++) acc[mi][ni][j] = 0.0f;

    const int nk = K >> 5;

    auto loadTile = [&](int k0i) {
        int buf = k0i % 3;
        int k0 = k0i << 5;
        uint32_t bufb = sbase + (uint32_t)(buf * STG) * 4u;
#pragma unroll
        for (int q = 0; q < 4; q++) {
            int r = q * 32 + arow;
            const float* src = A + (size_t)(rowBase + r) * K + k0 + ac4;
            uint32_t dst = bufb + (uint32_t)(r * ASTRIDE + ac4) * 4u;
            int sz = (rowBase + r < M) ? 16 : 0;
            asm volatile("cp.async.cg.shared.global [%0], [%1], 16, %2;\n"
                         :: "r"(dst), "l"(src), "r"(sz));
        }
#pragma unroll
        for (int q = 0; q < 4; q++) {
            int r = q * 8 + brow;
            const float* src = B + (size_t)(k0 + r) * Nn + colBase + bc4;
            uint32_t dst = bufb + (uint32_t)(ASZ + r * BSTRIDE + bc4) * 4u;
            int sz = (colBase + bc4 + 4 <= Nn) ? 16 : 0;
            asm volatile("cp.async.cg.shared.global [%0], [%1], 16, %2;\n"
                         :: "r"(dst), "l"(src), "r"(sz));
        }
        asm volatile("cp.async.commit_group;\n");
    };

    loadTile(0);
    if (nk > 1) loadTile(1);

    for (int k0i = 0; k0i < nk; k0i++) {
        if (k0i + 1 < nk) asm volatile("cp.async.wait_group 1;\n");
        else              asm volatile("cp.async.wait_group 0;\n");
        __syncthreads();
        if (k0i + 2 < nk) loadTile(k0i + 2);

        const uint32_t* As = sm + (k0i % 3) * STG;
        const uint32_t* Bs = As + ASZ;

#pragma unroll
        for (int kk = 0; kk < 32; kk += 8) {
            uint32_t af[2][4];
#pragma unroll
            for (int mi = 0; mi < 2; mi++) {
                int r = wm * 32 + mi * 16;
                af[mi][0] = As[(r + g) * ASTRIDE + kk + t4];
                af[mi][1] = As[(r + g + 8) * ASTRIDE + kk + t4];
                af[mi][2] = As[(r + g) * ASTRIDE + kk + t4 + 4];
                af[mi][3] = As[(r + g + 8) * ASTRIDE + kk + t4 + 4];
            }
            uint32_t bf[8][2];
#pragma unroll
            for (int ni = 0; ni < 8; ni++) {
                int c = wn * 64 + ni * 8 + g;
                bf[ni][0] = Bs[(kk + t4) * BSTRIDE + c];
                bf[ni][1] = Bs[(kk + t4 + 4) * BSTRIDE + c];
            }
#pragma unroll
            for (int mi = 0; mi < 2; mi++)
#pragma unroll
                for (int ni = 0; ni < 8; ni++) {
                    asm volatile(
                        "mma.sync.aligned.m16n8k8.row.col.f32.tf32.tf32.f32 "
                        "{%0,%1,%2,%3}, {%4,%5,%6,%7}, {%8,%9}, {%0,%1,%2,%3};"
                        : "+f"(acc[mi][ni][0]), "+f"(acc[mi][ni][1]),
                          "+f"(acc[mi][ni][2]), "+f"(acc[mi][ni][3])
                        : "r"(af[mi][0]), "r"(af[mi][1]), "r"(af[mi][2]), "r"(af[mi][3]),
                          "r"(bf[ni][0]), "r"(bf[ni][1]));
                }
        }
    }

#pragma unroll
    for (int mi = 0; mi < 2; mi++) {
#pragma unroll
        for (int ni = 0; ni < 8; ni++) {
            int r0 = rowBase + wm * 32 + mi * 16 + g;
            int c0 = colBase + wn * 64 + ni * 8 + t4 * 2;
            if (c0 >= Nn) continue;
            float bx = bias ? bias[c0] : 0.0f;
            float by = bias ? bias[c0 + 1] : 0.0f;
#pragma unroll
            for (int half = 0; half < 2; half++) {
                int r = r0 + half * 8;
                if (r >= M) continue;
                float vx = acc[mi][ni][half * 2] + bx;
                float vy = acc[mi][ni][half * 2 + 1] + by;
                if (FUSE) {
                    float2 tv = *(const float2*)(T + (size_t)r * Nn + c0);
                    float ux = (tv.x - g_mu[c0]) * g_rstd[c0] * gam[c0] + bet[c0];
                    float uy = (tv.y - g_mu[c0 + 1]) * g_rstd[c0 + 1] * gam[c0 + 1] + bet[c0 + 1];
                    ux = ux > 0.f ? ux : 0.01f * ux;
                    uy = uy > 0.f ? uy : 0.01f * uy;
                    vx += ux; vy += uy;
                }
                if (ROUND) { vx = f2tf32f(vx); vy = f2tf32f(vy); }
                *(float2*)(C + (size_t)r * Nn + c0) = make_float2(vx, vy);
            }
        }
    }
}

// ---------------- narrow FFMA GEMM: M x 64, K=16 (stage-4 W4) ---------------
__global__ void gemm_k16(const float* __restrict__ A, const float* __restrict__ B,
                         float* __restrict__ C) {
    __shared__ float Bs[16 * 64];
    int tid = threadIdx.x;
    ((float4*)Bs)[tid] = ((const float4*)B)[tid];
    __syncthreads();
    int row = blockIdx.x * 256 + tid;
    if (row >= NN) return;
    float a[16];
#pragma unroll
    for (int q = 0; q < 4; q++) {
        float4 v = *(const float4*)(A + (size_t)row * 16 + q * 4);
        a[q * 4] = v.x; a[q * 4 + 1] = v.y; a[q * 4 + 2] = v.z; a[q * 4 + 3] = v.w;
    }
    float acc[64];
#pragma unroll
    for (int c = 0; c < 64; c++) acc[c] = 0.0f;
#pragma unroll
    for (int k = 0; k < 16; k++) {
        float av = a[k];
#pragma unroll
        for (int c = 0; c < 64; c++) acc[c] = fmaf(av, Bs[k * 64 + c], acc[c]);
    }
#pragma unroll
    for (int q = 0; q < 16; q++) {
        *(float4*)(C + (size_t)row * 64 + q * 4) =
            make_float4(acc[q * 4], acc[q * 4 + 1], acc[q * 4 + 2], acc[q * 4 + 3]);
    }
}

// ---------------- GCN gather + fused BN partials ----------------------------
__global__ void gcn_gather_bn256(const float* __restrict__ h, const float* __restrict__ bias,
                                 float* __restrict__ out) {
    __shared__ float ss[2048], sq[2048];
    int tid = threadIdx.x, w = tid >> 5, lane = tid & 31;
    int node = blockIdx.x * 8 + w;
    float acc[8];
#pragma unroll
    for (int j = 0; j < 8; j++) acc[j] = 0.0f;
    float dv = g_dinv[node];
    int s0 = g_rowstart[node], s1 = g_rowstart[node + 1];
    for (int p = s0; p < s1; p++) {
        int s = g_esrc[p];
        float norm = g_enorm[p];
        const float* hp = h + (size_t)s * 256;
#pragma unroll
        for (int j = 0; j < 8; j++) acc[j] = fmaf(norm, hp[j * 32 + lane], acc[j]);
    }
    const float* hd = h + (size_t)node * 256;
    float self = dv * dv;
#pragma unroll
    for (int j = 0; j < 8; j++) {
        int c = j * 32 + lane;
        float v = acc[j] + self * hd[c] + bias[c];
        out[(size_t)node * 256 + c] = v;
        ss[w * 256 + c] = v;
        sq[w * 256 + c] = v * v;
    }
    __syncthreads();
    float s = 0.f, q = 0.f;
#pragma unroll
    for (int w2 = 0; w2 < 8; w2++) { s += ss[w2 * 256 + tid]; q += sq[w2 * 256 + tid]; }
    g_bnp1[(size_t)blockIdx.x * 256 + tid] = s;
    g_bnp2[(size_t)blockIdx.x * 256 + tid] = q;
}

// stage-4 gather, C=64; output rounded to tf32 (feeds pW tf32 GEMM)
__global__ void gcn_gather64(const float* __restrict__ h, const float* __restrict__ bias,
                             float* __restrict__ out) {
    int warp = (blockIdx.x * blockDim.x + threadIdx.x) >> 5;
    int lane = threadIdx.x & 31;
    if (warp >= NN) return;
    float a0 = 0.f, a1 = 0.f;
    float dv = g_dinv[warp];
    int s0 = g_rowstart[warp], s1 = g_rowstart[warp + 1];
    for (int p = s0; p < s1; p++) {
        int s = g_esrc[p];
        float norm = g_enorm[p];
        const float* hp = h + (size_t)s * 64;
        a0 = fmaf(norm, hp[lane], a0);
        a1 = fmaf(norm, hp[32 + lane], a1);
    }
    const float* hd = h + (size_t)warp * 64;
    float self = dv * dv;
    out[(size_t)warp * 64 + lane]      = f2tf32f(a0 + self * hd[lane] + bias[lane]);
    out[(size_t)warp * 64 + 32 + lane] = f2tf32f(a1 + self * hd[32 + lane] + bias[32 + lane]);
}

// C=16 gather + BN partials: 256 threads = 64 nodes (4 threads/node)
__global__ void gcn_gather16_bn(const float* __restrict__ h, const float* __restrict__ bias,
                                float* __restrict__ out) {
    __shared__ float ss[1024], sq[1024];
    int tid = threadIdx.x;
    int idx = blockIdx.x * 256 + tid;
    int node = idx >> 2, q4 = idx & 3;
    float ox = 0.f, oy = 0.f, oz = 0.f, ow = 0.f;
    if (node < NN) {
        float ax = 0.f, ay = 0.f, az = 0.f, aw = 0.f;
        float dv = g_dinv[node];
        int s0 = g_rowstart[node], s1 = g_rowstart[node + 1];
        for (int p = s0; p < s1; p++) {
            int s = g_esrc[p];
            float norm = g_enorm[p];
            float4 v = *(const float4*)(h + (size_t)s * 16 + q4 * 4);
            ax = fmaf(norm, v.x, ax); ay = fmaf(norm, v.y, ay);
            az = fmaf(norm, v.z, az); aw = fmaf(norm, v.w, aw);
        }
        float4 hv = *(const float4*)(h + (size_t)node * 16 + q4 * 4);
        float4 bv = *(const float4*)(bias + q4 * 4);
        float self = dv * dv;
        ox = ax + self * hv.x + bv.x;
        oy = ay + self * hv.y + bv.y;
        oz = az + self * hv.z + bv.z;
        ow = aw + self * hv.w + bv.w;
        *(float4*)(out + (size_t)node * 16 + q4 * 4) = make_float4(ox, oy, oz, ow);
    }
    ss[tid * 4 + 0] = ox; sq[tid * 4 + 0] = ox * ox;
    ss[tid * 4 + 1] = oy; sq[tid * 4 + 1] = oy * oy;
    ss[tid * 4 + 2] = oz; sq[tid * 4 + 2] = oz * oz;
    ss[tid * 4 + 3] = ow; sq[tid * 4 + 3] = ow * ow;
    __syncthreads();
    if (tid < 16) {
        int qq = tid >> 2, ii = tid & 3;
        float s = 0.f, q = 0.f;
        for (int nl = 0; nl < 64; nl++) {
            s += ss[(nl * 4 + qq) * 4 + ii];
            q += sq[(nl * 4 + qq) * 4 + ii];
        }
        g_bnp1[(size_t)blockIdx.x * 16 + tid] = s;
        g_bnp2[(size_t)blockIdx.x * 16 + tid] = q;
    }
}

// ---------------- GAT: alpha dot per node (warp per node) -------------------
__global__ void gat_alpha(const float* __restrict__ h2, const float* __restrict__ a_s,
                          const float* __restrict__ a_d) {
    __shared__ float s_as[256], s_ad[256];
    int tid = threadIdx.x;  // 128
    s_as[tid] = a_s[tid]; s_ad[tid] = a_d[tid];
    s_as[tid + 128] = a_s[tid + 128]; s_ad[tid + 128] = a_d[tid + 128];
    __syncthreads();
    int w = tid >> 5, lane = tid & 31;
    int n = blockIdx.x * 4 + w;
    if (n >= NN) return;
    float ps[4] = {0.f, 0.f, 0.f, 0.f}, pd[4] = {0.f, 0.f, 0.f, 0.f};
    const float* hp = h2 + (size_t)n * 256;
#pragma unroll
    for (int j = 0; j < 8; j++) {
        int c = j * 32 + lane;
        float v = hp[c];
        ps[j >> 1] = fmaf(v, s_as[c], ps[j >> 1]);
        pd[j >> 1] = fmaf(v, s_ad[c], pd[j >> 1]);
    }
#pragma unroll
    for (int hh = 0; hh < 4; hh++) {
#pragma unroll
        for (int off = 16; off > 0; off >>= 1) {
            ps[hh] += __shfl_xor_sync(0xffffffffu, ps[hh], off);
            pd[hh] += __shfl_xor_sync(0xffffffffu, pd[hh], off);
        }
    }
    if (lane == 0) {
        *(float4*)(g_als + (size_t)n * 4) = make_float4(ps[0], ps[1], ps[2], ps[3]);
        *(float4*)(g_ald + (size_t)n * 4) = make_float4(pd[0], pd[1], pd[2], pd[3]);
    }
}

// ---------------- GAT gather + fused BN partials ----------------------------
__global__ void gat_gather_bn(const float* __restrict__ h2, const float* __restrict__ bg,
                              float* __restrict__ out) {
    __shared__ float ss[512], sq[512];
    int tid = threadIdx.x, w = tid >> 5, lane = tid & 31;
    int node = blockIdx.x * 8 + w;
    float4 adv = *(const float4*)(g_ald + (size_t)node * 4);
    float4 asv = *(const float4*)(g_als + (size_t)node * 4);
    float ad[4] = {adv.x, adv.y, adv.z, adv.w};
    float eself[4];
    {
        float as_[4] = {asv.x, asv.y, asv.z, asv.w};
#pragma unroll
        for (int hh = 0; hh < 4; hh++) {
            float lg = as_[hh] + ad[hh];
            eself[hh] = lg > 0.f ? lg : 0.2f * lg;
        }
    }
    int s0 = g_rowstart[node], s1 = g_rowstart[node + 1];
    float m[4] = {eself[0], eself[1], eself[2], eself[3]};
    for (int p = s0 + lane; p < s1; p += 32) {
        int s = g_esrc[p];
        float4 a = *(const float4*)(g_als + (size_t)s * 4);
        float lg;
        lg = a.x + ad[0]; m[0] = fmaxf(m[0], lg > 0.f ? lg : 0.2f * lg);
        lg = a.y + ad[1]; m[1] = fmaxf(m[1], lg > 0.f ? lg : 0.2f * lg);
        lg = a.z + ad[2]; m[2] = fmaxf(m[2], lg > 0.f ? lg : 0.2f * lg);
        lg = a.w + ad[3]; m[3] = fmaxf(m[3], lg > 0.f ? lg : 0.2f * lg);
    }
#pragma unroll
    for (int hh = 0; hh < 4; hh++)
#pragma unroll
        for (int off = 16; off > 0; off >>= 1)
            m[hh] = fmaxf(m[hh], __shfl_xor_sync(0xffffffffu, m[hh], off));

    float adL = ad[0], mL = m[0];
    if (lane == 1) { adL = ad[1]; mL = m[1]; }
    else if (lane == 2) { adL = ad[2]; mL = m[2]; }
    else if (lane == 3) { adL = ad[3]; mL = m[3]; }
    float acc[8] = {0.f, 0.f, 0.f, 0.f, 0.f, 0.f, 0.f, 0.f};
    float denL = 0.f;
    for (int p = s0; p < s1; p++) {
        int s = g_esrc[p];
        float ee = 0.f;
        if (lane < 4) {
            float a = g_als[(size_t)s * 4 + lane];
            float lg = a + adL;
            lg = lg > 0.f ? lg : 0.2f * lg;
            ee = __expf(lg - mL);
            denL += ee;
        }
        float ee0 = __shfl_sync(0xffffffffu, ee, 0);
        float ee1 = __shfl_sync(0xffffffffu, ee, 1);
        float ee2 = __shfl_sync(0xffffffffu, ee, 2);
        float ee3 = __shfl_sync(0xffffffffu, ee, 3);
        const float* hp = h2 + (size_t)s * 256;
        acc[0] = fmaf(ee0, hp[lane], acc[0]);
        acc[1] = fmaf(ee0, hp[32 + lane], acc[1]);
        acc[2] = fmaf(ee1, hp[64 + lane], acc[2]);
        acc[3] = fmaf(ee1, hp[96 + lane], acc[3]);
        acc[4] = fmaf(ee2, hp[128 + lane], acc[4]);
        acc[5] = fmaf(ee2, hp[160 + lane], acc[5]);
        acc[6] = fmaf(ee3, hp[192 + lane], acc[6]);
        acc[7] = fmaf(ee3, hp[224 + lane], acc[7]);
    }
    float es[4], den[4];
#pragma unroll
    for (int hh = 0; hh < 4; hh++) {
        es[hh] = __expf(eself[hh] - m[hh]);
        den[hh] = __shfl_sync(0xffffffffu, denL, hh) + es[hh];
    }
    const float* hd = h2 + (size_t)node * 256;
    float o0 = 0.f, o1 = 0.f;
#pragma unroll
    for (int hh = 0; hh < 4; hh++) {
        o0 += (acc[2 * hh]     + es[hh] * hd[hh * 64 + lane])      / den[hh];
        o1 += (acc[2 * hh + 1] + es[hh] * hd[hh * 64 + 32 + lane]) / den[hh];
    }
    float t0 = 0.25f * o0 + bg[lane];
    float t1 = 0.25f * o1 + bg[32 + lane];
    out[(size_t)node * 64 + lane]      = t0;
    out[(size_t)node * 64 + 32 + lane] = t1;
    ss[w * 64 + lane] = t0;        sq[w * 64 + lane] = t0 * t0;
    ss[w * 64 + 32 + lane] = t1;   sq[w * 64 + 32 + lane] = t1 * t1;
    __syncthreads();
    if (tid < 64) {
        float s = 0.f, q = 0.f;
#pragma unroll
        for (int w2 = 0; w2 < 8; w2++) { s += ss[w2 * 64 + tid]; q += sq[w2 * 64 + tid]; }
        g_bnp1[(size_t)blockIdx.x * 64 + tid] = s;
        g_bnp2[(size_t)blockIdx.x * 64 + tid] = q;
    }
}

// ---------------- host ----------------
static inline int cdiv(int a, int b) { return (a + b - 1) / b; }

extern "C" void kernel_launch(void* const* d_in, const int* in_sizes, int n_in,
                              void* d_out, int out_size) {
    const float* x    = (const float*)d_in[0];
    const void*  edges = d_in[1];
    const float* W1   = (const float*)d_in[2];
    const float* b1   = (const float*)d_in[3];
    const float* g1   = (const float*)d_in[4];
    const float* be1  = (const float*)d_in[5];
    const float* Wg   = (const float*)d_in[6];
    const float* a_src = (const float*)d_in[7];
    const float* a_dst = (const float*)d_in[8];
    const float* bg   = (const float*)d_in[9];
    const float* g2   = (const float*)d_in[10];
    const float* be2  = (const float*)d_in[11];
    const float* W3   = (const float*)d_in[12];
    const float* b3   = (const float*)d_in[13];
    const float* g3   = (const float*)d_in[14];
    const float* be3  = (const float*)d_in[15];
    const float* W4   = (const float*)d_in[16];
    const float* b4   = (const float*)d_in[17];
    const float* r1b  = (const float*)d_in[19];
    const float* r2b  = (const float*)d_in[21];
    const float* r3b  = (const float*)d_in[23];
    const float* pb   = (const float*)d_in[25];
    float* out = (float*)d_out;

    float *h, *t, *x2, *xr, *res, *x3, *x4, *wr;
    cudaGetSymbolAddress((void**)&h,   g_h);
    cudaGetSymbolAddress((void**)&t,   g_t);
    cudaGetSymbolAddress((void**)&x2,  g_x2);
    cudaGetSymbolAddress((void**)&xr,  g_xr);
    cudaGetSymbolAddress((void**)&res, g_res);
    cudaGetSymbolAddress((void**)&x3,  g_x3);
    cudaGetSymbolAddress((void**)&x4,  g_x4);
    cudaGetSymbolAddress((void**)&wr,  g_wr);

    // lazy one-time infra (streams/events are not device memory)
    static cudaStream_t s1 = nullptr;
    static cudaEvent_t evFork = nullptr, evCSR = nullptr, evXR = nullptr,
                       evG1 = nullptr, evX2 = nullptr, evG2 = nullptr;
    if (s1 == nullptr) {
        cudaStreamCreateWithFlags(&s1, cudaStreamNonBlocking);
        cudaEventCreateWithFlags(&evFork, cudaEventDisableTiming);
        cudaEventCreateWithFlags(&evCSR,  cudaEventDisableTiming);
        cudaEventCreateWithFlags(&evXR,   cudaEventDisableTiming);
        cudaEventCreateWithFlags(&evG1,   cudaEventDisableTiming);
        cudaEventCreateWithFlags(&evX2,   cudaEventDisableTiming);
        cudaEventCreateWithFlags(&evG2,   cudaEventDisableTiming);
        const int SMEMB_ = SMEM_WORDS * 4;
        cudaFuncSetAttribute(tf32_gemm_ca<false, false>,
                             cudaFuncAttributeMaxDynamicSharedMemorySize, SMEMB_);
        cudaFuncSetAttribute(tf32_gemm_ca<true, false>,
                             cudaFuncAttributeMaxDynamicSharedMemorySize, SMEMB_);
    }
    const int SMEMB = SMEM_WORDS * 4;  // 107520

    const float invN = 1.0f / (float)NN;
    const int MB = cdiv(NN, 128);  // 391

    float* wW1  = wr + 0;
    float* wr1W = wr + 65536;
    float* wWg  = wr + 131072;
    float* wr2W = wr + 196608;
    float* wW3  = wr + 212992;
    float* wr3W = wr + 214016;
    float* wpW  = wr + 215040;

    // ---- fork: CSR chain on s1, rounding + GEMM1 on main ----
    cudaEventRecord(evFork, 0);
    cudaStreamWaitEvent(s1, evFork, 0);
    detect_kernel<<<1, 1, 0, s1>>>(edges);
    zero_indeg<<<cdiv(NN, 256), 256, 0, s1>>>();
    csr_count<<<cdiv(NE, 256), 256, 0, s1>>>(edges);
    scan1<<<NB196, 256, 0, s1>>>();
    scan2<<<1, 256, 0, s1>>>();
    scan3<<<NB196, 256, 0, s1>>>();
    csr_place<<<cdiv(NE, 256), 256, 0, s1>>>(edges);
    cudaEventRecord(evCSR, s1);

    round_weights<<<214, 256>>>((const float4*)d_in[2], (const float4*)d_in[18],
                                (const float4*)d_in[6], (const float4*)d_in[20],
                                (const float4*)d_in[12], (const float4*)d_in[22],
                                (const float4*)d_in[24]);
    round_x<<<12500, 256>>>((const float4*)x);
    cudaEventRecord(evXR, 0);
    tf32_gemm_ca<false, false><<<dim3(2, MB), 256, SMEMB>>>(
        xr, wW1, nullptr, h, NN, 256, 256, nullptr, nullptr, nullptr);

    // ---- Stage 1: gather+BN on main; r1W GEMM concurrently on s1 ----
    cudaStreamWaitEvent(0, evCSR, 0);
    gcn_gather_bn256<<<GB1, 256>>>(h, b1, t);
    cudaStreamWaitEvent(s1, evXR, 0);
    tf32_gemm_ca<false, false><<<dim3(2, MB), 256, SMEMB, s1>>>(
        xr, wr1W, r1b, res, NN, 256, 256, nullptr, nullptr, nullptr);
    cudaEventRecord(evG1, s1);
    bn_reduce<256><<<256, 256>>>(GB1, invN);
    cudaStreamWaitEvent(0, evG1, 0);
    fuse_res<256><<<12500, 256>>>((const float4*)t, (const float4*)res, g1, be1,
                                  (float4*)x2, NN * 64);
    cudaEventRecord(evX2, 0);

    // ---- Stage 2: Wg GEMM + GAT on main; r2W GEMM concurrently on s1 ----
    tf32_gemm_ca<false, false><<<dim3(2, MB), 256, SMEMB>>>(
        x2, wWg, nullptr, h, NN, 256, 256, nullptr, nullptr, nullptr);
    cudaStreamWaitEvent(s1, evX2, 0);
    tf32_gemm_ca<false, false><<<dim3(1, MB), 256, SMEMB, s1>>>(
        x2, wr2W, r2b, res, NN, 64, 256, nullptr, nullptr, nullptr);
    cudaEventRecord(evG2, s1);
    gat_alpha<<<cdiv(NN, 4), 128>>>(h, a_src, a_dst);
    gat_gather_bn<<<GB1, 256>>>(h, bg, t);
    bn_reduce<64><<<64, 256>>>(GB1, invN);
    cudaStreamWaitEvent(0, evG2, 0);
    fuse_res<64><<<3125, 256>>>((const float4*)t, (const float4*)res, g2, be2,
                                (float4*)x3, NN * 16);

    // ---- Stage 3: GCN(64->16) + BN + leaky + residual (sequential, small) --
    tf32_gemm_ca<false, false><<<dim3(1, MB), 256, SMEMB>>>(
        x3, wW3, nullptr, h, NN, 16, 64, nullptr, nullptr, nullptr);
    gcn_gather16_bn<<<GB3, 256>>>(h, b3, t);
    bn_reduce<16><<<16, 256>>>(GB3, invN);
    tf32_gemm_ca<true, false><<<dim3(1, MB), 256, SMEMB>>>(
        x3, wr3W, r3b, x4, NN, 16, 64, t, g3, be3);

    // ---- Stage 4: GCN(16->64), then final linear ----
    gemm_k16<<<NB196, 256>>>(x4, W4, h);
    gcn_gather64<<<cdiv(NN * 32, 256), 256>>>(h, b4, t);
    tf32_gemm_ca<false, false><<<dim3(1, MB), 256, SMEMB>>>(
        t, wpW, pb, out, NN, 64, 64, nullptr, nullptr, nullptr);
}

// round 11
// speedup vs baseline: 2.4388x; 1.0002x over previous
#include <cuda_runtime.h>
#include <cuda_bf16.h>
#include <cstdint>

#define NN 50000
#define NE 800000
#define NB196 196   // ceil(NN/256)
#define GB1 6250    // gather blocks, stages 1/2 (NN*32/256)
#define GB3 782     // ceil(NN*4/256)
#define WRTOT 219136

// ---------------- device scratch (static, no runtime alloc) ----------------
__device__ float g_h  [NN * 256];
__device__ float g_t  [NN * 256];
__device__ float g_x2 [NN * 256];
__device__ float g_xr [NN * 256];
__device__ float g_res[NN * 256];
__device__ float g_x3 [NN * 64];
__device__ float g_x4 [NN * 16];
__device__ float g_wr [WRTOT];
__device__ float g_ws [256 * 4];
__device__ float g_wd [256 * 4];
__device__ float g_w2comb[256 * 384];
__device__ float g_w3comb[64 * 32];
__device__ float g_dinv[NN];
__device__ int   g_indeg[NN];
__device__ int   g_rowstart[NN + 1];
__device__ int   g_cursor[NN];
__device__ float2 g_epack[NE];
__device__ int   g_scanpart[NN];
__device__ int   g_blocksum[NB196];
__device__ int   g_blockoff[NB196];
__device__ float g_als[NN * 4];
__device__ float g_ald[NN * 4];
__device__ float g_bnp1[GB1 * 256];
__device__ float g_bnp2[GB1 * 256];
__device__ float g_mu  [256];
__device__ float g_rstd[256];
__device__ int   g_e64;

__device__ __forceinline__ uint32_t f2tf32(float x) {
    uint32_t r;
    asm("cvt.rna.tf32.f32 %0, %1;" : "=r"(r) : "f"(x));
    return r;
}
__device__ __forceinline__ float f2tf32f(float x) { return __uint_as_float(f2tf32(x)); }

// ---------------- edge dtype detect ----------------
__global__ void detect_kernel(const void* edges) {
    const int2* q = (const int2*)edges;
    int all0 = 1;
    for (int k = 0; k < 64; k++) {
        if (q[k * 12497 + 3].y != 0) { all0 = 0; break; }
    }
    g_e64 = all0;
}

__global__ void zero_indeg() {
    int i = blockIdx.x * blockDim.x + threadIdx.x;
    if (i < NN) g_indeg[i] = 0;
}

__global__ void csr_count(const void* edges) {
    int e = blockIdx.x * blockDim.x + threadIdx.x;
    if (e >= NE) return;
    int d;
    if (g_e64) d = (int)((const long long*)edges)[NE + e];
    else       d = ((const int*)edges)[NE + e];
    atomicAdd(&g_indeg[d], 1);
}

// ---------------- parallel exclusive scan over indeg ------------------------
__global__ void scan1() {
    int b = blockIdx.x, t = threadIdx.x;
    int i = b * 256 + t;
    int d = (i < NN) ? g_indeg[i] : 0;
    int lane = t & 31, w = t >> 5;
    int v = d;
#pragma unroll
    for (int off = 1; off < 32; off <<= 1) {
        int u = __shfl_up_sync(0xffffffffu, v, off);
        if (lane >= off) v += u;
    }
    __shared__ int ws[8];
    if (lane == 31) ws[w] = v;
    __syncthreads();
    if (t == 0) {
        int run = 0;
        for (int j = 0; j < 8; j++) { int x = ws[j]; ws[j] = run; run += x; }
    }
    __syncthreads();
    v += ws[w];
    if (i < NN) g_scanpart[i] = v;
    if (t == 255) g_blocksum[b] = v;
}

__global__ void scan2() {
    int t = threadIdx.x;
    int d = (t < NB196) ? g_blocksum[t] : 0;
    int lane = t & 31, w = t >> 5;
    int v = d;
#pragma unroll
    for (int off = 1; off < 32; off <<= 1) {
        int u = __shfl_up_sync(0xffffffffu, v, off);
        if (lane >= off) v += u;
    }
    __shared__ int ws[8];
    if (lane == 31) ws[w] = v;
    __syncthreads();
    if (t == 0) {
        int run = 0;
        for (int j = 0; j < 8; j++) { int x = ws[j]; ws[j] = run; run += x; }
    }
    __syncthreads();
    v += ws[w];
    if (t < NB196) g_blockoff[t] = v - d;
}

__global__ void scan3() {
    int i = blockIdx.x * blockDim.x + threadIdx.x;
    if (i < NN) {
        int deg = g_indeg[i];
        int excl = g_blockoff[blockIdx.x] + g_scanpart[i] - deg;
        g_rowstart[i] = excl;
        g_cursor[i] = excl;
        g_dinv[i] = rsqrtf((float)deg + 1.0f);
    }
    if (i == 0) g_rowstart[NN] = NE;
}

__global__ void csr_place(const void* edges) {
    int e = blockIdx.x * blockDim.x + threadIdx.x;
    if (e >= NE) return;
    int s, d;
    if (g_e64) {
        s = (int)((const long long*)edges)[e];
        d = (int)((const long long*)edges)[NE + e];
    } else {
        s = ((const int*)edges)[e];
        d = ((const int*)edges)[NE + e];
    }
    int pos = atomicAdd(&g_cursor[d], 1);
    g_epack[pos] = make_float2(__int_as_float(s), g_dinv[s] * g_dinv[d]);
}

// ---------------- operand pre-rounding (tf32 RN) ----------------------------
__global__ void round_x(const float4* __restrict__ x) {
    int i = blockIdx.x * 256 + threadIdx.x;
    if (i >= NN * 64) return;
    float4 v = x[i];
    v.x = f2tf32f(v.x); v.y = f2tf32f(v.y); v.z = f2tf32f(v.z); v.w = f2tf32f(v.w);
    ((float4*)g_xr)[i] = v;
}

__global__ void round_weights(const float4* W1, const float4* r1W, const float4* Wg,
                              const float4* r2W, const float4* W3, const float4* r3W,
                              const float4* pW) {
    int i = blockIdx.x * 256 + threadIdx.x;   // 54784 float4
    if (i >= 54784) return;
    const float4* s; int b;
    if      (i < 16384) { s = W1;  b = 0; }
    else if (i < 32768) { s = r1W; b = 16384; }
    else if (i < 49152) { s = Wg;  b = 32768; }
    else if (i < 53248) { s = r2W; b = 49152; }
    else if (i < 53504) { s = W3;  b = 53248; }
    else if (i < 53760) { s = r3W; b = 53504; }
    else                { s = pW;  b = 53760; }
    float4 v = s[i - b];
    v.x = f2tf32f(v.x); v.y = f2tf32f(v.y); v.z = f2tf32f(v.z); v.w = f2tf32f(v.w);
    ((float4*)g_wr)[i] = v;
}

// fold GAT attention vectors through Wg (exact): Ws[k][h]=sum_d Wg[k][h*64+d]*a_s[h][d]
__global__ void alpha_fold(const float* __restrict__ Wg, const float* __restrict__ a_s,
                           const float* __restrict__ a_d) {
    int k = threadIdx.x;  // 256
    const float* wrow = Wg + (size_t)k * 256;
#pragma unroll
    for (int hh = 0; hh < 4; hh++) {
        float s = 0.f, d = 0.f;
#pragma unroll 8
        for (int dd = 0; dd < 64; dd++) {
            float w = wrow[hh * 64 + dd];
            s = fmaf(w, a_s[hh * 64 + dd], s);
            d = fmaf(w, a_d[hh * 64 + dd], d);
        }
        g_ws[k * 4 + hh] = s;
        g_wd[k * 4 + hh] = d;
    }
}

// build combined stage-2 B: [Wg(256) | r2W(64) | Ws(4) | Wd(4) | 0-pad] width 384
__global__ void build_w2comb() {
    int idx = blockIdx.x * 256 + threadIdx.x;  // 98304
    if (idx >= 256 * 384) return;
    int r = idx / 384, c = idx % 384;
    float v;
    if      (c < 256) v = g_wr[131072 + r * 256 + c];           // rounded Wg
    else if (c < 320) v = g_wr[196608 + r * 64 + (c - 256)];    // rounded r2W
    else if (c < 324) v = f2tf32f(g_ws[r * 4 + (c - 320)]);
    else if (c < 328) v = f2tf32f(g_wd[r * 4 + (c - 324)]);
    else              v = 0.f;
    g_w2comb[idx] = v;
}

// build combined stage-3 B: [W3(16) | r3W(16)] width 32, K=64
__global__ void build_w3comb() {
    int idx = blockIdx.x * 256 + threadIdx.x;  // 2048
    if (idx >= 64 * 32) return;
    int r = idx / 32, c = idx % 32;
    g_w3comb[idx] = (c < 16) ? g_wr[212992 + r * 16 + c]
                             : g_wr[214016 + r * 16 + (c - 16)];
}

// ---------------- BN partial reduce ----------------------------------------
template <int C>
__global__ void bn_reduce(int nblocks, float invN) {
    int c = blockIdx.x, t = threadIdx.x;
    double s = 0.0, q = 0.0;
    for (int b = t; b < nblocks; b += 256) {
        s += (double)g_bnp1[(size_t)b * C + c];
        q += (double)g_bnp2[(size_t)b * C + c];
    }
    __shared__ double sh[256], sh2[256];
    sh[t] = s; sh2[t] = q;
    __syncthreads();
    for (int off = 128; off; off >>= 1) {
        if (t < off) { sh[t] += sh[t + off]; sh2[t] += sh2[t + off]; }
        __syncthreads();
    }
    if (t == 0) {
        double m = sh[0] * (double)invN;
        double v = sh2[0] * (double)invN - m * m;
        g_mu[c] = (float)m;
        g_rstd[c] = rsqrtf((float)v + 1e-5f);
    }
}

// ---------------- BN+leaky+residual fuse ------------------------------------
template <int C, bool RND>
__global__ void fuse_res(const float4* __restrict__ t, const float4* __restrict__ res,
                         const float* __restrict__ g, const float* __restrict__ be,
                         float4* __restrict__ out, int n4) {
    int i = blockIdx.x * 256 + threadIdx.x;
    if (i >= n4) return;
    int c0 = (i * 4) & (C - 1);
    float4 tv = t[i], rv = res[i];
    float4 o;
    float u;
    u = (tv.x - g_mu[c0    ]) * g_rstd[c0    ] * g[c0    ] + be[c0    ];
    o.x = (u > 0.f ? u : 0.01f * u) + rv.x;
    u = (tv.y - g_mu[c0 + 1]) * g_rstd[c0 + 1] * g[c0 + 1] + be[c0 + 1];
    o.y = (u > 0.f ? u : 0.01f * u) + rv.y;
    u = (tv.z - g_mu[c0 + 2]) * g_rstd[c0 + 2] * g[c0 + 2] + be[c0 + 2];
    o.z = (u > 0.f ? u : 0.01f * u) + rv.z;
    u = (tv.w - g_mu[c0 + 3]) * g_rstd[c0 + 3] * g[c0 + 3] + be[c0 + 3];
    o.w = (u > 0.f ? u : 0.01f * u) + rv.w;
    if (RND) {
        o.x = f2tf32f(o.x); o.y = f2tf32f(o.y);
        o.z = f2tf32f(o.z); o.w = f2tf32f(o.w);
    }
    out[i] = o;
}

// ---------------- tf32 tensor-core GEMM, 3-stage cp.async -------------------
// EPI=0: C[r*Nn+c] = acc + bias[c].
// EPI=2: stage-2 routing: c<256 -> C(h); c<320 -> D(res,+bias); c<324 -> als; c<328 -> ald.
// EPI=3: stage-3 routing: c<16 -> C(h16); c<32 -> D(res16,+bias).
#define ASTRIDE 36
#define BSTRIDE 136
#define ASZ (128 * ASTRIDE)
#define BSZ (32 * BSTRIDE)
#define STG (ASZ + BSZ)
#define SMEM_WORDS (3 * STG)     // 107520 B

template <int EPI>
__global__ __launch_bounds__(256, 2)
void tf32_gemm_ca(const float* __restrict__ A, const float* __restrict__ B,
                  const float* __restrict__ bias, float* __restrict__ C,
                  float* __restrict__ D, int M, int Nn, int K) {
    extern __shared__ uint32_t sm[];
    const int tid = threadIdx.x;
    const int warp = tid >> 5, lane = tid & 31;
    const int wm = warp >> 1, wn = warp & 1;
    const int g = lane >> 2, t4 = lane & 3;
    const int rowBase = blockIdx.y * 128;
    const int colBase = blockIdx.x * 128;
    const uint32_t sbase = (uint32_t)__cvta_generic_to_shared(sm);

    const int arow = tid >> 3, ac4 = (tid & 7) * 4;
    const int brow = tid >> 5, bc4 = (tid & 31) * 4;

    float acc[2][8][4];
#pragma unroll
    for (int mi = 0; mi < 2; mi++)
#pragma unroll
        for (int ni = 0; ni < 8; ni++)
#pragma unroll
            for (int j = 0; j < 4; j++) acc[mi][ni][j] = 0.0f;

    const int nk = K >> 5;

    auto loadTile = [&](int k0i) {
        int buf = k0i % 3;
        int k0 = k0i << 5;
        uint32_t bufb = sbase + (uint32_t)(buf * STG) * 4u;
#pragma unroll
        for (int q = 0; q < 4; q++) {
            int r = q * 32 + arow;
            const float* src = A + (size_t)(rowBase + r) * K + k0 + ac4;
            uint32_t dst = bufb + (uint32_t)(r * ASTRIDE + ac4) * 4u;
            int sz = (rowBase + r < M) ? 16 : 0;
            asm volatile("cp.async.cg.shared.global [%0], [%1], 16, %2;\n"
                         :: "r"(dst), "l"(src), "r"(sz));
        }
#pragma unroll
        for (int q = 0; q < 4; q++) {
            int r = q * 8 + brow;
            const float* src = B + (size_t)(k0 + r) * Nn + colBase + bc4;
            uint32_t dst = bufb + (uint32_t)(ASZ + r * BSTRIDE + bc4) * 4u;
            int sz = (colBase + bc4 + 4 <= Nn) ? 16 : 0;
            asm volatile("cp.async.cg.shared.global [%0], [%1], 16, %2;\n"
                         :: "r"(dst), "l"(src), "r"(sz));
        }
        asm volatile("cp.async.commit_group;\n");
    };

    loadTile(0);
    if (nk > 1) loadTile(1);

    for (int k0i = 0; k0i < nk; k0i++) {
        if (k0i + 1 < nk) asm volatile("cp.async.wait_group 1;\n");
        else              asm volatile("cp.async.wait_group 0;\n");
        __syncthreads();
        if (k0i + 2 < nk) loadTile(k0i + 2);

        const uint32_t* As = sm + (k0i % 3) * STG;
        const uint32_t* Bs = As + ASZ;

#pragma unroll
        for (int kk = 0; kk < 32; kk += 8) {
            uint32_t af[2][4];
#pragma unroll
            for (int mi = 0; mi < 2; mi++) {
                int r = wm * 32 + mi * 16;
                af[mi][0] = As[(r + g) * ASTRIDE + kk + t4];
                af[mi][1] = As[(r + g + 8) * ASTRIDE + kk + t4];
                af[mi][2] = As[(r + g) * ASTRIDE + kk + t4 + 4];
                af[mi][3] = As[(r + g + 8) * ASTRIDE + kk + t4 + 4];
            }
            uint32_t bf[8][2];
#pragma unroll
            for (int ni = 0; ni < 8; ni++) {
                int c = wn * 64 + ni * 8 + g;
                bf[ni][0] = Bs[(kk + t4) * BSTRIDE + c];
                bf[ni][1] = Bs[(kk + t4 + 4) * BSTRIDE + c];
            }
#pragma unroll
            for (int mi = 0; mi < 2; mi++)
#pragma unroll
                for (int ni = 0; ni < 8; ni++) {
                    asm volatile(
                        "mma.sync.aligned.m16n8k8.row.col.f32.tf32.tf32.f32 "
                        "{%0,%1,%2,%3}, {%4,%5,%6,%7}, {%8,%9}, {%0,%1,%2,%3};"
                        : "+f"(acc[mi][ni][0]), "+f"(acc[mi][ni][1]),
                          "+f"(acc[mi][ni][2]), "+f"(acc[mi][ni][3])
                        : "r"(af[mi][0]), "r"(af[mi][1]), "r"(af[mi][2]), "r"(af[mi][3]),
                          "r"(bf[ni][0]), "r"(bf[ni][1]));
                }
        }
    }

#pragma unroll
    for (int mi = 0; mi < 2; mi++) {
#pragma unroll
        for (int ni = 0; ni < 8; ni++) {
            int r0 = rowBase + wm * 32 + mi * 16 + g;
            int c0 = colBase + wn * 64 + ni * 8 + t4 * 2;
#pragma unroll
            for (int half = 0; half < 2; half++) {
                int r = r0 + half * 8;
                if (r >= M) continue;
                float vx = acc[mi][ni][half * 2];
                float vy = acc[mi][ni][half * 2 + 1];
                if (EPI == 0) {
                    if (c0 >= Nn) continue;
                    if (bias) { vx += bias[c0]; vy += bias[c0 + 1]; }
                    *(float2*)(C + (size_t)r * Nn + c0) = make_float2(vx, vy);
                } else if (EPI == 2) {
                    if (c0 >= 328) continue;
                    if (c0 < 256) {
                        *(float2*)(C + (size_t)r * 256 + c0) = make_float2(vx, vy);
                    } else if (c0 < 320) {
                        int cc = c0 - 256;
                        *(float2*)(D + (size_t)r * 64 + cc) =
                            make_float2(vx + bias[cc], vy + bias[cc + 1]);
                    } else if (c0 < 324) {
                        *(float2*)(g_als + (size_t)r * 4 + (c0 - 320)) = make_float2(vx, vy);
                    } else {
                        *(float2*)(g_ald + (size_t)r * 4 + (c0 - 324)) = make_float2(vx, vy);
                    }
                } else {  // EPI == 3
                    if (c0 >= 32) continue;
                    if (c0 < 16) {
                        *(float2*)(C + (size_t)r * 16 + c0) = make_float2(vx, vy);
                    } else {
                        int cc = c0 - 16;
                        *(float2*)(D + (size_t)r * 16 + cc) =
                            make_float2(vx + bias[cc], vy + bias[cc + 1]);
                    }
                }
            }
        }
    }
}

// ---------------- narrow FFMA GEMM: M x 64, K=16 (stage-4 W4) ---------------
__global__ void gemm_k16(const float* __restrict__ A, const float* __restrict__ B,
                         float* __restrict__ C) {
    __shared__ float Bs[16 * 64];
    int tid = threadIdx.x;
    ((float4*)Bs)[tid] = ((const float4*)B)[tid];
    __syncthreads();
    int row = blockIdx.x * 256 + tid;
    if (row >= NN) return;
    float a[16];
#pragma unroll
    for (int q = 0; q < 4; q++) {
        float4 v = *(const float4*)(A + (size_t)row * 16 + q * 4);
        a[q * 4] = v.x; a[q * 4 + 1] = v.y; a[q * 4 + 2] = v.z; a[q * 4 + 3] = v.w;
    }
    float acc[64];
#pragma unroll
    for (int c = 0; c < 64; c++) acc[c] = 0.0f;
#pragma unroll
    for (int k = 0; k < 16; k++) {
        float av = a[k];
#pragma unroll
        for (int c = 0; c < 64; c++) acc[c] = fmaf(av, Bs[k * 64 + c], acc[c]);
    }
#pragma unroll
    for (int q = 0; q < 16; q++) {
        *(float4*)(C + (size_t)row * 64 + q * 4) =
            make_float4(acc[q * 4], acc[q * 4 + 1], acc[q * 4 + 2], acc[q * 4 + 3]);
    }
}

// ---------------- GCN gather + fused BN partials ----------------------------
__global__ void gcn_gather_bn256(const float* __restrict__ h, const float* __restrict__ bias,
                                 float* __restrict__ out) {
    __shared__ float ss[2048], sq[2048];
    int tid = threadIdx.x, w = tid >> 5, lane = tid & 31;
    int node = blockIdx.x * 8 + w;
    float acc[8];
#pragma unroll
    for (int j = 0; j < 8; j++) acc[j] = 0.0f;
    float dv = g_dinv[node];
    int s0 = g_rowstart[node], s1 = g_rowstart[node + 1];
    for (int p = s0; p < s1; p++) {
        float2 ep = g_epack[p];
        int s = __float_as_int(ep.x);
        float norm = ep.y;
        const float* hp = h + (size_t)s * 256;
#pragma unroll
        for (int j = 0; j < 8; j++) acc[j] = fmaf(norm, hp[j * 32 + lane], acc[j]);
    }
    const float* hd = h + (size_t)node * 256;
    float self = dv * dv;
#pragma unroll
    for (int j = 0; j < 8; j++) {
        int c = j * 32 + lane;
        float v = acc[j] + self * hd[c] + bias[c];
        out[(size_t)node * 256 + c] = v;
        ss[w * 256 + c] = v;
        sq[w * 256 + c] = v * v;
    }
    __syncthreads();
    float s = 0.f, q = 0.f;
#pragma unroll
    for (int w2 = 0; w2 < 8; w2++) { s += ss[w2 * 256 + tid]; q += sq[w2 * 256 + tid]; }
    g_bnp1[(size_t)blockIdx.x * 256 + tid] = s;
    g_bnp2[(size_t)blockIdx.x * 256 + tid] = q;
}

// stage-4 gather, C=64; output rounded to tf32 (feeds pW tf32 GEMM)
__global__ void gcn_gather64(const float* __restrict__ h, const float* __restrict__ bias,
                             float* __restrict__ out) {
    int warp = (blockIdx.x * blockDim.x + threadIdx.x) >> 5;
    int lane = threadIdx.x & 31;
    if (warp >= NN) return;
    float a0 = 0.f, a1 = 0.f;
    float dv = g_dinv[warp];
    int s0 = g_rowstart[warp], s1 = g_rowstart[warp + 1];
    for (int p = s0; p < s1; p++) {
        float2 ep = g_epack[p];
        int s = __float_as_int(ep.x);
        float norm = ep.y;
        const float* hp = h + (size_t)s * 64;
        a0 = fmaf(norm, hp[lane], a0);
        a1 = fmaf(norm, hp[32 + lane], a1);
    }
    const float* hd = h + (size_t)warp * 64;
    float self = dv * dv;
    out[(size_t)warp * 64 + lane]      = f2tf32f(a0 + self * hd[lane] + bias[lane]);
    out[(size_t)warp * 64 + 32 + lane] = f2tf32f(a1 + self * hd[32 + lane] + bias[32 + lane]);
}

// C=16 gather + BN partials: 256 threads = 64 nodes (4 threads/node)
__global__ void gcn_gather16_bn(const float* __restrict__ h, const float* __restrict__ bias,
                                float* __restrict__ out) {
    __shared__ float ss[1024], sq[1024];
    int tid = threadIdx.x;
    int idx = blockIdx.x * 256 + tid;
    int node = idx >> 2, q4 = idx & 3;
    float ox = 0.f, oy = 0.f, oz = 0.f, ow = 0.f;
    if (node < NN) {
        float ax = 0.f, ay = 0.f, az = 0.f, aw = 0.f;
        float dv = g_dinv[node];
        int s0 = g_rowstart[node], s1 = g_rowstart[node + 1];
        for (int p = s0; p < s1; p++) {
            float2 ep = g_epack[p];
            int s = __float_as_int(ep.x);
            float norm = ep.y;
            float4 v = *(const float4*)(h + (size_t)s * 16 + q4 * 4);
            ax = fmaf(norm, v.x, ax); ay = fmaf(norm, v.y, ay);
            az = fmaf(norm, v.z, az); aw = fmaf(norm, v.w, aw);
        }
        float4 hv = *(const float4*)(h + (size_t)node * 16 + q4 * 4);
        float4 bv = *(const float4*)(bias + q4 * 4);
        float self = dv * dv;
        ox = ax + self * hv.x + bv.x;
        oy = ay + self * hv.y + bv.y;
        oz = az + self * hv.z + bv.z;
        ow = aw + self * hv.w + bv.w;
        *(float4*)(out + (size_t)node * 16 + q4 * 4) = make_float4(ox, oy, oz, ow);
    }
    ss[tid * 4 + 0] = ox; sq[tid * 4 + 0] = ox * ox;
    ss[tid * 4 + 1] = oy; sq[tid * 4 + 1] = oy * oy;
    ss[tid * 4 + 2] = oz; sq[tid * 4 + 2] = oz * oz;
    ss[tid * 4 + 3] = ow; sq[tid * 4 + 3] = ow * ow;
    __syncthreads();
    if (tid < 16) {
        int qq = tid >> 2, ii = tid & 3;
        float s = 0.f, q = 0.f;
        for (int nl = 0; nl < 64; nl++) {
            s += ss[(nl * 4 + qq) * 4 + ii];
            q += sq[(nl * 4 + qq) * 4 + ii];
        }
        g_bnp1[(size_t)blockIdx.x * 16 + tid] = s;
        g_bnp2[(size_t)blockIdx.x * 16 + tid] = q;
    }
}

// ---------------- GAT gather + fused BN partials ----------------------------
__global__ void gat_gather_bn(const float* __restrict__ h2, const float* __restrict__ bg,
                              float* __restrict__ out) {
    __shared__ float ss[512], sq[512];
    int tid = threadIdx.x, w = tid >> 5, lane = tid & 31;
    int node = blockIdx.x * 8 + w;
    float4 adv = *(const float4*)(g_ald + (size_t)node * 4);
    float4 asv = *(const float4*)(g_als + (size_t)node * 4);
    float ad[4] = {adv.x, adv.y, adv.z, adv.w};
    float eself[4];
    {
        float as_[4] = {asv.x, asv.y, asv.z, asv.w};
#pragma unroll
        for (int hh = 0; hh < 4; hh++) {
            float lg = as_[hh] + ad[hh];
            eself[hh] = lg > 0.f ? lg : 0.2f * lg;
        }
    }
    int s0 = g_rowstart[node], s1 = g_rowstart[node + 1];
    float m[4] = {eself[0], eself[1], eself[2], eself[3]};
    for (int p = s0 + lane; p < s1; p += 32) {
        int s = __float_as_int(g_epack[p].x);
        float4 a = *(const float4*)(g_als + (size_t)s * 4);
        float lg;
        lg = a.x + ad[0]; m[0] = fmaxf(m[0], lg > 0.f ? lg : 0.2f * lg);
        lg = a.y + ad[1]; m[1] = fmaxf(m[1], lg > 0.f ? lg : 0.2f * lg);
        lg = a.z + ad[2]; m[2] = fmaxf(m[2], lg > 0.f ? lg : 0.2f * lg);
        lg = a.w + ad[3]; m[3] = fmaxf(m[3], lg > 0.f ? lg : 0.2f * lg);
    }
#pragma unroll
    for (int hh = 0; hh < 4; hh++)
#pragma unroll
        for (int off = 16; off > 0; off >>= 1)
            m[hh] = fmaxf(m[hh], __shfl_xor_sync(0xffffffffu, m[hh], off));

    float adL = ad[0], mL = m[0];
    if (lane == 1) { adL = ad[1]; mL = m[1]; }
    else if (lane == 2) { adL = ad[2]; mL = m[2]; }
    else if (lane == 3) { adL = ad[3]; mL = m[3]; }
    float acc[8] = {0.f, 0.f, 0.f, 0.f, 0.f, 0.f, 0.f, 0.f};
    float denL = 0.f;
    for (int p = s0; p < s1; p++) {
        int s = __float_as_int(g_epack[p].x);
        float ee = 0.f;
        if (lane < 4) {
            float a = g_als[(size_t)s * 4 + lane];
            float lg = a + adL;
            lg = lg > 0.f ? lg : 0.2f * lg;
            ee = __expf(lg - mL);
            denL += ee;
        }
        float ee0 = __shfl_sync(0xffffffffu, ee, 0);
        float ee1 = __shfl_sync(0xffffffffu, ee, 1);
        float ee2 = __shfl_sync(0xffffffffu, ee, 2);
        float ee3 = __shfl_sync(0xffffffffu, ee, 3);
        const float* hp = h2 + (size_t)s * 256;
        acc[0] = fmaf(ee0, hp[lane], acc[0]);
        acc[1] = fmaf(ee0, hp[32 + lane], acc[1]);
        acc[2] = fmaf(ee1, hp[64 + lane], acc[2]);
        acc[3] = fmaf(ee1, hp[96 + lane], acc[3]);
        acc[4] = fmaf(ee2, hp[128 + lane], acc[4]);
        acc[5] = fmaf(ee2, hp[160 + lane], acc[5]);
        acc[6] = fmaf(ee3, hp[192 + lane], acc[6]);
        acc[7] = fmaf(ee3, hp[224 + lane], acc[7]);
    }
    float es[4], den[4];
#pragma unroll
    for (int hh = 0; hh < 4; hh++) {
        es[hh] = __expf(eself[hh] - m[hh]);
        den[hh] = __shfl_sync(0xffffffffu, denL, hh) + es[hh];
    }
    const float* hd = h2 + (size_t)node * 256;
    float o0 = 0.f, o1 = 0.f;
#pragma unroll
    for (int hh = 0; hh < 4; hh++) {
        o0 += (acc[2 * hh]     + es[hh] * hd[hh * 64 + lane])      / den[hh];
        o1 += (acc[2 * hh + 1] + es[hh] * hd[hh * 64 + 32 + lane]) / den[hh];
    }
    float t0 = 0.25f * o0 + bg[lane];
    float t1 = 0.25f * o1 + bg[32 + lane];
    out[(size_t)node * 64 + lane]      = t0;
    out[(size_t)node * 64 + 32 + lane] = t1;
    ss[w * 64 + lane] = t0;        sq[w * 64 + lane] = t0 * t0;
    ss[w * 64 + 32 + lane] = t1;   sq[w * 64 + 32 + lane] = t1 * t1;
    __syncthreads();
    if (tid < 64) {
        float s = 0.f, q = 0.f;
#pragma unroll
        for (int w2 = 0; w2 < 8; w2++) { s += ss[w2 * 64 + tid]; q += sq[w2 * 64 + tid]; }
        g_bnp1[(size_t)blockIdx.x * 64 + tid] = s;
        g_bnp2[(size_t)blockIdx.x * 64 + tid] = q;
    }
}

// ---------------- host ----------------
static inline int cdiv(int a, int b) { return (a + b - 1) / b; }

extern "C" void kernel_launch(void* const* d_in, const int* in_sizes, int n_in,
                              void* d_out, int out_size) {
    const float* x    = (const float*)d_in[0];
    const void*  edges = d_in[1];
    const float* b1   = (const float*)d_in[3];
    const float* g1   = (const float*)d_in[4];
    const float* be1  = (const float*)d_in[5];
    const float* Wg   = (const float*)d_in[6];
    const float* a_src = (const float*)d_in[7];
    const float* a_dst = (const float*)d_in[8];
    const float* bg   = (const float*)d_in[9];
    const float* g2   = (const float*)d_in[10];
    const float* be2  = (const float*)d_in[11];
    const float* b3   = (const float*)d_in[13];
    const float* g3   = (const float*)d_in[14];
    const float* be3  = (const float*)d_in[15];
    const float* W4   = (const float*)d_in[16];
    const float* b4   = (const float*)d_in[17];
    const float* r1b  = (const float*)d_in[19];
    const float* r2b  = (const float*)d_in[21];
    const float* r3b  = (const float*)d_in[23];
    const float* pb   = (const float*)d_in[25];
    float* out = (float*)d_out;

    float *h, *t, *x2, *xr, *res, *x3, *x4, *wr, *w2c, *w3c;
    cudaGetSymbolAddress((void**)&h,   g_h);
    cudaGetSymbolAddress((void**)&t,   g_t);
    cudaGetSymbolAddress((void**)&x2,  g_x2);
    cudaGetSymbolAddress((void**)&xr,  g_xr);
    cudaGetSymbolAddress((void**)&res, g_res);
    cudaGetSymbolAddress((void**)&x3,  g_x3);
    cudaGetSymbolAddress((void**)&x4,  g_x4);
    cudaGetSymbolAddress((void**)&wr,  g_wr);
    cudaGetSymbolAddress((void**)&w2c, g_w2comb);
    cudaGetSymbolAddress((void**)&w3c, g_w3comb);

    static cudaStream_t s1 = nullptr;
    static cudaEvent_t evFork = nullptr, evCSR = nullptr, evXR = nullptr, evG1 = nullptr;
    if (s1 == nullptr) {
        cudaStreamCreateWithFlags(&s1, cudaStreamNonBlocking);
        cudaEventCreateWithFlags(&evFork, cudaEventDisableTiming);
        cudaEventCreateWithFlags(&evCSR,  cudaEventDisableTiming);
        cudaEventCreateWithFlags(&evXR,   cudaEventDisableTiming);
        cudaEventCreateWithFlags(&evG1,   cudaEventDisableTiming);
        const int SMEMB_ = SMEM_WORDS * 4;
        cudaFuncSetAttribute(tf32_gemm_ca<0>,
                             cudaFuncAttributeMaxDynamicSharedMemorySize, SMEMB_);
        cudaFuncSetAttribute(tf32_gemm_ca<2>,
                             cudaFuncAttributeMaxDynamicSharedMemorySize, SMEMB_);
        cudaFuncSetAttribute(tf32_gemm_ca<3>,
                             cudaFuncAttributeMaxDynamicSharedMemorySize, SMEMB_);
    }
    const int SMEMB = SMEM_WORDS * 4;  // 107520

    const float invN = 1.0f / (float)NN;
    const int MB = cdiv(NN, 128);  // 391

    float* wW1  = wr + 0;
    float* wr1W = wr + 65536;
    float* wpW  = wr + 215040;

    // ---- fork: CSR chain on s1; rounding + weight prep + GEMM1 on main ----
    cudaEventRecord(evFork, 0);
    cudaStreamWaitEvent(s1, evFork, 0);
    detect_kernel<<<1, 1, 0, s1>>>(edges);
    zero_indeg<<<cdiv(NN, 256), 256, 0, s1>>>();
    csr_count<<<cdiv(NE, 256), 256, 0, s1>>>(edges);
    scan1<<<NB196, 256, 0, s1>>>();
    scan2<<<1, 256, 0, s1>>>();
    scan3<<<NB196, 256, 0, s1>>>();
    csr_place<<<cdiv(NE, 256), 256, 0, s1>>>(edges);
    cudaEventRecord(evCSR, s1);

    round_weights<<<214, 256>>>((const float4*)d_in[2], (const float4*)d_in[18],
                                (const float4*)d_in[6], (const float4*)d_in[20],
                                (const float4*)d_in[12], (const float4*)d_in[22],
                                (const float4*)d_in[24]);
    alpha_fold<<<1, 256>>>(Wg, a_src, a_dst);
    build_w2comb<<<384, 256>>>();
    build_w3comb<<<8, 256>>>();
    round_x<<<12500, 256>>>((const float4*)x);
    cudaEventRecord(evXR, 0);
    tf32_gemm_ca<0><<<dim3(2, MB), 256, SMEMB>>>(
        xr, wW1, nullptr, h, nullptr, NN, 256, 256);

    // ---- Stage 1: gather+BN on main; r1W GEMM concurrently on s1 ----
    cudaStreamWaitEvent(0, evCSR, 0);
    gcn_gather_bn256<<<GB1, 256>>>(h, b1, t);
    cudaStreamWaitEvent(s1, evXR, 0);
    tf32_gemm_ca<0><<<dim3(2, MB), 256, SMEMB, s1>>>(
        xr, wr1W, r1b, res, nullptr, NN, 256, 256);
    cudaEventRecord(evG1, s1);
    bn_reduce<256><<<256, 256>>>(GB1, invN);
    cudaStreamWaitEvent(0, evG1, 0);
    fuse_res<256, true><<<12500, 256>>>((const float4*)t, (const float4*)res, g1, be1,
                                        (float4*)x2, NN * 64);

    // ---- Stage 2: mega-GEMM [Wg|r2W|Ws|Wd] -> h, res, als, ald ----
    tf32_gemm_ca<2><<<dim3(3, MB), 256, SMEMB>>>(
        x2, w2c, r2b, h, res, NN, 384, 256);
    gat_gather_bn<<<GB1, 256>>>(h, bg, t);
    bn_reduce<64><<<64, 256>>>(GB1, invN);
    fuse_res<64, true><<<3125, 256>>>((const float4*)t, (const float4*)res, g2, be2,
                                      (float4*)x3, NN * 16);

    // ---- Stage 3: merged [W3|r3W] GEMM -> h16, res16 ----
    tf32_gemm_ca<3><<<dim3(1, MB), 256, SMEMB>>>(
        x3, w3c, r3b, h, res, NN, 32, 64);
    gcn_gather16_bn<<<GB3, 256>>>(h, b3, t);
    bn_reduce<16><<<16, 256>>>(GB3, invN);
    fuse_res<16, false><<<782, 256>>>((const float4*)t, (const float4*)res, g3, be3,
                                      (float4*)x4, NN * 4);

    // ---- Stage 4: GCN(16->64), then final linear ----
    gemm_k16<<<NB196, 256>>>(x4, W4, h);
    gcn_gather64<<<cdiv(NN * 32, 256), 256>>>(h, b4, t);
    tf32_gemm_ca<0><<<dim3(1, MB), 256, SMEMB>>>(
        t, wpW, pb, out, nullptr, NN, 64, 64);
}

// round 12
// speedup vs baseline: 2.5016x; 1.0257x over previous
#include <cuda_runtime.h>
#include <cuda_fp16.h>
#include <cstdint>

#define NN 50000
#define NE 800000
#define NB196 196   // ceil(NN/256)
#define GB1 6250    // gather blocks, stages 1/2 (NN*32/256)
#define GB3 782     // ceil(NN*4/256)
#define WRTOT 219136

// ---------------- device scratch (static, no runtime alloc) ----------------
__device__ float g_h  [NN * 256];   // stages 1-2: reinterpreted as __half[NN*256]
__device__ float g_t  [NN * 256];
__device__ float g_x2 [NN * 256];
__device__ float g_xr [NN * 256];
__device__ float g_res[NN * 256];
__device__ float g_x3 [NN * 64];
__device__ float g_x4 [NN * 16];
__device__ float g_wr [WRTOT];
__device__ float g_ws [256 * 4];
__device__ float g_wd [256 * 4];
__device__ float g_w2comb[256 * 384];
__device__ float g_w3comb[64 * 32];
__device__ float g_dinv[NN];
__device__ int   g_indeg[NN];
__device__ int   g_rowstart[NN + 1];
__device__ int   g_cursor[NN];
__device__ float2 g_epack[NE];
__device__ int   g_scanpart[NN];
__device__ int   g_blocksum[NB196];
__device__ int   g_blockoff[NB196];
__device__ float g_als[NN * 4];
__device__ float g_ald[NN * 4];
__device__ float g_bnp1[GB1 * 256];
__device__ float g_bnp2[GB1 * 256];
__device__ float g_mu  [256];
__device__ float g_rstd[256];
__device__ int   g_e64;

__device__ __forceinline__ uint32_t f2tf32(float x) {
    uint32_t r;
    asm("cvt.rna.tf32.f32 %0, %1;" : "=r"(r) : "f"(x));
    return r;
}
__device__ __forceinline__ float f2tf32f(float x) { return __uint_as_float(f2tf32(x)); }

// ---------------- edge dtype detect ----------------
__global__ void detect_kernel(const void* edges) {
    const int2* q = (const int2*)edges;
    int all0 = 1;
    for (int k = 0; k < 64; k++) {
        if (q[k * 12497 + 3].y != 0) { all0 = 0; break; }
    }
    g_e64 = all0;
}

__global__ void zero_indeg() {
    int i = blockIdx.x * blockDim.x + threadIdx.x;
    if (i < NN) g_indeg[i] = 0;
}

__global__ void csr_count(const void* edges) {
    int e = blockIdx.x * blockDim.x + threadIdx.x;
    if (e >= NE) return;
    int d;
    if (g_e64) d = (int)((const long long*)edges)[NE + e];
    else       d = ((const int*)edges)[NE + e];
    atomicAdd(&g_indeg[d], 1);
}

// ---------------- parallel exclusive scan over indeg ------------------------
__global__ void scan1() {
    int b = blockIdx.x, t = threadIdx.x;
    int i = b * 256 + t;
    int d = (i < NN) ? g_indeg[i] : 0;
    int lane = t & 31, w = t >> 5;
    int v = d;
#pragma unroll
    for (int off = 1; off < 32; off <<= 1) {
        int u = __shfl_up_sync(0xffffffffu, v, off);
        if (lane >= off) v += u;
    }
    __shared__ int ws[8];
    if (lane == 31) ws[w] = v;
    __syncthreads();
    if (t == 0) {
        int run = 0;
        for (int j = 0; j < 8; j++) { int x = ws[j]; ws[j] = run; run += x; }
    }
    __syncthreads();
    v += ws[w];
    if (i < NN) g_scanpart[i] = v;
    if (t == 255) g_blocksum[b] = v;
}

__global__ void scan2() {
    int t = threadIdx.x;
    int d = (t < NB196) ? g_blocksum[t] : 0;
    int lane = t & 31, w = t >> 5;
    int v = d;
#pragma unroll
    for (int off = 1; off < 32; off <<= 1) {
        int u = __shfl_up_sync(0xffffffffu, v, off);
        if (lane >= off) v += u;
    }
    __shared__ int ws[8];
    if (lane == 31) ws[w] = v;
    __syncthreads();
    if (t == 0) {
        int run = 0;
        for (int j = 0; j < 8; j++) { int x = ws[j]; ws[j] = run; run += x; }
    }
    __syncthreads();
    v += ws[w];
    if (t < NB196) g_blockoff[t] = v - d;
}

__global__ void scan3() {
    int i = blockIdx.x * blockDim.x + threadIdx.x;
    if (i < NN) {
        int deg = g_indeg[i];
        int excl = g_blockoff[blockIdx.x] + g_scanpart[i] - deg;
        g_rowstart[i] = excl;
        g_cursor[i] = excl;
        g_dinv[i] = rsqrtf((float)deg + 1.0f);
    }
    if (i == 0) g_rowstart[NN] = NE;
}

__global__ void csr_place(const void* edges) {
    int e = blockIdx.x * blockDim.x + threadIdx.x;
    if (e >= NE) return;
    int s, d;
    if (g_e64) {
        s = (int)((const long long*)edges)[e];
        d = (int)((const long long*)edges)[NE + e];
    } else {
        s = ((const int*)edges)[e];
        d = ((const int*)edges)[NE + e];
    }
    int pos = atomicAdd(&g_cursor[d], 1);
    g_epack[pos] = make_float2(__int_as_float(s), g_dinv[s] * g_dinv[d]);
}

// ---------------- operand pre-rounding (tf32 RN) ----------------------------
__global__ void round_x(const float4* __restrict__ x) {
    int i = blockIdx.x * 256 + threadIdx.x;
    if (i >= NN * 64) return;
    float4 v = x[i];
    v.x = f2tf32f(v.x); v.y = f2tf32f(v.y); v.z = f2tf32f(v.z); v.w = f2tf32f(v.w);
    ((float4*)g_xr)[i] = v;
}

__global__ void round_weights(const float4* W1, const float4* r1W, const float4* Wg,
                              const float4* r2W, const float4* W3, const float4* r3W,
                              const float4* pW) {
    int i = blockIdx.x * 256 + threadIdx.x;   // 54784 float4
    if (i >= 54784) return;
    const float4* s; int b;
    if      (i < 16384) { s = W1;  b = 0; }
    else if (i < 32768) { s = r1W; b = 16384; }
    else if (i < 49152) { s = Wg;  b = 32768; }
    else if (i < 53248) { s = r2W; b = 49152; }
    else if (i < 53504) { s = W3;  b = 53248; }
    else if (i < 53760) { s = r3W; b = 53504; }
    else                { s = pW;  b = 53760; }
    float4 v = s[i - b];
    v.x = f2tf32f(v.x); v.y = f2tf32f(v.y); v.z = f2tf32f(v.z); v.w = f2tf32f(v.w);
    ((float4*)g_wr)[i] = v;
}

// fold GAT attention vectors through Wg (exact)
__global__ void alpha_fold(const float* __restrict__ Wg, const float* __restrict__ a_s,
                           const float* __restrict__ a_d) {
    int k = threadIdx.x;  // 256
    const float* wrow = Wg + (size_t)k * 256;
#pragma unroll
    for (int hh = 0; hh < 4; hh++) {
        float s = 0.f, d = 0.f;
#pragma unroll 8
        for (int dd = 0; dd < 64; dd++) {
            float w = wrow[hh * 64 + dd];
            s = fmaf(w, a_s[hh * 64 + dd], s);
            d = fmaf(w, a_d[hh * 64 + dd], d);
        }
        g_ws[k * 4 + hh] = s;
        g_wd[k * 4 + hh] = d;
    }
}

__global__ void build_w2comb() {
    int idx = blockIdx.x * 256 + threadIdx.x;  // 98304
    if (idx >= 256 * 384) return;
    int r = idx / 384, c = idx % 384;
    float v;
    if      (c < 256) v = g_wr[131072 + r * 256 + c];
    else if (c < 320) v = g_wr[196608 + r * 64 + (c - 256)];
    else if (c < 324) v = f2tf32f(g_ws[r * 4 + (c - 320)]);
    else if (c < 328) v = f2tf32f(g_wd[r * 4 + (c - 324)]);
    else              v = 0.f;
    g_w2comb[idx] = v;
}

__global__ void build_w3comb() {
    int idx = blockIdx.x * 256 + threadIdx.x;  // 2048
    if (idx >= 64 * 32) return;
    int r = idx / 32, c = idx % 32;
    g_w3comb[idx] = (c < 16) ? g_wr[212992 + r * 16 + c]
                             : g_wr[214016 + r * 16 + (c - 16)];
}

// ---------------- BN partial reduce ----------------------------------------
template <int C>
__global__ void bn_reduce(int nblocks, float invN) {
    int c = blockIdx.x, t = threadIdx.x;
    double s = 0.0, q = 0.0;
    for (int b = t; b < nblocks; b += 256) {
        s += (double)g_bnp1[(size_t)b * C + c];
        q += (double)g_bnp2[(size_t)b * C + c];
    }
    __shared__ double sh[256], sh2[256];
    sh[t] = s; sh2[t] = q;
    __syncthreads();
    for (int off = 128; off; off >>= 1) {
        if (t < off) { sh[t] += sh[t + off]; sh2[t] += sh2[t + off]; }
        __syncthreads();
    }
    if (t == 0) {
        double m = sh[0] * (double)invN;
        double v = sh2[0] * (double)invN - m * m;
        g_mu[c] = (float)m;
        g_rstd[c] = rsqrtf((float)v + 1e-5f);
    }
}

// ---------------- BN+leaky+residual fuse ------------------------------------
template <int C, bool RND>
__global__ void fuse_res(const float4* __restrict__ t, const float4* __restrict__ res,
                         const float* __restrict__ g, const float* __restrict__ be,
                         float4* __restrict__ out, int n4) {
    int i = blockIdx.x * 256 + threadIdx.x;
    if (i >= n4) return;
    int c0 = (i * 4) & (C - 1);
    float4 tv = t[i], rv = res[i];
    float4 o;
    float u;
    u = (tv.x - g_mu[c0    ]) * g_rstd[c0    ] * g[c0    ] + be[c0    ];
    o.x = (u > 0.f ? u : 0.01f * u) + rv.x;
    u = (tv.y - g_mu[c0 + 1]) * g_rstd[c0 + 1] * g[c0 + 1] + be[c0 + 1];
    o.y = (u > 0.f ? u : 0.01f * u) + rv.y;
    u = (tv.z - g_mu[c0 + 2]) * g_rstd[c0 + 2] * g[c0 + 2] + be[c0 + 2];
    o.z = (u > 0.f ? u : 0.01f * u) + rv.z;
    u = (tv.w - g_mu[c0 + 3]) * g_rstd[c0 + 3] * g[c0 + 3] + be[c0 + 3];
    o.w = (u > 0.f ? u : 0.01f * u) + rv.w;
    if (RND) {
        o.x = f2tf32f(o.x); o.y = f2tf32f(o.y);
        o.z = f2tf32f(o.z); o.w = f2tf32f(o.w);
    }
    out[i] = o;
}

// ---------------- tf32 tensor-core GEMM, 3-stage cp.async -------------------
// EPI=0: float C + bias.
// EPI=1: fp16 C (no bias) — stage-1 h.
// EPI=2: stage-2 routing: c<256 -> fp16 h; c<320 -> res(+bias); c<324 -> als; c<328 -> ald.
// EPI=3: stage-3 routing: c<16 -> h16(float); c<32 -> res16(+bias).
#define ASTRIDE 36
#define BSTRIDE 136
#define ASZ (128 * ASTRIDE)
#define BSZ (32 * BSTRIDE)
#define STG (ASZ + BSZ)
#define SMEM_WORDS (3 * STG)     // 107520 B

template <int EPI>
__global__ __launch_bounds__(256, 2)
void tf32_gemm_ca(const float* __restrict__ A, const float* __restrict__ B,
                  const float* __restrict__ bias, float* __restrict__ C,
                  float* __restrict__ D, int M, int Nn, int K) {
    extern __shared__ uint32_t sm[];
    const int tid = threadIdx.x;
    const int warp = tid >> 5, lane = tid & 31;
    const int wm = warp >> 1, wn = warp & 1;
    const int g = lane >> 2, t4 = lane & 3;
    const int rowBase = blockIdx.y * 128;
    const int colBase = blockIdx.x * 128;
    const uint32_t sbase = (uint32_t)__cvta_generic_to_shared(sm);

    const int arow = tid >> 3, ac4 = (tid & 7) * 4;
    const int brow = tid >> 5, bc4 = (tid & 31) * 4;

    float acc[2][8][4];
#pragma unroll
    for (int mi = 0; mi < 2; mi++)
#pragma unroll
        for (int ni = 0; ni < 8; ni++)
#pragma unroll
            for (int j = 0; j < 4; j++) acc[mi][ni][j] = 0.0f;

    const int nk = K >> 5;

    auto loadTile = [&](int k0i) {
        int buf = k0i % 3;
        int k0 = k0i << 5;
        uint32_t bufb = sbase + (uint32_t)(buf * STG) * 4u;
#pragma unroll
        for (int q = 0; q < 4; q++) {
            int r = q * 32 + arow;
            const float* src = A + (size_t)(rowBase + r) * K + k0 + ac4;
            uint32_t dst = bufb + (uint32_t)(r * ASTRIDE + ac4) * 4u;
            int sz = (rowBase + r < M) ? 16 : 0;
            asm volatile("cp.async.cg.shared.global [%0], [%1], 16, %2;\n"
                         :: "r"(dst), "l"(src), "r"(sz));
        }
#pragma unroll
        for (int q = 0; q < 4; q++) {
            int r = q * 8 + brow;
            const float* src = B + (size_t)(k0 + r) * Nn + colBase + bc4;
            uint32_t dst = bufb + (uint32_t)(ASZ + r * BSTRIDE + bc4) * 4u;
            int sz = (colBase + bc4 + 4 <= Nn) ? 16 : 0;
            asm volatile("cp.async.cg.shared.global [%0], [%1], 16, %2;\n"
                         :: "r"(dst), "l"(src), "r"(sz));
        }
        asm volatile("cp.async.commit_group;\n");
    };

    loadTile(0);
    if (nk > 1) loadTile(1);

    for (int k0i = 0; k0i < nk; k0i++) {
        if (k0i + 1 < nk) asm volatile("cp.async.wait_group 1;\n");
        else              asm volatile("cp.async.wait_group 0;\n");
        __syncthreads();
        if (k0i + 2 < nk) loadTile(k0i + 2);

        const uint32_t* As = sm + (k0i % 3) * STG;
        const uint32_t* Bs = As + ASZ;

#pragma unroll
        for (int kk = 0; kk < 32; kk += 8) {
            uint32_t af[2][4];
#pragma unroll
            for (int mi = 0; mi < 2; mi++) {
                int r = wm * 32 + mi * 16;
                af[mi][0] = As[(r + g) * ASTRIDE + kk + t4];
                af[mi][1] = As[(r + g + 8) * ASTRIDE + kk + t4];
                af[mi][2] = As[(r + g) * ASTRIDE + kk + t4 + 4];
                af[mi][3] = As[(r + g + 8) * ASTRIDE + kk + t4 + 4];
            }
            uint32_t bf[8][2];
#pragma unroll
            for (int ni = 0; ni < 8; ni++) {
                int c = wn * 64 + ni * 8 + g;
                bf[ni][0] = Bs[(kk + t4) * BSTRIDE + c];
                bf[ni][1] = Bs[(kk + t4 + 4) * BSTRIDE + c];
            }
#pragma unroll
            for (int mi = 0; mi < 2; mi++)
#pragma unroll
                for (int ni = 0; ni < 8; ni++) {
                    asm volatile(
                        "mma.sync.aligned.m16n8k8.row.col.f32.tf32.tf32.f32 "
                        "{%0,%1,%2,%3}, {%4,%5,%6,%7}, {%8,%9}, {%0,%1,%2,%3};"
                        : "+f"(acc[mi][ni][0]), "+f"(acc[mi][ni][1]),
                          "+f"(acc[mi][ni][2]), "+f"(acc[mi][ni][3])
                        : "r"(af[mi][0]), "r"(af[mi][1]), "r"(af[mi][2]), "r"(af[mi][3]),
                          "r"(bf[ni][0]), "r"(bf[ni][1]));
                }
        }
    }

#pragma unroll
    for (int mi = 0; mi < 2; mi++) {
#pragma unroll
        for (int ni = 0; ni < 8; ni++) {
            int r0 = rowBase + wm * 32 + mi * 16 + g;
            int c0 = colBase + wn * 64 + ni * 8 + t4 * 2;
#pragma unroll
            for (int half = 0; half < 2; half++) {
                int r = r0 + half * 8;
                if (r >= M) continue;
                float vx = acc[mi][ni][half * 2];
                float vy = acc[mi][ni][half * 2 + 1];
                if (EPI == 0) {
                    if (c0 >= Nn) continue;
                    if (bias) { vx += bias[c0]; vy += bias[c0 + 1]; }
                    *(float2*)(C + (size_t)r * Nn + c0) = make_float2(vx, vy);
                } else if (EPI == 1) {
                    if (c0 >= Nn) continue;
                    ((__half2*)C)[(size_t)r * 128 + (c0 >> 1)] = __floats2half2_rn(vx, vy);
                } else if (EPI == 2) {
                    if (c0 >= 328) continue;
                    if (c0 < 256) {
                        ((__half2*)C)[(size_t)r * 128 + (c0 >> 1)] = __floats2half2_rn(vx, vy);
                    } else if (c0 < 320) {
                        int cc = c0 - 256;
                        *(float2*)(D + (size_t)r * 64 + cc) =
                            make_float2(vx + bias[cc], vy + bias[cc + 1]);
                    } else if (c0 < 324) {
                        *(float2*)(g_als + (size_t)r * 4 + (c0 - 320)) = make_float2(vx, vy);
                    } else {
                        *(float2*)(g_ald + (size_t)r * 4 + (c0 - 324)) = make_float2(vx, vy);
                    }
                } else {  // EPI == 3
                    if (c0 >= 32) continue;
                    if (c0 < 16) {
                        *(float2*)(C + (size_t)r * 16 + c0) = make_float2(vx, vy);
                    } else {
                        int cc = c0 - 16;
                        *(float2*)(D + (size_t)r * 16 + cc) =
                            make_float2(vx + bias[cc], vy + bias[cc + 1]);
                    }
                }
            }
        }
    }
}

// ---------------- narrow FFMA GEMM: M x 64, K=16 (stage-4 W4) ---------------
__global__ void gemm_k16(const float* __restrict__ A, const float* __restrict__ B,
                         float* __restrict__ C) {
    __shared__ float Bs[16 * 64];
    int tid = threadIdx.x;
    ((float4*)Bs)[tid] = ((const float4*)B)[tid];
    __syncthreads();
    int row = blockIdx.x * 256 + tid;
    if (row >= NN) return;
    float a[16];
#pragma unroll
    for (int q = 0; q < 4; q++) {
        float4 v = *(const float4*)(A + (size_t)row * 16 + q * 4);
        a[q * 4] = v.x; a[q * 4 + 1] = v.y; a[q * 4 + 2] = v.z; a[q * 4 + 3] = v.w;
    }
    float acc[64];
#pragma unroll
    for (int c = 0; c < 64; c++) acc[c] = 0.0f;
#pragma unroll
    for (int k = 0; k < 16; k++) {
        float av = a[k];
#pragma unroll
        for (int c = 0; c < 64; c++) acc[c] = fmaf(av, Bs[k * 64 + c], acc[c]);
    }
#pragma unroll
    for (int q = 0; q < 16; q++) {
        *(float4*)(C + (size_t)row * 64 + q * 4) =
            make_float4(acc[q * 4], acc[q * 4 + 1], acc[q * 4 + 2], acc[q * 4 + 3]);
    }
}

// ---------------- GCN gather (fp16 h) + fused BN partials -------------------
// 8 warps = 8 nodes; each lane owns 4 half2 (8 columns: pairs at 2*(q*32+lane)).
__global__ void gcn_gather_bn256(const __half2* __restrict__ h, const float* __restrict__ bias,
                                 float* __restrict__ out) {
    __shared__ float ss[2048], sq[2048];
    int tid = threadIdx.x, w = tid >> 5, lane = tid & 31;
    int node = blockIdx.x * 8 + w;
    float2 acc[4];
#pragma unroll
    for (int q = 0; q < 4; q++) acc[q] = make_float2(0.f, 0.f);
    float dv = g_dinv[node];
    int s0 = g_rowstart[node], s1 = g_rowstart[node + 1];
    for (int p = s0; p < s1; p++) {
        float2 ep = g_epack[p];
        int s = __float_as_int(ep.x);
        float norm = ep.y;
        const __half2* hp = h + (size_t)s * 128;
#pragma unroll
        for (int q = 0; q < 4; q++) {
            float2 f = __half22float2(hp[q * 32 + lane]);
            acc[q].x = fmaf(norm, f.x, acc[q].x);
            acc[q].y = fmaf(norm, f.y, acc[q].y);
        }
    }
    const __half2* hd = h + (size_t)node * 128;
    float self = dv * dv;
#pragma unroll
    for (int q = 0; q < 4; q++) {
        int c = 2 * (q * 32 + lane);
        float2 fd = __half22float2(hd[q * 32 + lane]);
        float2 bv = *(const float2*)(bias + c);
        float vx = acc[q].x + self * fd.x + bv.x;
        float vy = acc[q].y + self * fd.y + bv.y;
        *(float2*)(out + (size_t)node * 256 + c) = make_float2(vx, vy);
        ss[w * 256 + c] = vx;     sq[w * 256 + c] = vx * vx;
        ss[w * 256 + c + 1] = vy; sq[w * 256 + c + 1] = vy * vy;
    }
    __syncthreads();
    float s = 0.f, q = 0.f;
#pragma unroll
    for (int w2 = 0; w2 < 8; w2++) { s += ss[w2 * 256 + tid]; q += sq[w2 * 256 + tid]; }
    g_bnp1[(size_t)blockIdx.x * 256 + tid] = s;
    g_bnp2[(size_t)blockIdx.x * 256 + tid] = q;
}

// stage-4 gather, C=64 (fp32 h); output rounded tf32
__global__ void gcn_gather64(const float* __restrict__ h, const float* __restrict__ bias,
                             float* __restrict__ out) {
    int warp = (blockIdx.x * blockDim.x + threadIdx.x) >> 5;
    int lane = threadIdx.x & 31;
    if (warp >= NN) return;
    float a0 = 0.f, a1 = 0.f;
    float dv = g_dinv[warp];
    int s0 = g_rowstart[warp], s1 = g_rowstart[warp + 1];
    for (int p = s0; p < s1; p++) {
        float2 ep = g_epack[p];
        int s = __float_as_int(ep.x);
        float norm = ep.y;
        const float* hp = h + (size_t)s * 64;
        a0 = fmaf(norm, hp[lane], a0);
        a1 = fmaf(norm, hp[32 + lane], a1);
    }
    const float* hd = h + (size_t)warp * 64;
    float self = dv * dv;
    out[(size_t)warp * 64 + lane]      = f2tf32f(a0 + self * hd[lane] + bias[lane]);
    out[(size_t)warp * 64 + 32 + lane] = f2tf32f(a1 + self * hd[32 + lane] + bias[32 + lane]);
}

// C=16 gather + BN partials
__global__ void gcn_gather16_bn(const float* __restrict__ h, const float* __restrict__ bias,
                                float* __restrict__ out) {
    __shared__ float ss[1024], sq[1024];
    int tid = threadIdx.x;
    int idx = blockIdx.x * 256 + tid;
    int node = idx >> 2, q4 = idx & 3;
    float ox = 0.f, oy = 0.f, oz = 0.f, ow = 0.f;
    if (node < NN) {
        float ax = 0.f, ay = 0.f, az = 0.f, aw = 0.f;
        float dv = g_dinv[node];
        int s0 = g_rowstart[node], s1 = g_rowstart[node + 1];
        for (int p = s0; p < s1; p++) {
            float2 ep = g_epack[p];
            int s = __float_as_int(ep.x);
            float norm = ep.y;
            float4 v = *(const float4*)(h + (size_t)s * 16 + q4 * 4);
            ax = fmaf(norm, v.x, ax); ay = fmaf(norm, v.y, ay);
            az = fmaf(norm, v.z, az); aw = fmaf(norm, v.w, aw);
        }
        float4 hv = *(const float4*)(h + (size_t)node * 16 + q4 * 4);
        float4 bv = *(const float4*)(bias + q4 * 4);
        float self = dv * dv;
        ox = ax + self * hv.x + bv.x;
        oy = ay + self * hv.y + bv.y;
        oz = az + self * hv.z + bv.z;
        ow = aw + self * hv.w + bv.w;
        *(float4*)(out + (size_t)node * 16 + q4 * 4) = make_float4(ox, oy, oz, ow);
    }
    ss[tid * 4 + 0] = ox; sq[tid * 4 + 0] = ox * ox;
    ss[tid * 4 + 1] = oy; sq[tid * 4 + 1] = oy * oy;
    ss[tid * 4 + 2] = oz; sq[tid * 4 + 2] = oz * oz;
    ss[tid * 4 + 3] = ow; sq[tid * 4 + 3] = ow * ow;
    __syncthreads();
    if (tid < 16) {
        int qq = tid >> 2, ii = tid & 3;
        float s = 0.f, q = 0.f;
        for (int nl = 0; nl < 64; nl++) {
            s += ss[(nl * 4 + qq) * 4 + ii];
            q += sq[(nl * 4 + qq) * 4 + ii];
        }
        g_bnp1[(size_t)blockIdx.x * 16 + tid] = s;
        g_bnp2[(size_t)blockIdx.x * 16 + tid] = q;
    }
}

// ---------------- GAT gather (fp16 h2) + fused BN partials ------------------
// Lane owns half2 q*32+lane for q=0..3 (columns 2*(q*32+lane), +1); head = q.
__global__ void gat_gather_bn(const __half2* __restrict__ h2, const float* __restrict__ bg,
                              float* __restrict__ out) {
    __shared__ float ss[512], sq[512];
    int tid = threadIdx.x, w = tid >> 5, lane = tid & 31;
    int node = blockIdx.x * 8 + w;
    float4 adv = *(const float4*)(g_ald + (size_t)node * 4);
    float4 asv = *(const float4*)(g_als + (size_t)node * 4);
    float ad[4] = {adv.x, adv.y, adv.z, adv.w};
    float eself[4];
    {
        float as_[4] = {asv.x, asv.y, asv.z, asv.w};
#pragma unroll
        for (int hh = 0; hh < 4; hh++) {
            float lg = as_[hh] + ad[hh];
            eself[hh] = lg > 0.f ? lg : 0.2f * lg;
        }
    }
    int s0 = g_rowstart[node], s1 = g_rowstart[node + 1];
    // pass A: per-head max
    float m[4] = {eself[0], eself[1], eself[2], eself[3]};
    for (int p = s0 + lane; p < s1; p += 32) {
        int s = __float_as_int(g_epack[p].x);
        float4 a = *(const float4*)(g_als + (size_t)s * 4);
        float lg;
        lg = a.x + ad[0]; m[0] = fmaxf(m[0], lg > 0.f ? lg : 0.2f * lg);
        lg = a.y + ad[1]; m[1] = fmaxf(m[1], lg > 0.f ? lg : 0.2f * lg);
        lg = a.z + ad[2]; m[2] = fmaxf(m[2], lg > 0.f ? lg : 0.2f * lg);
        lg = a.w + ad[3]; m[3] = fmaxf(m[3], lg > 0.f ? lg : 0.2f * lg);
    }
#pragma unroll
    for (int hh = 0; hh < 4; hh++)
#pragma unroll
        for (int off = 16; off > 0; off >>= 1)
            m[hh] = fmaxf(m[hh], __shfl_xor_sync(0xffffffffu, m[hh], off));

    // pass B: exp on lanes 0..3, broadcast; head q maps to half2 quadrant q
    float adL = ad[0], mL = m[0];
    if (lane == 1) { adL = ad[1]; mL = m[1]; }
    else if (lane == 2) { adL = ad[2]; mL = m[2]; }
    else if (lane == 3) { adL = ad[3]; mL = m[3]; }
    float2 acc[4];
#pragma unroll
    for (int q = 0; q < 4; q++) acc[q] = make_float2(0.f, 0.f);
    float denL = 0.f;
    for (int p = s0; p < s1; p++) {
        int s = __float_as_int(g_epack[p].x);
        float ee = 0.f;
        if (lane < 4) {
            float a = g_als[(size_t)s * 4 + lane];
            float lg = a + adL;
            lg = lg > 0.f ? lg : 0.2f * lg;
            ee = __expf(lg - mL);
            denL += ee;
        }
        float eh[4];
        eh[0] = __shfl_sync(0xffffffffu, ee, 0);
        eh[1] = __shfl_sync(0xffffffffu, ee, 1);
        eh[2] = __shfl_sync(0xffffffffu, ee, 2);
        eh[3] = __shfl_sync(0xffffffffu, ee, 3);
        const __half2* hp = h2 + (size_t)s * 128;
#pragma unroll
        for (int q = 0; q < 4; q++) {
            float2 f = __half22float2(hp[q * 32 + lane]);
            acc[q].x = fmaf(eh[q], f.x, acc[q].x);
            acc[q].y = fmaf(eh[q], f.y, acc[q].y);
        }
    }
    float es[4], den[4];
#pragma unroll
    for (int hh = 0; hh < 4; hh++) {
        es[hh] = __expf(eself[hh] - m[hh]);
        den[hh] = __shfl_sync(0xffffffffu, denL, hh) + es[hh];
    }
    const __half2* hd = h2 + (size_t)node * 128;
    float o0 = 0.f, o1 = 0.f;
#pragma unroll
    for (int q = 0; q < 4; q++) {
        float2 fd = __half22float2(hd[q * 32 + lane]);
        float inv = 1.0f / den[q];
        o0 += (acc[q].x + es[q] * fd.x) * inv;
        o1 += (acc[q].y + es[q] * fd.y) * inv;
    }
    int c = 2 * lane;  // output columns c, c+1 (d = 2*lane within head)
    float t0 = 0.25f * o0 + bg[c];
    float t1 = 0.25f * o1 + bg[c + 1];
    *(float2*)(out + (size_t)node * 64 + c) = make_float2(t0, t1);
    ss[w * 64 + c] = t0;     sq[w * 64 + c] = t0 * t0;
    ss[w * 64 + c + 1] = t1; sq[w * 64 + c + 1] = t1 * t1;
    __syncthreads();
    if (tid < 64) {
        float s = 0.f, q = 0.f;
#pragma unroll
        for (int w2 = 0; w2 < 8; w2++) { s += ss[w2 * 64 + tid]; q += sq[w2 * 64 + tid]; }
        g_bnp1[(size_t)blockIdx.x * 64 + tid] = s;
        g_bnp2[(size_t)blockIdx.x * 64 + tid] = q;
    }
}

// ---------------- host ----------------
static inline int cdiv(int a, int b) { return (a + b - 1) / b; }

extern "C" void kernel_launch(void* const* d_in, const int* in_sizes, int n_in,
                              void* d_out, int out_size) {
    const float* x    = (const float*)d_in[0];
    const void*  edges = d_in[1];
    const float* b1   = (const float*)d_in[3];
    const float* g1   = (const float*)d_in[4];
    const float* be1  = (const float*)d_in[5];
    const float* Wg   = (const float*)d_in[6];
    const float* a_src = (const float*)d_in[7];
    const float* a_dst = (const float*)d_in[8];
    const float* bg   = (const float*)d_in[9];
    const float* g2   = (const float*)d_in[10];
    const float* be2  = (const float*)d_in[11];
    const float* b3   = (const float*)d_in[13];
    const float* g3   = (const float*)d_in[14];
    const float* be3  = (const float*)d_in[15];
    const float* W4   = (const float*)d_in[16];
    const float* b4   = (const float*)d_in[17];
    const float* r1b  = (const float*)d_in[19];
    const float* r2b  = (const float*)d_in[21];
    const float* r3b  = (const float*)d_in[23];
    const float* pb   = (const float*)d_in[25];
    float* out = (float*)d_out;

    float *h, *t, *x2, *xr, *res, *x3, *x4, *wr, *w2c, *w3c;
    cudaGetSymbolAddress((void**)&h,   g_h);
    cudaGetSymbolAddress((void**)&t,   g_t);
    cudaGetSymbolAddress((void**)&x2,  g_x2);
    cudaGetSymbolAddress((void**)&xr,  g_xr);
    cudaGetSymbolAddress((void**)&res, g_res);
    cudaGetSymbolAddress((void**)&x3,  g_x3);
    cudaGetSymbolAddress((void**)&x4,  g_x4);
    cudaGetSymbolAddress((void**)&wr,  g_wr);
    cudaGetSymbolAddress((void**)&w2c, g_w2comb);
    cudaGetSymbolAddress((void**)&w3c, g_w3comb);

    static cudaStream_t s1 = nullptr;
    static cudaEvent_t evFork = nullptr, evCSR = nullptr, evXR = nullptr, evG1 = nullptr;
    if (s1 == nullptr) {
        cudaStreamCreateWithFlags(&s1, cudaStreamNonBlocking);
        cudaEventCreateWithFlags(&evFork, cudaEventDisableTiming);
        cudaEventCreateWithFlags(&evCSR,  cudaEventDisableTiming);
        cudaEventCreateWithFlags(&evXR,   cudaEventDisableTiming);
        cudaEventCreateWithFlags(&evG1,   cudaEventDisableTiming);
        const int SMEMB_ = SMEM_WORDS * 4;
        cudaFuncSetAttribute(tf32_gemm_ca<0>,
                             cudaFuncAttributeMaxDynamicSharedMemorySize, SMEMB_);
        cudaFuncSetAttribute(tf32_gemm_ca<1>,
                             cudaFuncAttributeMaxDynamicSharedMemorySize, SMEMB_);
        cudaFuncSetAttribute(tf32_gemm_ca<2>,
                             cudaFuncAttributeMaxDynamicSharedMemorySize, SMEMB_);
        cudaFuncSetAttribute(tf32_gemm_ca<3>,
                             cudaFuncAttributeMaxDynamicSharedMemorySize, SMEMB_);
    }
    const int SMEMB = SMEM_WORDS * 4;  // 107520

    const float invN = 1.0f / (float)NN;
    const int MB = cdiv(NN, 128);  // 391

    float* wW1  = wr + 0;
    float* wr1W = wr + 65536;
    float* wpW  = wr + 215040;

    // ---- fork: CSR chain on s1; rounding + weight prep + GEMM1 on main ----
    cudaEventRecord(evFork, 0);
    cudaStreamWaitEvent(s1, evFork, 0);
    detect_kernel<<<1, 1, 0, s1>>>(edges);
    zero_indeg<<<cdiv(NN, 256), 256, 0, s1>>>();
    csr_count<<<cdiv(NE, 256), 256, 0, s1>>>(edges);
    scan1<<<NB196, 256, 0, s1>>>();
    scan2<<<1, 256, 0, s1>>>();
    scan3<<<NB196, 256, 0, s1>>>();
    csr_place<<<cdiv(NE, 256), 256, 0, s1>>>(edges);
    cudaEventRecord(evCSR, s1);

    round_weights<<<214, 256>>>((const float4*)d_in[2], (const float4*)d_in[18],
                                (const float4*)d_in[6], (const float4*)d_in[20],
                                (const float4*)d_in[12], (const float4*)d_in[22],
                                (const float4*)d_in[24]);
    alpha_fold<<<1, 256>>>(Wg, a_src, a_dst);
    build_w2comb<<<384, 256>>>();
    build_w3comb<<<8, 256>>>();
    round_x<<<12500, 256>>>((const float4*)x);
    cudaEventRecord(evXR, 0);
    tf32_gemm_ca<1><<<dim3(2, MB), 256, SMEMB>>>(
        xr, wW1, nullptr, h, nullptr, NN, 256, 256);   // h in fp16

    // ---- Stage 1: gather+BN on main; r1W GEMM concurrently on s1 ----
    cudaStreamWaitEvent(0, evCSR, 0);
    gcn_gather_bn256<<<GB1, 256>>>((const __half2*)h, b1, t);
    cudaStreamWaitEvent(s1, evXR, 0);
    tf32_gemm_ca<0><<<dim3(2, MB), 256, SMEMB, s1>>>(
        xr, wr1W, r1b, res, nullptr, NN, 256, 256);
    cudaEventRecord(evG1, s1);
    bn_reduce<256><<<256, 256>>>(GB1, invN);
    cudaStreamWaitEvent(0, evG1, 0);
    fuse_res<256, true><<<12500, 256>>>((const float4*)t, (const float4*)res, g1, be1,
                                        (float4*)x2, NN * 64);

    // ---- Stage 2: mega-GEMM [Wg|r2W|Ws|Wd] -> h(fp16), res, als, ald ----
    tf32_gemm_ca<2><<<dim3(3, MB), 256, SMEMB>>>(
        x2, w2c, r2b, h, res, NN, 384, 256);
    gat_gather_bn<<<GB1, 256>>>((const __half2*)h, bg, t);
    bn_reduce<64><<<64, 256>>>(GB1, invN);
    fuse_res<64, true><<<3125, 256>>>((const float4*)t, (const float4*)res, g2, be2,
                                      (float4*)x3, NN * 16);

    // ---- Stage 3: merged [W3|r3W] GEMM -> h16(float), res16 ----
    tf32_gemm_ca<3><<<dim3(1, MB), 256, SMEMB>>>(
        x3, w3c, r3b, h, res, NN, 32, 64);
    gcn_gather16_bn<<<GB3, 256>>>(h, b3, t);
    bn_reduce<16><<<16, 256>>>(GB3, invN);
    fuse_res<16, false><<<782, 256>>>((const float4*)t, (const float4*)res, g3, be3,
                                      (float4*)x4, NN * 4);

    // ---- Stage 4: GCN(16->64) fp32, then final linear ----
    gemm_k16<<<NB196, 256>>>(x4, W4, h);
    gcn_gather64<<<cdiv(NN * 32, 256), 256>>>(h, b4, t);
    tf32_gemm_ca<0><<<dim3(1, MB), 256, SMEMB>>>(
        t, wpW, pb, out, nullptr, NN, 64, 64);
}

// round 13
// speedup vs baseline: 2.7791x; 1.1109x over previous
#include <cuda_runtime.h>
#include <cuda_fp16.h>
#include <cstdint>

#define NN 50000
#define NE 800000
#define NB196 196   // ceil(NN/256)
#define GB1 6250    // gather blocks, stages 1/2 (NN*32/256)
#define GB3 782     // ceil(NN*4/256)
#define WRTOT 219136

// ---------------- device scratch (static, no runtime alloc) ----------------
__device__ float g_h  [NN * 256];   // stages 1-2: reinterpreted as __half[NN*256]
__device__ float g_t  [NN * 256];
__device__ float g_x2 [NN * 256];
__device__ float g_xr [NN * 256];
__device__ float g_res[NN * 256];
__device__ float g_x3 [NN * 64];
__device__ float g_x4 [NN * 16];
__device__ float g_wr [WRTOT];
__device__ float g_ws [256 * 4];
__device__ float g_wd [256 * 4];
__device__ float g_w2comb[256 * 384];
__device__ float g_w3comb[64 * 32];
__device__ float g_dinv[NN];
__device__ int   g_indeg[NN];
__device__ int   g_rowstart[NN + 1];
__device__ int   g_cursor[NN];
__device__ float2 g_epack[NE];
__device__ int   g_scanpart[NN];
__device__ int   g_blocksum[NB196];
__device__ int   g_blockoff[NB196];
__device__ float g_als[NN * 4];
__device__ float g_ald[NN * 4];
__device__ float g_bnp1[GB1 * 256];
__device__ float g_bnp2[GB1 * 256];
__device__ float g_mu  [256];
__device__ float g_rstd[256];
__device__ int   g_e64;

__device__ __forceinline__ uint32_t f2tf32(float x) {
    uint32_t r;
    asm("cvt.rna.tf32.f32 %0, %1;" : "=r"(r) : "f"(x));
    return r;
}
__device__ __forceinline__ float f2tf32f(float x) { return __uint_as_float(f2tf32(x)); }

// ---------------- edge dtype detect ----------------
__global__ void detect_kernel(const void* edges) {
    const int2* q = (const int2*)edges;
    int all0 = 1;
    for (int k = 0; k < 64; k++) {
        if (q[k * 12497 + 3].y != 0) { all0 = 0; break; }
    }
    g_e64 = all0;
}

__global__ void zero_indeg() {
    int i = blockIdx.x * blockDim.x + threadIdx.x;
    if (i < NN) g_indeg[i] = 0;
}

__global__ void csr_count(const void* edges) {
    int e = blockIdx.x * blockDim.x + threadIdx.x;
    if (e >= NE) return;
    int d;
    if (g_e64) d = (int)((const long long*)edges)[NE + e];
    else       d = ((const int*)edges)[NE + e];
    atomicAdd(&g_indeg[d], 1);
}

// ---------------- parallel exclusive scan over indeg ------------------------
__global__ void scan1() {
    int b = blockIdx.x, t = threadIdx.x;
    int i = b * 256 + t;
    int d = (i < NN) ? g_indeg[i] : 0;
    int lane = t & 31, w = t >> 5;
    int v = d;
#pragma unroll
    for (int off = 1; off < 32; off <<= 1) {
        int u = __shfl_up_sync(0xffffffffu, v, off);
        if (lane >= off) v += u;
    }
    __shared__ int ws[8];
    if (lane == 31) ws[w] = v;
    __syncthreads();
    if (t == 0) {
        int run = 0;
        for (int j = 0; j < 8; j++) { int x = ws[j]; ws[j] = run; run += x; }
    }
    __syncthreads();
    v += ws[w];
    if (i < NN) g_scanpart[i] = v;
    if (t == 255) g_blocksum[b] = v;
}

__global__ void scan2() {
    int t = threadIdx.x;
    int d = (t < NB196) ? g_blocksum[t] : 0;
    int lane = t & 31, w = t >> 5;
    int v = d;
#pragma unroll
    for (int off = 1; off < 32; off <<= 1) {
        int u = __shfl_up_sync(0xffffffffu, v, off);
        if (lane >= off) v += u;
    }
    __shared__ int ws[8];
    if (lane == 31) ws[w] = v;
    __syncthreads();
    if (t == 0) {
        int run = 0;
        for (int j = 0; j < 8; j++) { int x = ws[j]; ws[j] = run; run += x; }
    }
    __syncthreads();
    v += ws[w];
    if (t < NB196) g_blockoff[t] = v - d;
}

__global__ void scan3() {
    int i = blockIdx.x * blockDim.x + threadIdx.x;
    if (i < NN) {
        int deg = g_indeg[i];
        int excl = g_blockoff[blockIdx.x] + g_scanpart[i] - deg;
        g_rowstart[i] = excl;
        g_cursor[i] = excl;
        g_dinv[i] = rsqrtf((float)deg + 1.0f);
    }
    if (i == 0) g_rowstart[NN] = NE;
}

__global__ void csr_place(const void* edges) {
    int e = blockIdx.x * blockDim.x + threadIdx.x;
    if (e >= NE) return;
    int s, d;
    if (g_e64) {
        s = (int)((const long long*)edges)[e];
        d = (int)((const long long*)edges)[NE + e];
    } else {
        s = ((const int*)edges)[e];
        d = ((const int*)edges)[NE + e];
    }
    int pos = atomicAdd(&g_cursor[d], 1);
    g_epack[pos] = make_float2(__int_as_float(s), g_dinv[s] * g_dinv[d]);
}

// ---------------- operand pre-rounding (tf32 RN) ----------------------------
__global__ void round_x(const float4* __restrict__ x) {
    int i = blockIdx.x * 256 + threadIdx.x;
    if (i >= NN * 64) return;
    float4 v = x[i];
    v.x = f2tf32f(v.x); v.y = f2tf32f(v.y); v.z = f2tf32f(v.z); v.w = f2tf32f(v.w);
    ((float4*)g_xr)[i] = v;
}

__global__ void round_weights(const float4* W1, const float4* r1W, const float4* Wg,
                              const float4* r2W, const float4* W3, const float4* r3W,
                              const float4* pW) {
    int i = blockIdx.x * 256 + threadIdx.x;   // 54784 float4
    if (i >= 54784) return;
    const float4* s; int b;
    if      (i < 16384) { s = W1;  b = 0; }
    else if (i < 32768) { s = r1W; b = 16384; }
    else if (i < 49152) { s = Wg;  b = 32768; }
    else if (i < 53248) { s = r2W; b = 49152; }
    else if (i < 53504) { s = W3;  b = 53248; }
    else if (i < 53760) { s = r3W; b = 53504; }
    else                { s = pW;  b = 53760; }
    float4 v = s[i - b];
    v.x = f2tf32f(v.x); v.y = f2tf32f(v.y); v.z = f2tf32f(v.z); v.w = f2tf32f(v.w);
    ((float4*)g_wr)[i] = v;
}

// fold GAT attention vectors through Wg (exact)
__global__ void alpha_fold(const float* __restrict__ Wg, const float* __restrict__ a_s,
                           const float* __restrict__ a_d) {
    int k = threadIdx.x;  // 256
    const float* wrow = Wg + (size_t)k * 256;
#pragma unroll
    for (int hh = 0; hh < 4; hh++) {
        float s = 0.f, d = 0.f;
#pragma unroll 8
        for (int dd = 0; dd < 64; dd++) {
            float w = wrow[hh * 64 + dd];
            s = fmaf(w, a_s[hh * 64 + dd], s);
            d = fmaf(w, a_d[hh * 64 + dd], d);
        }
        g_ws[k * 4 + hh] = s;
        g_wd[k * 4 + hh] = d;
    }
}

__global__ void build_w2comb() {
    int idx = blockIdx.x * 256 + threadIdx.x;  // 98304
    if (idx >= 256 * 384) return;
    int r = idx / 384, c = idx % 384;
    float v;
    if      (c < 256) v = g_wr[131072 + r * 256 + c];
    else if (c < 320) v = g_wr[196608 + r * 64 + (c - 256)];
    else if (c < 324) v = f2tf32f(g_ws[r * 4 + (c - 320)]);
    else if (c < 328) v = f2tf32f(g_wd[r * 4 + (c - 324)]);
    else              v = 0.f;
    g_w2comb[idx] = v;
}

__global__ void build_w3comb() {
    int idx = blockIdx.x * 256 + threadIdx.x;  // 2048
    if (idx >= 64 * 32) return;
    int r = idx / 32, c = idx % 32;
    g_w3comb[idx] = (c < 16) ? g_wr[212992 + r * 16 + c]
                             : g_wr[214016 + r * 16 + (c - 16)];
}

// ---------------- BN partial reduce ----------------------------------------
template <int C>
__global__ void bn_reduce(int nblocks, float invN) {
    int c = blockIdx.x, t = threadIdx.x;
    double s = 0.0, q = 0.0;
    for (int b = t; b < nblocks; b += 256) {
        s += (double)g_bnp1[(size_t)b * C + c];
        q += (double)g_bnp2[(size_t)b * C + c];
    }
    __shared__ double sh[256], sh2[256];
    sh[t] = s; sh2[t] = q;
    __syncthreads();
    for (int off = 128; off; off >>= 1) {
        if (t < off) { sh[t] += sh[t + off]; sh2[t] += sh2[t + off]; }
        __syncthreads();
    }
    if (t == 0) {
        double m = sh[0] * (double)invN;
        double v = sh2[0] * (double)invN - m * m;
        g_mu[c] = (float)m;
        g_rstd[c] = rsqrtf((float)v + 1e-5f);
    }
}

// ---------------- BN+leaky+residual fuse ------------------------------------
template <int C, bool RND>
__global__ void fuse_res(const float4* __restrict__ t, const float4* __restrict__ res,
                         const float* __restrict__ g, const float* __restrict__ be,
                         float4* __restrict__ out, int n4) {
    int i = blockIdx.x * 256 + threadIdx.x;
    if (i >= n4) return;
    int c0 = (i * 4) & (C - 1);
    float4 tv = t[i], rv = res[i];
    float4 o;
    float u;
    u = (tv.x - g_mu[c0    ]) * g_rstd[c0    ] * g[c0    ] + be[c0    ];
    o.x = (u > 0.f ? u : 0.01f * u) + rv.x;
    u = (tv.y - g_mu[c0 + 1]) * g_rstd[c0 + 1] * g[c0 + 1] + be[c0 + 1];
    o.y = (u > 0.f ? u : 0.01f * u) + rv.y;
    u = (tv.z - g_mu[c0 + 2]) * g_rstd[c0 + 2] * g[c0 + 2] + be[c0 + 2];
    o.z = (u > 0.f ? u : 0.01f * u) + rv.z;
    u = (tv.w - g_mu[c0 + 3]) * g_rstd[c0 + 3] * g[c0 + 3] + be[c0 + 3];
    o.w = (u > 0.f ? u : 0.01f * u) + rv.w;
    if (RND) {
        o.x = f2tf32f(o.x); o.y = f2tf32f(o.y);
        o.z = f2tf32f(o.z); o.w = f2tf32f(o.w);
    }
    out[i] = o;
}

// ---------------- tf32 tensor-core GEMM, 3-stage cp.async -------------------
// EPI=0: float C + bias.
// EPI=1: fp16 C (no bias) — stage-1 h.
// EPI=2: stage-2 routing: c<256 -> fp16 h; c<320 -> res(+bias); c<324 -> als; c<328 -> ald.
// EPI=3: stage-3 routing: c<16 -> h16(float); c<32 -> res16(+bias).
#define ASTRIDE 36
#define BSTRIDE 136
#define ASZ (128 * ASTRIDE)
#define BSZ (32 * BSTRIDE)
#define STG (ASZ + BSZ)
#define SMEM_WORDS (3 * STG)     // 107520 B

template <int EPI>
__global__ __launch_bounds__(256, 2)
void tf32_gemm_ca(const float* __restrict__ A, const float* __restrict__ B,
                  const float* __restrict__ bias, float* __restrict__ C,
                  float* __restrict__ D, int M, int Nn, int K) {
    extern __shared__ uint32_t sm[];
    const int tid = threadIdx.x;
    const int warp = tid >> 5, lane = tid & 31;
    const int wm = warp >> 1, wn = warp & 1;
    const int g = lane >> 2, t4 = lane & 3;
    const int rowBase = blockIdx.y * 128;
    const int colBase = blockIdx.x * 128;
    const uint32_t sbase = (uint32_t)__cvta_generic_to_shared(sm);

    const int arow = tid >> 3, ac4 = (tid & 7) * 4;
    const int brow = tid >> 5, bc4 = (tid & 31) * 4;

    float acc[2][8][4];
#pragma unroll
    for (int mi = 0; mi < 2; mi++)
#pragma unroll
        for (int ni = 0; ni < 8; ni++)
#pragma unroll
            for (int j = 0; j < 4; j++) acc[mi][ni][j] = 0.0f;

    const int nk = K >> 5;

    auto loadTile = [&](int k0i) {
        int buf = k0i % 3;
        int k0 = k0i << 5;
        uint32_t bufb = sbase + (uint32_t)(buf * STG) * 4u;
#pragma unroll
        for (int q = 0; q < 4; q++) {
            int r = q * 32 + arow;
            const float* src = A + (size_t)(rowBase + r) * K + k0 + ac4;
            uint32_t dst = bufb + (uint32_t)(r * ASTRIDE + ac4) * 4u;
            int sz = (rowBase + r < M) ? 16 : 0;
            asm volatile("cp.async.cg.shared.global [%0], [%1], 16, %2;\n"
                         :: "r"(dst), "l"(src), "r"(sz));
        }
#pragma unroll
        for (int q = 0; q < 4; q++) {
            int r = q * 8 + brow;
            const float* src = B + (size_t)(k0 + r) * Nn + colBase + bc4;
            uint32_t dst = bufb + (uint32_t)(ASZ + r * BSTRIDE + bc4) * 4u;
            int sz = (colBase + bc4 + 4 <= Nn) ? 16 : 0;
            asm volatile("cp.async.cg.shared.global [%0], [%1], 16, %2;\n"
                         :: "r"(dst), "l"(src), "r"(sz));
        }
        asm volatile("cp.async.commit_group;\n");
    };

    loadTile(0);
    if (nk > 1) loadTile(1);

    for (int k0i = 0; k0i < nk; k0i++) {
        if (k0i + 1 < nk) asm volatile("cp.async.wait_group 1;\n");
        else              asm volatile("cp.async.wait_group 0;\n");
        __syncthreads();
        if (k0i + 2 < nk) loadTile(k0i + 2);

        const uint32_t* As = sm + (k0i % 3) * STG;
        const uint32_t* Bs = As + ASZ;

#pragma unroll
        for (int kk = 0; kk < 32; kk += 8) {
            uint32_t af[2][4];
#pragma unroll
            for (int mi = 0; mi < 2; mi++) {
                int r = wm * 32 + mi * 16;
                af[mi][0] = As[(r + g) * ASTRIDE + kk + t4];
                af[mi][1] = As[(r + g + 8) * ASTRIDE + kk + t4];
                af[mi][2] = As[(r + g) * ASTRIDE + kk + t4 + 4];
                af[mi][3] = As[(r + g + 8) * ASTRIDE + kk + t4 + 4];
            }
            uint32_t bf[8][2];
#pragma unroll
            for (int ni = 0; ni < 8; ni++) {
                int c = wn * 64 + ni * 8 + g;
                bf[ni][0] = Bs[(kk + t4) * BSTRIDE + c];
                bf[ni][1] = Bs[(kk + t4 + 4) * BSTRIDE + c];
            }
#pragma unroll
            for (int mi = 0; mi < 2; mi++)
#pragma unroll
                for (int ni = 0; ni < 8; ni++) {
                    asm volatile(
                        "mma.sync.aligned.m16n8k8.row.col.f32.tf32.tf32.f32 "
                        "{%0,%1,%2,%3}, {%4,%5,%6,%7}, {%8,%9}, {%0,%1,%2,%3};"
                        : "+f"(acc[mi][ni][0]), "+f"(acc[mi][ni][1]),
                          "+f"(acc[mi][ni][2]), "+f"(acc[mi][ni][3])
                        : "r"(af[mi][0]), "r"(af[mi][1]), "r"(af[mi][2]), "r"(af[mi][3]),
                          "r"(bf[ni][0]), "r"(bf[ni][1]));
                }
        }
    }

#pragma unroll
    for (int mi = 0; mi < 2; mi++) {
#pragma unroll
        for (int ni = 0; ni < 8; ni++) {
            int r0 = rowBase + wm * 32 + mi * 16 + g;
            int c0 = colBase + wn * 64 + ni * 8 + t4 * 2;
#pragma unroll
            for (int half = 0; half < 2; half++) {
                int r = r0 + half * 8;
                if (r >= M) continue;
                float vx = acc[mi][ni][half * 2];
                float vy = acc[mi][ni][half * 2 + 1];
                if (EPI == 0) {
                    if (c0 >= Nn) continue;
                    if (bias) { vx += bias[c0]; vy += bias[c0 + 1]; }
                    *(float2*)(C + (size_t)r * Nn + c0) = make_float2(vx, vy);
                } else if (EPI == 1) {
                    if (c0 >= Nn) continue;
                    ((__half2*)C)[(size_t)r * 128 + (c0 >> 1)] = __floats2half2_rn(vx, vy);
                } else if (EPI == 2) {
                    if (c0 >= 328) continue;
                    if (c0 < 256) {
                        ((__half2*)C)[(size_t)r * 128 + (c0 >> 1)] = __floats2half2_rn(vx, vy);
                    } else if (c0 < 320) {
                        int cc = c0 - 256;
                        *(float2*)(D + (size_t)r * 64 + cc) =
                            make_float2(vx + bias[cc], vy + bias[cc + 1]);
                    } else if (c0 < 324) {
                        *(float2*)(g_als + (size_t)r * 4 + (c0 - 320)) = make_float2(vx, vy);
                    } else {
                        *(float2*)(g_ald + (size_t)r * 4 + (c0 - 324)) = make_float2(vx, vy);
                    }
                } else {  // EPI == 3
                    if (c0 >= 32) continue;
                    if (c0 < 16) {
                        *(float2*)(C + (size_t)r * 16 + c0) = make_float2(vx, vy);
                    } else {
                        int cc = c0 - 16;
                        *(float2*)(D + (size_t)r * 16 + cc) =
                            make_float2(vx + bias[cc], vy + bias[cc + 1]);
                    }
                }
            }
        }
    }
}

// ---------------- narrow FFMA GEMM: M x 64, K=16 (stage-4 W4) ---------------
__global__ void gemm_k16(const float* __restrict__ A, const float* __restrict__ B,
                         float* __restrict__ C) {
    __shared__ float Bs[16 * 64];
    int tid = threadIdx.x;
    ((float4*)Bs)[tid] = ((const float4*)B)[tid];
    __syncthreads();
    int row = blockIdx.x * 256 + tid;
    if (row >= NN) return;
    float a[16];
#pragma unroll
    for (int q = 0; q < 4; q++) {
        float4 v = *(const float4*)(A + (size_t)row * 16 + q * 4);
        a[q * 4] = v.x; a[q * 4 + 1] = v.y; a[q * 4 + 2] = v.z; a[q * 4 + 3] = v.w;
    }
    float acc[64];
#pragma unroll
    for (int c = 0; c < 64; c++) acc[c] = 0.0f;
#pragma unroll
    for (int k = 0; k < 16; k++) {
        float av = a[k];
#pragma unroll
        for (int c = 0; c < 64; c++) acc[c] = fmaf(av, Bs[k * 64 + c], acc[c]);
    }
#pragma unroll
    for (int q = 0; q < 16; q++) {
        *(float4*)(C + (size_t)row * 64 + q * 4) =
            make_float4(acc[q * 4], acc[q * 4 + 1], acc[q * 4 + 2], acc[q * 4 + 3]);
    }
}

// ---------------- GCN gather (fp16 h, 2-edge unrolled) + BN partials --------
__global__ void gcn_gather_bn256(const __half2* __restrict__ h, const float* __restrict__ bias,
                                 float* __restrict__ out) {
    __shared__ float ss[2048], sq[2048];
    int tid = threadIdx.x, w = tid >> 5, lane = tid & 31;
    int node = blockIdx.x * 8 + w;
    float2 acc[4];
#pragma unroll
    for (int q = 0; q < 4; q++) acc[q] = make_float2(0.f, 0.f);
    float dv = g_dinv[node];
    int s0 = g_rowstart[node], s1 = g_rowstart[node + 1];
    int p = s0;
    for (; p + 2 <= s1; p += 2) {
        float2 e0 = g_epack[p], e1 = g_epack[p + 1];
        const __half2* h0 = h + (size_t)__float_as_int(e0.x) * 128;
        const __half2* h1 = h + (size_t)__float_as_int(e1.x) * 128;
        __half2 v0[4], v1[4];
#pragma unroll
        for (int q = 0; q < 4; q++) { v0[q] = h0[q * 32 + lane]; v1[q] = h1[q * 32 + lane]; }
#pragma unroll
        for (int q = 0; q < 4; q++) {
            float2 f0 = __half22float2(v0[q]);
            acc[q].x = fmaf(e0.y, f0.x, acc[q].x);
            acc[q].y = fmaf(e0.y, f0.y, acc[q].y);
            float2 f1 = __half22float2(v1[q]);
            acc[q].x = fmaf(e1.y, f1.x, acc[q].x);
            acc[q].y = fmaf(e1.y, f1.y, acc[q].y);
        }
    }
    if (p < s1) {
        float2 e0 = g_epack[p];
        const __half2* h0 = h + (size_t)__float_as_int(e0.x) * 128;
#pragma unroll
        for (int q = 0; q < 4; q++) {
            float2 f0 = __half22float2(h0[q * 32 + lane]);
            acc[q].x = fmaf(e0.y, f0.x, acc[q].x);
            acc[q].y = fmaf(e0.y, f0.y, acc[q].y);
        }
    }
    const __half2* hd = h + (size_t)node * 128;
    float self = dv * dv;
#pragma unroll
    for (int q = 0; q < 4; q++) {
        int c = 2 * (q * 32 + lane);
        float2 fd = __half22float2(hd[q * 32 + lane]);
        float2 bv = *(const float2*)(bias + c);
        float vx = acc[q].x + self * fd.x + bv.x;
        float vy = acc[q].y + self * fd.y + bv.y;
        *(float2*)(out + (size_t)node * 256 + c) = make_float2(vx, vy);
        ss[w * 256 + c] = vx;     sq[w * 256 + c] = vx * vx;
        ss[w * 256 + c + 1] = vy; sq[w * 256 + c + 1] = vy * vy;
    }
    __syncthreads();
    float s = 0.f, q = 0.f;
#pragma unroll
    for (int w2 = 0; w2 < 8; w2++) { s += ss[w2 * 256 + tid]; q += sq[w2 * 256 + tid]; }
    g_bnp1[(size_t)blockIdx.x * 256 + tid] = s;
    g_bnp2[(size_t)blockIdx.x * 256 + tid] = q;
}

// stage-4 gather, C=64 (fp32 h, 2-edge unrolled); output rounded tf32
__global__ void gcn_gather64(const float* __restrict__ h, const float* __restrict__ bias,
                             float* __restrict__ out) {
    int warp = (blockIdx.x * blockDim.x + threadIdx.x) >> 5;
    int lane = threadIdx.x & 31;
    if (warp >= NN) return;
    float a0 = 0.f, a1 = 0.f;
    float dv = g_dinv[warp];
    int s0 = g_rowstart[warp], s1 = g_rowstart[warp + 1];
    int p = s0;
    for (; p + 2 <= s1; p += 2) {
        float2 e0 = g_epack[p], e1 = g_epack[p + 1];
        const float* h0 = h + (size_t)__float_as_int(e0.x) * 64;
        const float* h1 = h + (size_t)__float_as_int(e1.x) * 64;
        float u0 = h0[lane], u1 = h0[32 + lane];
        float u2 = h1[lane], u3 = h1[32 + lane];
        a0 = fmaf(e0.y, u0, a0); a1 = fmaf(e0.y, u1, a1);
        a0 = fmaf(e1.y, u2, a0); a1 = fmaf(e1.y, u3, a1);
    }
    if (p < s1) {
        float2 e0 = g_epack[p];
        const float* h0 = h + (size_t)__float_as_int(e0.x) * 64;
        a0 = fmaf(e0.y, h0[lane], a0);
        a1 = fmaf(e0.y, h0[32 + lane], a1);
    }
    const float* hd = h + (size_t)warp * 64;
    float self = dv * dv;
    out[(size_t)warp * 64 + lane]      = f2tf32f(a0 + self * hd[lane] + bias[lane]);
    out[(size_t)warp * 64 + 32 + lane] = f2tf32f(a1 + self * hd[32 + lane] + bias[32 + lane]);
}

// C=16 gather (2-edge unrolled) + BN partials
__global__ void gcn_gather16_bn(const float* __restrict__ h, const float* __restrict__ bias,
                                float* __restrict__ out) {
    __shared__ float ss[1024], sq[1024];
    int tid = threadIdx.x;
    int idx = blockIdx.x * 256 + tid;
    int node = idx >> 2, q4 = idx & 3;
    float ox = 0.f, oy = 0.f, oz = 0.f, ow = 0.f;
    if (node < NN) {
        float ax = 0.f, ay = 0.f, az = 0.f, aw = 0.f;
        float dv = g_dinv[node];
        int s0 = g_rowstart[node], s1 = g_rowstart[node + 1];
        int p = s0;
        for (; p + 2 <= s1; p += 2) {
            float2 e0 = g_epack[p], e1 = g_epack[p + 1];
            float4 v0 = *(const float4*)(h + (size_t)__float_as_int(e0.x) * 16 + q4 * 4);
            float4 v1 = *(const float4*)(h + (size_t)__float_as_int(e1.x) * 16 + q4 * 4);
            ax = fmaf(e0.y, v0.x, ax); ay = fmaf(e0.y, v0.y, ay);
            az = fmaf(e0.y, v0.z, az); aw = fmaf(e0.y, v0.w, aw);
            ax = fmaf(e1.y, v1.x, ax); ay = fmaf(e1.y, v1.y, ay);
            az = fmaf(e1.y, v1.z, az); aw = fmaf(e1.y, v1.w, aw);
        }
        if (p < s1) {
            float2 e0 = g_epack[p];
            float4 v0 = *(const float4*)(h + (size_t)__float_as_int(e0.x) * 16 + q4 * 4);
            ax = fmaf(e0.y, v0.x, ax); ay = fmaf(e0.y, v0.y, ay);
            az = fmaf(e0.y, v0.z, az); aw = fmaf(e0.y, v0.w, aw);
        }
        float4 hv = *(const float4*)(h + (size_t)node * 16 + q4 * 4);
        float4 bv = *(const float4*)(bias + q4 * 4);
        float self = dv * dv;
        ox = ax + self * hv.x + bv.x;
        oy = ay + self * hv.y + bv.y;
        oz = az + self * hv.z + bv.z;
        ow = aw + self * hv.w + bv.w;
        *(float4*)(out + (size_t)node * 16 + q4 * 4) = make_float4(ox, oy, oz, ow);
    }
    ss[tid * 4 + 0] = ox; sq[tid * 4 + 0] = ox * ox;
    ss[tid * 4 + 1] = oy; sq[tid * 4 + 1] = oy * oy;
    ss[tid * 4 + 2] = oz; sq[tid * 4 + 2] = oz * oz;
    ss[tid * 4 + 3] = ow; sq[tid * 4 + 3] = ow * ow;
    __syncthreads();
    if (tid < 16) {
        int qq = tid >> 2, ii = tid & 3;
        float s = 0.f, q = 0.f;
        for (int nl = 0; nl < 64; nl++) {
            s += ss[(nl * 4 + qq) * 4 + ii];
            q += sq[(nl * 4 + qq) * 4 + ii];
        }
        g_bnp1[(size_t)blockIdx.x * 16 + tid] = s;
        g_bnp2[(size_t)blockIdx.x * 16 + tid] = q;
    }
}

// ---------------- GAT gather (fp16 h2, 2-edge unrolled) + BN partials -------
// Lane owns half2 q*32+lane for q=0..3; head = q. In the main loop lanes 0-7
// compute exp for two edges (lane>>2 selects edge, lane&3 the head).
__global__ void gat_gather_bn(const __half2* __restrict__ h2, const float* __restrict__ bg,
                              float* __restrict__ out) {
    __shared__ float ss[512], sq[512];
    int tid = threadIdx.x, w = tid >> 5, lane = tid & 31;
    int node = blockIdx.x * 8 + w;
    float4 adv = *(const float4*)(g_ald + (size_t)node * 4);
    float4 asv = *(const float4*)(g_als + (size_t)node * 4);
    float ad[4] = {adv.x, adv.y, adv.z, adv.w};
    float eself[4];
    {
        float as_[4] = {asv.x, asv.y, asv.z, asv.w};
#pragma unroll
        for (int hh = 0; hh < 4; hh++) {
            float lg = as_[hh] + ad[hh];
            eself[hh] = lg > 0.f ? lg : 0.2f * lg;
        }
    }
    int s0 = g_rowstart[node], s1 = g_rowstart[node + 1];
    // pass A: per-head max
    float m[4] = {eself[0], eself[1], eself[2], eself[3]};
    for (int p = s0 + lane; p < s1; p += 32) {
        int s = __float_as_int(g_epack[p].x);
        float4 a = *(const float4*)(g_als + (size_t)s * 4);
        float lg;
        lg = a.x + ad[0]; m[0] = fmaxf(m[0], lg > 0.f ? lg : 0.2f * lg);
        lg = a.y + ad[1]; m[1] = fmaxf(m[1], lg > 0.f ? lg : 0.2f * lg);
        lg = a.z + ad[2]; m[2] = fmaxf(m[2], lg > 0.f ? lg : 0.2f * lg);
        lg = a.w + ad[3]; m[3] = fmaxf(m[3], lg > 0.f ? lg : 0.2f * lg);
    }
#pragma unroll
    for (int hh = 0; hh < 4; hh++)
#pragma unroll
        for (int off = 16; off > 0; off >>= 1)
            m[hh] = fmaxf(m[hh], __shfl_xor_sync(0xffffffffu, m[hh], off));

    // per-lane head params for lanes 0-7 (head = lane & 3)
    int h4 = lane & 3;
    float adL = ad[0], mL = m[0];
    if (h4 == 1) { adL = ad[1]; mL = m[1]; }
    else if (h4 == 2) { adL = ad[2]; mL = m[2]; }
    else if (h4 == 3) { adL = ad[3]; mL = m[3]; }

    float2 acc[4];
#pragma unroll
    for (int q = 0; q < 4; q++) acc[q] = make_float2(0.f, 0.f);
    float denL = 0.f;  // lanes 0-7 accumulate; head denom = lane h + lane h+4
    int p = s0;
    for (; p + 2 <= s1; p += 2) {
        int sA = __float_as_int(g_epack[p].x);
        int sB = __float_as_int(g_epack[p + 1].x);
        float ee = 0.f;
        if (lane < 8) {
            int sN = (lane < 4) ? sA : sB;
            float a = g_als[(size_t)sN * 4 + h4];
            float lg = a + adL;
            lg = lg > 0.f ? lg : 0.2f * lg;
            ee = __expf(lg - mL);
            denL += ee;
        }
        float ehA[4], ehB[4];
#pragma unroll
        for (int q = 0; q < 4; q++) {
            ehA[q] = __shfl_sync(0xffffffffu, ee, q);
            ehB[q] = __shfl_sync(0xffffffffu, ee, 4 + q);
        }
        const __half2* hpA = h2 + (size_t)sA * 128;
        const __half2* hpB = h2 + (size_t)sB * 128;
        __half2 vA[4], vB[4];
#pragma unroll
        for (int q = 0; q < 4; q++) { vA[q] = hpA[q * 32 + lane]; vB[q] = hpB[q * 32 + lane]; }
#pragma unroll
        for (int q = 0; q < 4; q++) {
            float2 fA = __half22float2(vA[q]);
            acc[q].x = fmaf(ehA[q], fA.x, acc[q].x);
            acc[q].y = fmaf(ehA[q], fA.y, acc[q].y);
            float2 fB = __half22float2(vB[q]);
            acc[q].x = fmaf(ehB[q], fB.x, acc[q].x);
            acc[q].y = fmaf(ehB[q], fB.y, acc[q].y);
        }
    }
    if (p < s1) {
        int sA = __float_as_int(g_epack[p].x);
        float ee = 0.f;
        if (lane < 4) {
            float a = g_als[(size_t)sA * 4 + h4];
            float lg = a + adL;
            lg = lg > 0.f ? lg : 0.2f * lg;
            ee = __expf(lg - mL);
            denL += ee;
        }
        float ehA[4];
#pragma unroll
        for (int q = 0; q < 4; q++) ehA[q] = __shfl_sync(0xffffffffu, ee, q);
        const __half2* hpA = h2 + (size_t)sA * 128;
#pragma unroll
        for (int q = 0; q < 4; q++) {
            float2 fA = __half22float2(hpA[q * 32 + lane]);
            acc[q].x = fmaf(ehA[q], fA.x, acc[q].x);
            acc[q].y = fmaf(ehA[q], fA.y, acc[q].y);
        }
    }
    float es[4], den[4];
#pragma unroll
    for (int hh = 0; hh < 4; hh++) {
        es[hh] = __expf(eself[hh] - m[hh]);
        den[hh] = __shfl_sync(0xffffffffu, denL, hh)
                + __shfl_sync(0xffffffffu, denL, hh + 4) + es[hh];
    }
    const __half2* hd = h2 + (size_t)node * 128;
    float o0 = 0.f, o1 = 0.f;
#pragma unroll
    for (int q = 0; q < 4; q++) {
        float2 fd = __half22float2(hd[q * 32 + lane]);
        float inv = 1.0f / den[q];
        o0 += (acc[q].x + es[q] * fd.x) * inv;
        o1 += (acc[q].y + es[q] * fd.y) * inv;
    }
    int c = 2 * lane;
    float t0 = 0.25f * o0 + bg[c];
    float t1 = 0.25f * o1 + bg[c + 1];
    *(float2*)(out + (size_t)node * 64 + c) = make_float2(t0, t1);
    ss[w * 64 + c] = t0;     sq[w * 64 + c] = t0 * t0;
    ss[w * 64 + c + 1] = t1; sq[w * 64 + c + 1] = t1 * t1;
    __syncthreads();
    if (tid < 64) {
        float s = 0.f, q = 0.f;
#pragma unroll
        for (int w2 = 0; w2 < 8; w2++) { s += ss[w2 * 64 + tid]; q += sq[w2 * 64 + tid]; }
        g_bnp1[(size_t)blockIdx.x * 64 + tid] = s;
        g_bnp2[(size_t)blockIdx.x * 64 + tid] = q;
    }
}

// ---------------- host ----------------
static inline int cdiv(int a, int b) { return (a + b - 1) / b; }

extern "C" void kernel_launch(void* const* d_in, const int* in_sizes, int n_in,
                              void* d_out, int out_size) {
    const float* x    = (const float*)d_in[0];
    const void*  edges = d_in[1];
    const float* b1   = (const float*)d_in[3];
    const float* g1   = (const float*)d_in[4];
    const float* be1  = (const float*)d_in[5];
    const float* Wg   = (const float*)d_in[6];
    const float* a_src = (const float*)d_in[7];
    const float* a_dst = (const float*)d_in[8];
    const float* bg   = (const float*)d_in[9];
    const float* g2   = (const float*)d_in[10];
    const float* be2  = (const float*)d_in[11];
    const float* b3   = (const float*)d_in[13];
    const float* g3   = (const float*)d_in[14];
    const float* be3  = (const float*)d_in[15];
    const float* W4   = (const float*)d_in[16];
    const float* b4   = (const float*)d_in[17];
    const float* r1b  = (const float*)d_in[19];
    const float* r2b  = (const float*)d_in[21];
    const float* r3b  = (const float*)d_in[23];
    const float* pb   = (const float*)d_in[25];
    float* out = (float*)d_out;

    float *h, *t, *x2, *xr, *res, *x3, *x4, *wr, *w2c, *w3c;
    cudaGetSymbolAddress((void**)&h,   g_h);
    cudaGetSymbolAddress((void**)&t,   g_t);
    cudaGetSymbolAddress((void**)&x2,  g_x2);
    cudaGetSymbolAddress((void**)&xr,  g_xr);
    cudaGetSymbolAddress((void**)&res, g_res);
    cudaGetSymbolAddress((void**)&x3,  g_x3);
    cudaGetSymbolAddress((void**)&x4,  g_x4);
    cudaGetSymbolAddress((void**)&wr,  g_wr);
    cudaGetSymbolAddress((void**)&w2c, g_w2comb);
    cudaGetSymbolAddress((void**)&w3c, g_w3comb);

    static cudaStream_t s1 = nullptr;
    static cudaEvent_t evFork = nullptr, evCSR = nullptr, evXR = nullptr, evG1 = nullptr;
    if (s1 == nullptr) {
        cudaStreamCreateWithFlags(&s1, cudaStreamNonBlocking);
        cudaEventCreateWithFlags(&evFork, cudaEventDisableTiming);
        cudaEventCreateWithFlags(&evCSR,  cudaEventDisableTiming);
        cudaEventCreateWithFlags(&evXR,   cudaEventDisableTiming);
        cudaEventCreateWithFlags(&evG1,   cudaEventDisableTiming);
        const int SMEMB_ = SMEM_WORDS * 4;
        cudaFuncSetAttribute(tf32_gemm_ca<0>,
                             cudaFuncAttributeMaxDynamicSharedMemorySize, SMEMB_);
        cudaFuncSetAttribute(tf32_gemm_ca<1>,
                             cudaFuncAttributeMaxDynamicSharedMemorySize, SMEMB_);
        cudaFuncSetAttribute(tf32_gemm_ca<2>,
                             cudaFuncAttributeMaxDynamicSharedMemorySize, SMEMB_);
        cudaFuncSetAttribute(tf32_gemm_ca<3>,
                             cudaFuncAttributeMaxDynamicSharedMemorySize, SMEMB_);
    }
    const int SMEMB = SMEM_WORDS * 4;  // 107520

    const float invN = 1.0f / (float)NN;
    const int MB = cdiv(NN, 128);  // 391

    float* wW1  = wr + 0;
    float* wr1W = wr + 65536;
    float* wpW  = wr + 215040;

    // ---- main-stream prep first (submission order puts gemm1 at launch #6
    //      so ncu -s 5 -c 1 profiles the big GEMM); DAG unchanged via events --
    cudaEventRecord(evFork, 0);
    round_weights<<<214, 256>>>((const float4*)d_in[2], (const float4*)d_in[18],
                                (const float4*)d_in[6], (const float4*)d_in[20],
                                (const float4*)d_in[12], (const float4*)d_in[22],
                                (const float4*)d_in[24]);
    alpha_fold<<<1, 256>>>(Wg, a_src, a_dst);
    build_w2comb<<<384, 256>>>();
    build_w3comb<<<8, 256>>>();
    round_x<<<12500, 256>>>((const float4*)x);
    cudaEventRecord(evXR, 0);
    tf32_gemm_ca<1><<<dim3(2, MB), 256, SMEMB>>>(
        xr, wW1, nullptr, h, nullptr, NN, 256, 256);   // h in fp16  (launch #6)

    // ---- CSR chain on s1 (concurrent with the prep/GEMM above) ----
    cudaStreamWaitEvent(s1, evFork, 0);
    detect_kernel<<<1, 1, 0, s1>>>(edges);
    zero_indeg<<<cdiv(NN, 256), 256, 0, s1>>>();
    csr_count<<<cdiv(NE, 256), 256, 0, s1>>>(edges);
    scan1<<<NB196, 256, 0, s1>>>();
    scan2<<<1, 256, 0, s1>>>();
    scan3<<<NB196, 256, 0, s1>>>();
    csr_place<<<cdiv(NE, 256), 256, 0, s1>>>(edges);
    cudaEventRecord(evCSR, s1);

    // ---- Stage 1: gather+BN on main; r1W GEMM concurrently on s1 ----
    cudaStreamWaitEvent(0, evCSR, 0);
    gcn_gather_bn256<<<GB1, 256>>>((const __half2*)h, b1, t);
    cudaStreamWaitEvent(s1, evXR, 0);
    tf32_gemm_ca<0><<<dim3(2, MB), 256, SMEMB, s1>>>(
        xr, wr1W, r1b, res, nullptr, NN, 256, 256);
    cudaEventRecord(evG1, s1);
    bn_reduce<256><<<256, 256>>>(GB1, invN);
    cudaStreamWaitEvent(0, evG1, 0);
    fuse_res<256, true><<<12500, 256>>>((const float4*)t, (const float4*)res, g1, be1,
                                        (float4*)x2, NN * 64);

    // ---- Stage 2: mega-GEMM [Wg|r2W|Ws|Wd] -> h(fp16), res, als, ald ----
    tf32_gemm_ca<2><<<dim3(3, MB), 256, SMEMB>>>(
        x2, w2c, r2b, h, res, NN, 384, 256);
    gat_gather_bn<<<GB1, 256>>>((const __half2*)h, bg, t);
    bn_reduce<64><<<64, 256>>>(GB1, invN);
    fuse_res<64, true><<<3125, 256>>>((const float4*)t, (const float4*)res, g2, be2,
                                      (float4*)x3, NN * 16);

    // ---- Stage 3: merged [W3|r3W] GEMM -> h16(float), res16 ----
    tf32_gemm_ca<3><<<dim3(1, MB), 256, SMEMB>>>(
        x3, w3c, r3b, h, res, NN, 32, 64);
    gcn_gather16_bn<<<GB3, 256>>>(h, b3, t);
    bn_reduce<16><<<16, 256>>>(GB3, invN);
    fuse_res<16, false><<<782, 256>>>((const float4*)t, (const float4*)res, g3, be3,
                                      (float4*)x4, NN * 4);

    // ---- Stage 4: GCN(16->64) fp32, then final linear ----
    gemm_k16<<<NB196, 256>>>(x4, W4, h);
    gcn_gather64<<<cdiv(NN * 32, 256), 256>>>(h, b4, t);
    tf32_gemm_ca<0><<<dim3(1, MB), 256, SMEMB>>>(
        t, wpW, pb, out, nullptr, NN, 64, 64);
}

// round 14
// speedup vs baseline: 2.7822x; 1.0011x over previous
#include <cuda_runtime.h>
#include <cuda_fp16.h>
#include <cstdint>

#define NN 50000
#define NE 800000
#define NB196 196   // ceil(NN/256)
#define GB1 6250    // gather blocks, stages 1/2 (NN*32/256)
#define GB3 782     // ceil(NN*4/256)
#define WRTOT 219136

// ---------------- device scratch (static, no runtime alloc) ----------------
__device__ float g_h  [NN * 256];   // stages 1-2 & 4: reinterpreted as __half
__device__ float g_t  [NN * 256];
__device__ float g_x2 [NN * 256];
__device__ float g_xr [NN * 256];
__device__ float g_res[NN * 256];
__device__ float g_x3 [NN * 64];
__device__ float g_x4 [NN * 16];
__device__ float g_wr [WRTOT];
__device__ float g_ws [256 * 4];
__device__ float g_wd [256 * 4];
__device__ float g_w2comb[256 * 384];
__device__ float g_w3comb[64 * 32];
__device__ float g_dinv[NN];
__device__ int   g_indeg[NN];
__device__ int   g_rowstart[NN + 1];
__device__ int   g_cursor[NN];
__device__ float2 g_epack[NE];
__device__ int   g_scanpart[NN];
__device__ int   g_blocksum[NB196];
__device__ int   g_blockoff[NB196];
__device__ float g_als[NN * 4];
__device__ float g_ald[NN * 4];
__device__ float g_bnp1[GB1 * 256];
__device__ float g_bnp2[GB1 * 256];
__device__ float g_mu  [256];
__device__ float g_rstd[256];
__device__ int   g_e64;

__device__ __forceinline__ uint32_t f2tf32(float x) {
    uint32_t r;
    asm("cvt.rna.tf32.f32 %0, %1;" : "=r"(r) : "f"(x));
    return r;
}
__device__ __forceinline__ float f2tf32f(float x) { return __uint_as_float(f2tf32(x)); }

// ---------------- edge dtype detect ----------------
__global__ void detect_kernel(const void* edges) {
    const int2* q = (const int2*)edges;
    int all0 = 1;
    for (int k = 0; k < 64; k++) {
        if (q[k * 12497 + 3].y != 0) { all0 = 0; break; }
    }
    g_e64 = all0;
}

__global__ void zero_indeg() {
    int i = blockIdx.x * blockDim.x + threadIdx.x;
    if (i < NN) g_indeg[i] = 0;
}

__global__ void csr_count(const void* edges) {
    int e = blockIdx.x * blockDim.x + threadIdx.x;
    if (e >= NE) return;
    int d;
    if (g_e64) d = (int)((const long long*)edges)[NE + e];
    else       d = ((const int*)edges)[NE + e];
    atomicAdd(&g_indeg[d], 1);
}

// ---------------- parallel exclusive scan over indeg ------------------------
__global__ void scan1() {
    int b = blockIdx.x, t = threadIdx.x;
    int i = b * 256 + t;
    int d = (i < NN) ? g_indeg[i] : 0;
    int lane = t & 31, w = t >> 5;
    int v = d;
#pragma unroll
    for (int off = 1; off < 32; off <<= 1) {
        int u = __shfl_up_sync(0xffffffffu, v, off);
        if (lane >= off) v += u;
    }
    __shared__ int ws[8];
    if (lane == 31) ws[w] = v;
    __syncthreads();
    if (t == 0) {
        int run = 0;
        for (int j = 0; j < 8; j++) { int x = ws[j]; ws[j] = run; run += x; }
    }
    __syncthreads();
    v += ws[w];
    if (i < NN) g_scanpart[i] = v;
    if (t == 255) g_blocksum[b] = v;
}

__global__ void scan2() {
    int t = threadIdx.x;
    int d = (t < NB196) ? g_blocksum[t] : 0;
    int lane = t & 31, w = t >> 5;
    int v = d;
#pragma unroll
    for (int off = 1; off < 32; off <<= 1) {
        int u = __shfl_up_sync(0xffffffffu, v, off);
        if (lane >= off) v += u;
    }
    __shared__ int ws[8];
    if (lane == 31) ws[w] = v;
    __syncthreads();
    if (t == 0) {
        int run = 0;
        for (int j = 0; j < 8; j++) { int x = ws[j]; ws[j] = run; run += x; }
    }
    __syncthreads();
    v += ws[w];
    if (t < NB196) g_blockoff[t] = v - d;
}

__global__ void scan3() {
    int i = blockIdx.x * blockDim.x + threadIdx.x;
    if (i < NN) {
        int deg = g_indeg[i];
        int excl = g_blockoff[blockIdx.x] + g_scanpart[i] - deg;
        g_rowstart[i] = excl;
        g_cursor[i] = excl;
        g_dinv[i] = rsqrtf((float)deg + 1.0f);
    }
    if (i == 0) g_rowstart[NN] = NE;
}

__global__ void csr_place(const void* edges) {
    int e = blockIdx.x * blockDim.x + threadIdx.x;
    if (e >= NE) return;
    int s, d;
    if (g_e64) {
        s = (int)((const long long*)edges)[e];
        d = (int)((const long long*)edges)[NE + e];
    } else {
        s = ((const int*)edges)[e];
        d = ((const int*)edges)[NE + e];
    }
    int pos = atomicAdd(&g_cursor[d], 1);
    g_epack[pos] = make_float2(__int_as_float(s), g_dinv[s] * g_dinv[d]);
}

// ---------------- operand pre-rounding (tf32 RN) ----------------------------
__global__ void round_x(const float4* __restrict__ x) {
    int i = blockIdx.x * 256 + threadIdx.x;
    if (i >= NN * 64) return;
    float4 v = x[i];
    v.x = f2tf32f(v.x); v.y = f2tf32f(v.y); v.z = f2tf32f(v.z); v.w = f2tf32f(v.w);
    ((float4*)g_xr)[i] = v;
}

__global__ void round_weights(const float4* W1, const float4* r1W, const float4* Wg,
                              const float4* r2W, const float4* W3, const float4* r3W,
                              const float4* pW) {
    int i = blockIdx.x * 256 + threadIdx.x;   // 54784 float4
    if (i >= 54784) return;
    const float4* s; int b;
    if      (i < 16384) { s = W1;  b = 0; }
    else if (i < 32768) { s = r1W; b = 16384; }
    else if (i < 49152) { s = Wg;  b = 32768; }
    else if (i < 53248) { s = r2W; b = 49152; }
    else if (i < 53504) { s = W3;  b = 53248; }
    else if (i < 53760) { s = r3W; b = 53504; }
    else                { s = pW;  b = 53760; }
    float4 v = s[i - b];
    v.x = f2tf32f(v.x); v.y = f2tf32f(v.y); v.z = f2tf32f(v.z); v.w = f2tf32f(v.w);
    ((float4*)g_wr)[i] = v;
}

// fold GAT attention vectors through Wg (exact)
__global__ void alpha_fold(const float* __restrict__ Wg, const float* __restrict__ a_s,
                           const float* __restrict__ a_d) {
    int k = threadIdx.x;  // 256
    const float* wrow = Wg + (size_t)k * 256;
#pragma unroll
    for (int hh = 0; hh < 4; hh++) {
        float s = 0.f, d = 0.f;
#pragma unroll 8
        for (int dd = 0; dd < 64; dd++) {
            float w = wrow[hh * 64 + dd];
            s = fmaf(w, a_s[hh * 64 + dd], s);
            d = fmaf(w, a_d[hh * 64 + dd], d);
        }
        g_ws[k * 4 + hh] = s;
        g_wd[k * 4 + hh] = d;
    }
}

__global__ void build_w2comb() {
    int idx = blockIdx.x * 256 + threadIdx.x;  // 98304
    if (idx >= 256 * 384) return;
    int r = idx / 384, c = idx % 384;
    float v;
    if      (c < 256) v = g_wr[131072 + r * 256 + c];
    else if (c < 320) v = g_wr[196608 + r * 64 + (c - 256)];
    else if (c < 324) v = f2tf32f(g_ws[r * 4 + (c - 320)]);
    else if (c < 328) v = f2tf32f(g_wd[r * 4 + (c - 324)]);
    else              v = 0.f;
    g_w2comb[idx] = v;
}

__global__ void build_w3comb() {
    int idx = blockIdx.x * 256 + threadIdx.x;  // 2048
    if (idx >= 64 * 32) return;
    int r = idx / 32, c = idx % 32;
    g_w3comb[idx] = (c < 16) ? g_wr[212992 + r * 16 + c]
                             : g_wr[214016 + r * 16 + (c - 16)];
}

// ---------------- BN partial reduce ----------------------------------------
template <int C>
__global__ void bn_reduce(int nblocks, float invN) {
    int c = blockIdx.x, t = threadIdx.x;
    double s = 0.0, q = 0.0;
    for (int b = t; b < nblocks; b += 256) {
        s += (double)g_bnp1[(size_t)b * C + c];
        q += (double)g_bnp2[(size_t)b * C + c];
    }
    __shared__ double sh[256], sh2[256];
    sh[t] = s; sh2[t] = q;
    __syncthreads();
    for (int off = 128; off; off >>= 1) {
        if (t < off) { sh[t] += sh[t + off]; sh2[t] += sh2[t + off]; }
        __syncthreads();
    }
    if (t == 0) {
        double m = sh[0] * (double)invN;
        double v = sh2[0] * (double)invN - m * m;
        g_mu[c] = (float)m;
        g_rstd[c] = rsqrtf((float)v + 1e-5f);
    }
}

// ---------------- BN+leaky+residual fuse ------------------------------------
template <int C, bool RND>
__global__ void fuse_res(const float4* __restrict__ t, const float4* __restrict__ res,
                         const float* __restrict__ g, const float* __restrict__ be,
                         float4* __restrict__ out, int n4) {
    int i = blockIdx.x * 256 + threadIdx.x;
    if (i >= n4) return;
    int c0 = (i * 4) & (C - 1);
    float4 tv = t[i], rv = res[i];
    float4 o;
    float u;
    u = (tv.x - g_mu[c0    ]) * g_rstd[c0    ] * g[c0    ] + be[c0    ];
    o.x = (u > 0.f ? u : 0.01f * u) + rv.x;
    u = (tv.y - g_mu[c0 + 1]) * g_rstd[c0 + 1] * g[c0 + 1] + be[c0 + 1];
    o.y = (u > 0.f ? u : 0.01f * u) + rv.y;
    u = (tv.z - g_mu[c0 + 2]) * g_rstd[c0 + 2] * g[c0 + 2] + be[c0 + 2];
    o.z = (u > 0.f ? u : 0.01f * u) + rv.z;
    u = (tv.w - g_mu[c0 + 3]) * g_rstd[c0 + 3] * g[c0 + 3] + be[c0 + 3];
    o.w = (u > 0.f ? u : 0.01f * u) + rv.w;
    if (RND) {
        o.x = f2tf32f(o.x); o.y = f2tf32f(o.y);
        o.z = f2tf32f(o.z); o.w = f2tf32f(o.w);
    }
    out[i] = o;
}

// ---------------- tf32 tensor-core GEMM, 3-stage cp.async -------------------
// EPI=0: float C + bias.
// EPI=1: fp16 C (no bias) — stage-1 h.
// EPI=2: stage-2 routing: c<256 -> fp16 h; c<320 -> res(+bias); c<324 -> als; c<328 -> ald.
// EPI=3: stage-3 routing: c<16 -> h16(float); c<32 -> res16(+bias).
#define ASTRIDE 36
#define BSTRIDE 136
#define ASZ (128 * ASTRIDE)
#define BSZ (32 * BSTRIDE)
#define STG (ASZ + BSZ)
#define SMEM_WORDS (3 * STG)     // 107520 B

template <int EPI>
__global__ __launch_bounds__(256, 2)
void tf32_gemm_ca(const float* __restrict__ A, const float* __restrict__ B,
                  const float* __restrict__ bias, float* __restrict__ C,
                  float* __restrict__ D, int M, int Nn, int K) {
    extern __shared__ uint32_t sm[];
    const int tid = threadIdx.x;
    const int warp = tid >> 5, lane = tid & 31;
    const int wm = warp >> 1, wn = warp & 1;
    const int g = lane >> 2, t4 = lane & 3;
    const int rowBase = blockIdx.y * 128;
    const int colBase = blockIdx.x * 128;
    const uint32_t sbase = (uint32_t)__cvta_generic_to_shared(sm);

    const int arow = tid >> 3, ac4 = (tid & 7) * 4;
    const int brow = tid >> 5, bc4 = (tid & 31) * 4;

    float acc[2][8][4];
#pragma unroll
    for (int mi = 0; mi < 2; mi++)
#pragma unroll
        for (int ni = 0; ni < 8; ni++)
#pragma unroll
            for (int j = 0; j < 4; j++) acc[mi][ni][j] = 0.0f;

    const int nk = K >> 5;

    auto loadTile = [&](int k0i) {
        int buf = k0i % 3;
        int k0 = k0i << 5;
        uint32_t bufb = sbase + (uint32_t)(buf * STG) * 4u;
#pragma unroll
        for (int q = 0; q < 4; q++) {
            int r = q * 32 + arow;
            const float* src = A + (size_t)(rowBase + r) * K + k0 + ac4;
            uint32_t dst = bufb + (uint32_t)(r * ASTRIDE + ac4) * 4u;
            int sz = (rowBase + r < M) ? 16 : 0;
            asm volatile("cp.async.cg.shared.global [%0], [%1], 16, %2;\n"
                         :: "r"(dst), "l"(src), "r"(sz));
        }
#pragma unroll
        for (int q = 0; q < 4; q++) {
            int r = q * 8 + brow;
            const float* src = B + (size_t)(k0 + r) * Nn + colBase + bc4;
            uint32_t dst = bufb + (uint32_t)(ASZ + r * BSTRIDE + bc4) * 4u;
            int sz = (colBase + bc4 + 4 <= Nn) ? 16 : 0;
            asm volatile("cp.async.cg.shared.global [%0], [%1], 16, %2;\n"
                         :: "r"(dst), "l"(src), "r"(sz));
        }
        asm volatile("cp.async.commit_group;\n");
    };

    loadTile(0);
    if (nk > 1) loadTile(1);

    for (int k0i = 0; k0i < nk; k0i++) {
        if (k0i + 1 < nk) asm volatile("cp.async.wait_group 1;\n");
        else              asm volatile("cp.async.wait_group 0;\n");
        __syncthreads();
        if (k0i + 2 < nk) loadTile(k0i + 2);

        const uint32_t* As = sm + (k0i % 3) * STG;
        const uint32_t* Bs = As + ASZ;

#pragma unroll
        for (int kk = 0; kk < 32; kk += 8) {
            uint32_t af[2][4];
#pragma unroll
            for (int mi = 0; mi < 2; mi++) {
                int r = wm * 32 + mi * 16;
                af[mi][0] = As[(r + g) * ASTRIDE + kk + t4];
                af[mi][1] = As[(r + g + 8) * ASTRIDE + kk + t4];
                af[mi][2] = As[(r + g) * ASTRIDE + kk + t4 + 4];
                af[mi][3] = As[(r + g + 8) * ASTRIDE + kk + t4 + 4];
            }
            uint32_t bf[8][2];
#pragma unroll
            for (int ni = 0; ni < 8; ni++) {
                int c = wn * 64 + ni * 8 + g;
                bf[ni][0] = Bs[(kk + t4) * BSTRIDE + c];
                bf[ni][1] = Bs[(kk + t4 + 4) * BSTRIDE + c];
            }
#pragma unroll
            for (int mi = 0; mi < 2; mi++)
#pragma unroll
                for (int ni = 0; ni < 8; ni++) {
                    asm volatile(
                        "mma.sync.aligned.m16n8k8.row.col.f32.tf32.tf32.f32 "
                        "{%0,%1,%2,%3}, {%4,%5,%6,%7}, {%8,%9}, {%0,%1,%2,%3};"
                        : "+f"(acc[mi][ni][0]), "+f"(acc[mi][ni][1]),
                          "+f"(acc[mi][ni][2]), "+f"(acc[mi][ni][3])
                        : "r"(af[mi][0]), "r"(af[mi][1]), "r"(af[mi][2]), "r"(af[mi][3]),
                          "r"(bf[ni][0]), "r"(bf[ni][1]));
                }
        }
    }

#pragma unroll
    for (int mi = 0; mi < 2; mi++) {
#pragma unroll
        for (int ni = 0; ni < 8; ni++) {
            int r0 = rowBase + wm * 32 + mi * 16 + g;
            int c0 = colBase + wn * 64 + ni * 8 + t4 * 2;
#pragma unroll
            for (int half = 0; half < 2; half++) {
                int r = r0 + half * 8;
                if (r >= M) continue;
                float vx = acc[mi][ni][half * 2];
                float vy = acc[mi][ni][half * 2 + 1];
                if (EPI == 0) {
                    if (c0 >= Nn) continue;
                    if (bias) { vx += bias[c0]; vy += bias[c0 + 1]; }
                    *(float2*)(C + (size_t)r * Nn + c0) = make_float2(vx, vy);
                } else if (EPI == 1) {
                    if (c0 >= Nn) continue;
                    ((__half2*)C)[(size_t)r * 128 + (c0 >> 1)] = __floats2half2_rn(vx, vy);
                } else if (EPI == 2) {
                    if (c0 >= 328) continue;
                    if (c0 < 256) {
                        ((__half2*)C)[(size_t)r * 128 + (c0 >> 1)] = __floats2half2_rn(vx, vy);
                    } else if (c0 < 320) {
                        int cc = c0 - 256;
                        *(float2*)(D + (size_t)r * 64 + cc) =
                            make_float2(vx + bias[cc], vy + bias[cc + 1]);
                    } else if (c0 < 324) {
                        *(float2*)(g_als + (size_t)r * 4 + (c0 - 320)) = make_float2(vx, vy);
                    } else {
                        *(float2*)(g_ald + (size_t)r * 4 + (c0 - 324)) = make_float2(vx, vy);
                    }
                } else {  // EPI == 3
                    if (c0 >= 32) continue;
                    if (c0 < 16) {
                        *(float2*)(C + (size_t)r * 16 + c0) = make_float2(vx, vy);
                    } else {
                        int cc = c0 - 16;
                        *(float2*)(D + (size_t)r * 16 + cc) =
                            make_float2(vx + bias[cc], vy + bias[cc + 1]);
                    }
                }
            }
        }
    }
}

// ---------------- narrow FFMA GEMM: M x 64, K=16, fp16 out (stage-4 W4) -----
__global__ void gemm_k16(const float* __restrict__ A, const float* __restrict__ B,
                         __half2* __restrict__ C) {
    __shared__ float Bs[16 * 64];
    int tid = threadIdx.x;
    ((float4*)Bs)[tid] = ((const float4*)B)[tid];
    __syncthreads();
    int row = blockIdx.x * 256 + tid;
    if (row >= NN) return;
    float a[16];
#pragma unroll
    for (int q = 0; q < 4; q++) {
        float4 v = *(const float4*)(A + (size_t)row * 16 + q * 4);
        a[q * 4] = v.x; a[q * 4 + 1] = v.y; a[q * 4 + 2] = v.z; a[q * 4 + 3] = v.w;
    }
    float acc[64];
#pragma unroll
    for (int c = 0; c < 64; c++) acc[c] = 0.0f;
#pragma unroll
    for (int k = 0; k < 16; k++) {
        float av = a[k];
#pragma unroll
        for (int c = 0; c < 64; c++) acc[c] = fmaf(av, Bs[k * 64 + c], acc[c]);
    }
#pragma unroll
    for (int q = 0; q < 32; q++)
        C[(size_t)row * 32 + q] = __floats2half2_rn(acc[q * 2], acc[q * 2 + 1]);
}

// ---------------- GCN gather (fp16 h, 4-edge unrolled) + BN partials --------
__global__ void gcn_gather_bn256(const __half2* __restrict__ h, const float* __restrict__ bias,
                                 float* __restrict__ out) {
    __shared__ float ss[2048], sq[2048];
    int tid = threadIdx.x, w = tid >> 5, lane = tid & 31;
    int node = blockIdx.x * 8 + w;
    float2 acc[4];
#pragma unroll
    for (int q = 0; q < 4; q++) acc[q] = make_float2(0.f, 0.f);
    float dv = g_dinv[node];
    int s0 = g_rowstart[node], s1 = g_rowstart[node + 1];
    int p = s0;
    for (; p + 4 <= s1; p += 4) {
        float2 e0 = g_epack[p], e1 = g_epack[p + 1];
        float2 e2 = g_epack[p + 2], e3 = g_epack[p + 3];
        const __half2* h0 = h + (size_t)__float_as_int(e0.x) * 128;
        const __half2* h1 = h + (size_t)__float_as_int(e1.x) * 128;
        const __half2* h2 = h + (size_t)__float_as_int(e2.x) * 128;
        const __half2* h3 = h + (size_t)__float_as_int(e3.x) * 128;
        __half2 v0[4], v1[4], v2[4], v3[4];
#pragma unroll
        for (int q = 0; q < 4; q++) {
            v0[q] = h0[q * 32 + lane]; v1[q] = h1[q * 32 + lane];
            v2[q] = h2[q * 32 + lane]; v3[q] = h3[q * 32 + lane];
        }
#pragma unroll
        for (int q = 0; q < 4; q++) {
            float2 f;
            f = __half22float2(v0[q]);
            acc[q].x = fmaf(e0.y, f.x, acc[q].x); acc[q].y = fmaf(e0.y, f.y, acc[q].y);
            f = __half22float2(v1[q]);
            acc[q].x = fmaf(e1.y, f.x, acc[q].x); acc[q].y = fmaf(e1.y, f.y, acc[q].y);
            f = __half22float2(v2[q]);
            acc[q].x = fmaf(e2.y, f.x, acc[q].x); acc[q].y = fmaf(e2.y, f.y, acc[q].y);
            f = __half22float2(v3[q]);
            acc[q].x = fmaf(e3.y, f.x, acc[q].x); acc[q].y = fmaf(e3.y, f.y, acc[q].y);
        }
    }
    for (; p < s1; p++) {
        float2 e0 = g_epack[p];
        const __half2* h0 = h + (size_t)__float_as_int(e0.x) * 128;
#pragma unroll
        for (int q = 0; q < 4; q++) {
            float2 f0 = __half22float2(h0[q * 32 + lane]);
            acc[q].x = fmaf(e0.y, f0.x, acc[q].x);
            acc[q].y = fmaf(e0.y, f0.y, acc[q].y);
        }
    }
    const __half2* hd = h + (size_t)node * 128;
    float self = dv * dv;
#pragma unroll
    for (int q = 0; q < 4; q++) {
        int c = 2 * (q * 32 + lane);
        float2 fd = __half22float2(hd[q * 32 + lane]);
        float2 bv = *(const float2*)(bias + c);
        float vx = acc[q].x + self * fd.x + bv.x;
        float vy = acc[q].y + self * fd.y + bv.y;
        *(float2*)(out + (size_t)node * 256 + c) = make_float2(vx, vy);
        ss[w * 256 + c] = vx;     sq[w * 256 + c] = vx * vx;
        ss[w * 256 + c + 1] = vy; sq[w * 256 + c + 1] = vy * vy;
    }
    __syncthreads();
    float s = 0.f, q = 0.f;
#pragma unroll
    for (int w2 = 0; w2 < 8; w2++) { s += ss[w2 * 256 + tid]; q += sq[w2 * 256 + tid]; }
    g_bnp1[(size_t)blockIdx.x * 256 + tid] = s;
    g_bnp2[(size_t)blockIdx.x * 256 + tid] = q;
}

// stage-4 gather, C=64 (fp16 h, 4-edge unrolled); lane owns cols 2l,2l+1
__global__ void gcn_gather64(const __half2* __restrict__ h, const float* __restrict__ bias,
                             float* __restrict__ out) {
    int warp = (blockIdx.x * blockDim.x + threadIdx.x) >> 5;
    int lane = threadIdx.x & 31;
    if (warp >= NN) return;
    float a0 = 0.f, a1 = 0.f;
    float dv = g_dinv[warp];
    int s0 = g_rowstart[warp], s1 = g_rowstart[warp + 1];
    int p = s0;
    for (; p + 4 <= s1; p += 4) {
        float2 e0 = g_epack[p], e1 = g_epack[p + 1];
        float2 e2 = g_epack[p + 2], e3 = g_epack[p + 3];
        __half2 v0 = h[(size_t)__float_as_int(e0.x) * 32 + lane];
        __half2 v1 = h[(size_t)__float_as_int(e1.x) * 32 + lane];
        __half2 v2 = h[(size_t)__float_as_int(e2.x) * 32 + lane];
        __half2 v3 = h[(size_t)__float_as_int(e3.x) * 32 + lane];
        float2 f;
        f = __half22float2(v0); a0 = fmaf(e0.y, f.x, a0); a1 = fmaf(e0.y, f.y, a1);
        f = __half22float2(v1); a0 = fmaf(e1.y, f.x, a0); a1 = fmaf(e1.y, f.y, a1);
        f = __half22float2(v2); a0 = fmaf(e2.y, f.x, a0); a1 = fmaf(e2.y, f.y, a1);
        f = __half22float2(v3); a0 = fmaf(e3.y, f.x, a0); a1 = fmaf(e3.y, f.y, a1);
    }
    for (; p < s1; p++) {
        float2 e0 = g_epack[p];
        float2 f = __half22float2(h[(size_t)__float_as_int(e0.x) * 32 + lane]);
        a0 = fmaf(e0.y, f.x, a0);
        a1 = fmaf(e0.y, f.y, a1);
    }
    float2 fd = __half22float2(h[(size_t)warp * 32 + lane]);
    float self = dv * dv;
    int c = 2 * lane;
    out[(size_t)warp * 64 + c]     = f2tf32f(a0 + self * fd.x + bias[c]);
    out[(size_t)warp * 64 + c + 1] = f2tf32f(a1 + self * fd.y + bias[c + 1]);
}

// C=16 gather (2-edge unrolled) + BN partials
__global__ void gcn_gather16_bn(const float* __restrict__ h, const float* __restrict__ bias,
                                float* __restrict__ out) {
    __shared__ float ss[1024], sq[1024];
    int tid = threadIdx.x;
    int idx = blockIdx.x * 256 + tid;
    int node = idx >> 2, q4 = idx & 3;
    float ox = 0.f, oy = 0.f, oz = 0.f, ow = 0.f;
    if (node < NN) {
        float ax = 0.f, ay = 0.f, az = 0.f, aw = 0.f;
        float dv = g_dinv[node];
        int s0 = g_rowstart[node], s1 = g_rowstart[node + 1];
        int p = s0;
        for (; p + 2 <= s1; p += 2) {
            float2 e0 = g_epack[p], e1 = g_epack[p + 1];
            float4 v0 = *(const float4*)(h + (size_t)__float_as_int(e0.x) * 16 + q4 * 4);
            float4 v1 = *(const float4*)(h + (size_t)__float_as_int(e1.x) * 16 + q4 * 4);
            ax = fmaf(e0.y, v0.x, ax); ay = fmaf(e0.y, v0.y, ay);
            az = fmaf(e0.y, v0.z, az); aw = fmaf(e0.y, v0.w, aw);
            ax = fmaf(e1.y, v1.x, ax); ay = fmaf(e1.y, v1.y, ay);
            az = fmaf(e1.y, v1.z, az); aw = fmaf(e1.y, v1.w, aw);
        }
        if (p < s1) {
            float2 e0 = g_epack[p];
            float4 v0 = *(const float4*)(h + (size_t)__float_as_int(e0.x) * 16 + q4 * 4);
            ax = fmaf(e0.y, v0.x, ax); ay = fmaf(e0.y, v0.y, ay);
            az = fmaf(e0.y, v0.z, az); aw = fmaf(e0.y, v0.w, aw);
        }
        float4 hv = *(const float4*)(h + (size_t)node * 16 + q4 * 4);
        float4 bv = *(const float4*)(bias + q4 * 4);
        float self = dv * dv;
        ox = ax + self * hv.x + bv.x;
        oy = ay + self * hv.y + bv.y;
        oz = az + self * hv.z + bv.z;
        ow = aw + self * hv.w + bv.w;
        *(float4*)(out + (size_t)node * 16 + q4 * 4) = make_float4(ox, oy, oz, ow);
    }
    ss[tid * 4 + 0] = ox; sq[tid * 4 + 0] = ox * ox;
    ss[tid * 4 + 1] = oy; sq[tid * 4 + 1] = oy * oy;
    ss[tid * 4 + 2] = oz; sq[tid * 4 + 2] = oz * oz;
    ss[tid * 4 + 3] = ow; sq[tid * 4 + 3] = ow * ow;
    __syncthreads();
    if (tid < 16) {
        int qq = tid >> 2, ii = tid & 3;
        float s = 0.f, q = 0.f;
        for (int nl = 0; nl < 64; nl++) {
            s += ss[(nl * 4 + qq) * 4 + ii];
            q += sq[(nl * 4 + qq) * 4 + ii];
        }
        g_bnp1[(size_t)blockIdx.x * 16 + tid] = s;
        g_bnp2[(size_t)blockIdx.x * 16 + tid] = q;
    }
}

// ---------------- GAT gather (fp16 h2, 4-edge unrolled) + BN partials -------
// Lane owns half2 q*32+lane, head = q. Lanes 0-15 compute exp for 4 edges:
// edge = lane>>2, head = lane&3. den[h] = lanes h, h+4, h+8, h+12 (+self).
__global__ void gat_gather_bn(const __half2* __restrict__ h2, const float* __restrict__ bg,
                              float* __restrict__ out) {
    __shared__ float ss[512], sq[512];
    int tid = threadIdx.x, w = tid >> 5, lane = tid & 31;
    int node = blockIdx.x * 8 + w;
    float4 adv = *(const float4*)(g_ald + (size_t)node * 4);
    float4 asv = *(const float4*)(g_als + (size_t)node * 4);
    float ad[4] = {adv.x, adv.y, adv.z, adv.w};
    float eself[4];
    {
        float as_[4] = {asv.x, asv.y, asv.z, asv.w};
#pragma unroll
        for (int hh = 0; hh < 4; hh++) {
            float lg = as_[hh] + ad[hh];
            eself[hh] = lg > 0.f ? lg : 0.2f * lg;
        }
    }
    int s0 = g_rowstart[node], s1 = g_rowstart[node + 1];
    // pass A: per-head max
    float m[4] = {eself[0], eself[1], eself[2], eself[3]};
    for (int p = s0 + lane; p < s1; p += 32) {
        int s = __float_as_int(g_epack[p].x);
        float4 a = *(const float4*)(g_als + (size_t)s * 4);
        float lg;
        lg = a.x + ad[0]; m[0] = fmaxf(m[0], lg > 0.f ? lg : 0.2f * lg);
        lg = a.y + ad[1]; m[1] = fmaxf(m[1], lg > 0.f ? lg : 0.2f * lg);
        lg = a.z + ad[2]; m[2] = fmaxf(m[2], lg > 0.f ? lg : 0.2f * lg);
        lg = a.w + ad[3]; m[3] = fmaxf(m[3], lg > 0.f ? lg : 0.2f * lg);
    }
#pragma unroll
    for (int hh = 0; hh < 4; hh++)
#pragma unroll
        for (int off = 16; off > 0; off >>= 1)
            m[hh] = fmaxf(m[hh], __shfl_xor_sync(0xffffffffu, m[hh], off));

    int h4 = lane & 3;
    float adL = ad[0], mL = m[0];
    if (h4 == 1) { adL = ad[1]; mL = m[1]; }
    else if (h4 == 2) { adL = ad[2]; mL = m[2]; }
    else if (h4 == 3) { adL = ad[3]; mL = m[3]; }

    float2 acc[4];
#pragma unroll
    for (int q = 0; q < 4; q++) acc[q] = make_float2(0.f, 0.f);
    float denL = 0.f;  // lanes 0-15 accumulate
    int p = s0;
    for (; p + 4 <= s1; p += 4) {
        int sA = __float_as_int(g_epack[p].x);
        int sB = __float_as_int(g_epack[p + 1].x);
        int sC = __float_as_int(g_epack[p + 2].x);
        int sD = __float_as_int(g_epack[p + 3].x);
        float ee = 0.f;
        if (lane < 16) {
            int eidx = lane >> 2;
            int sN = (eidx == 0) ? sA : (eidx == 1) ? sB : (eidx == 2) ? sC : sD;
            float a = g_als[(size_t)sN * 4 + h4];
            float lg = a + adL;
            lg = lg > 0.f ? lg : 0.2f * lg;
            ee = __expf(lg - mL);
            denL += ee;
        }
        const __half2* hpA = h2 + (size_t)sA * 128;
        const __half2* hpB = h2 + (size_t)sB * 128;
        const __half2* hpC = h2 + (size_t)sC * 128;
        const __half2* hpD = h2 + (size_t)sD * 128;
        __half2 vA[4], vB[4], vC[4], vD[4];
#pragma unroll
        for (int q = 0; q < 4; q++) {
            vA[q] = hpA[q * 32 + lane]; vB[q] = hpB[q * 32 + lane];
            vC[q] = hpC[q * 32 + lane]; vD[q] = hpD[q * 32 + lane];
        }
#pragma unroll
        for (int q = 0; q < 4; q++) {
            float eA = __shfl_sync(0xffffffffu, ee, q);
            float eB = __shfl_sync(0xffffffffu, ee, 4 + q);
            float eC = __shfl_sync(0xffffffffu, ee, 8 + q);
            float eD = __shfl_sync(0xffffffffu, ee, 12 + q);
            float2 f;
            f = __half22float2(vA[q]);
            acc[q].x = fmaf(eA, f.x, acc[q].x); acc[q].y = fmaf(eA, f.y, acc[q].y);
            f = __half22float2(vB[q]);
            acc[q].x = fmaf(eB, f.x, acc[q].x); acc[q].y = fmaf(eB, f.y, acc[q].y);
            f = __half22float2(vC[q]);
            acc[q].x = fmaf(eC, f.x, acc[q].x); acc[q].y = fmaf(eC, f.y, acc[q].y);
            f = __half22float2(vD[q]);
            acc[q].x = fmaf(eD, f.x, acc[q].x); acc[q].y = fmaf(eD, f.y, acc[q].y);
        }
    }
    for (; p < s1; p++) {
        int sA = __float_as_int(g_epack[p].x);
        float ee = 0.f;
        if (lane < 4) {
            float a = g_als[(size_t)sA * 4 + h4];
            float lg = a + adL;
            lg = lg > 0.f ? lg : 0.2f * lg;
            ee = __expf(lg - mL);
            denL += ee;
        }
        const __half2* hpA = h2 + (size_t)sA * 128;
#pragma unroll
        for (int q = 0; q < 4; q++) {
            float eA = __shfl_sync(0xffffffffu, ee, q);
            float2 fA = __half22float2(hpA[q * 32 + lane]);
            acc[q].x = fmaf(eA, fA.x, acc[q].x);
            acc[q].y = fmaf(eA, fA.y, acc[q].y);
        }
    }
    float es[4], den[4];
#pragma unroll
    for (int hh = 0; hh < 4; hh++) {
        es[hh] = __expf(eself[hh] - m[hh]);
        den[hh] = __shfl_sync(0xffffffffu, denL, hh)
                + __shfl_sync(0xffffffffu, denL, hh + 4)
                + __shfl_sync(0xffffffffu, denL, hh + 8)
                + __shfl_sync(0xffffffffu, denL, hh + 12) + es[hh];
    }
    const __half2* hd = h2 + (size_t)node * 128;
    float o0 = 0.f, o1 = 0.f;
#pragma unroll
    for (int q = 0; q < 4; q++) {
        float2 fd = __half22float2(hd[q * 32 + lane]);
        float inv = 1.0f / den[q];
        o0 += (acc[q].x + es[q] * fd.x) * inv;
        o1 += (acc[q].y + es[q] * fd.y) * inv;
    }
    int c = 2 * lane;
    float t0 = 0.25f * o0 + bg[c];
    float t1 = 0.25f * o1 + bg[c + 1];
    *(float2*)(out + (size_t)node * 64 + c) = make_float2(t0, t1);
    ss[w * 64 + c] = t0;     sq[w * 64 + c] = t0 * t0;
    ss[w * 64 + c + 1] = t1; sq[w * 64 + c + 1] = t1 * t1;
    __syncthreads();
    if (tid < 64) {
        float s = 0.f, q = 0.f;
#pragma unroll
        for (int w2 = 0; w2 < 8; w2++) { s += ss[w2 * 64 + tid]; q += sq[w2 * 64 + tid]; }
        g_bnp1[(size_t)blockIdx.x * 64 + tid] = s;
        g_bnp2[(size_t)blockIdx.x * 64 + tid] = q;
    }
}

// ---------------- host ----------------
static inline int cdiv(int a, int b) { return (a + b - 1) / b; }

extern "C" void kernel_launch(void* const* d_in, const int* in_sizes, int n_in,
                              void* d_out, int out_size) {
    const float* x    = (const float*)d_in[0];
    const void*  edges = d_in[1];
    const float* b1   = (const float*)d_in[3];
    const float* g1   = (const float*)d_in[4];
    const float* be1  = (const float*)d_in[5];
    const float* Wg   = (const float*)d_in[6];
    const float* a_src = (const float*)d_in[7];
    const float* a_dst = (const float*)d_in[8];
    const float* bg   = (const float*)d_in[9];
    const float* g2   = (const float*)d_in[10];
    const float* be2  = (const float*)d_in[11];
    const float* b3   = (const float*)d_in[13];
    const float* g3   = (const float*)d_in[14];
    const float* be3  = (const float*)d_in[15];
    const float* W4   = (const float*)d_in[16];
    const float* b4   = (const float*)d_in[17];
    const float* r1b  = (const float*)d_in[19];
    const float* r2b  = (const float*)d_in[21];
    const float* r3b  = (const float*)d_in[23];
    const float* pb   = (const float*)d_in[25];
    float* out = (float*)d_out;

    float *h, *t, *x2, *xr, *res, *x3, *x4, *wr, *w2c, *w3c;
    cudaGetSymbolAddress((void**)&h,   g_h);
    cudaGetSymbolAddress((void**)&t,   g_t);
    cudaGetSymbolAddress((void**)&x2,  g_x2);
    cudaGetSymbolAddress((void**)&xr,  g_xr);
    cudaGetSymbolAddress((void**)&res, g_res);
    cudaGetSymbolAddress((void**)&x3,  g_x3);
    cudaGetSymbolAddress((void**)&x4,  g_x4);
    cudaGetSymbolAddress((void**)&wr,  g_wr);
    cudaGetSymbolAddress((void**)&w2c, g_w2comb);
    cudaGetSymbolAddress((void**)&w3c, g_w3comb);

    static cudaStream_t s1 = nullptr;
    static cudaEvent_t evFork = nullptr, evCSR = nullptr, evXR = nullptr, evG1 = nullptr;
    if (s1 == nullptr) {
        cudaStreamCreateWithFlags(&s1, cudaStreamNonBlocking);
        cudaEventCreateWithFlags(&evFork, cudaEventDisableTiming);
        cudaEventCreateWithFlags(&evCSR,  cudaEventDisableTiming);
        cudaEventCreateWithFlags(&evXR,   cudaEventDisableTiming);
        cudaEventCreateWithFlags(&evG1,   cudaEventDisableTiming);
        const int SMEMB_ = SMEM_WORDS * 4;
        cudaFuncSetAttribute(tf32_gemm_ca<0>,
                             cudaFuncAttributeMaxDynamicSharedMemorySize, SMEMB_);
        cudaFuncSetAttribute(tf32_gemm_ca<1>,
                             cudaFuncAttributeMaxDynamicSharedMemorySize, SMEMB_);
        cudaFuncSetAttribute(tf32_gemm_ca<2>,
                             cudaFuncAttributeMaxDynamicSharedMemorySize, SMEMB_);
        cudaFuncSetAttribute(tf32_gemm_ca<3>,
                             cudaFuncAttributeMaxDynamicSharedMemorySize, SMEMB_);
    }
    const int SMEMB = SMEM_WORDS * 4;  // 107520

    const float invN = 1.0f / (float)NN;
    const int MB = cdiv(NN, 128);  // 391

    float* wW1  = wr + 0;
    float* wr1W = wr + 65536;
    float* wpW  = wr + 215040;

    // ---- main-stream prep; CSR chain concurrent on s1 ----
    cudaEventRecord(evFork, 0);
    round_weights<<<214, 256>>>((const float4*)d_in[2], (const float4*)d_in[18],
                                (const float4*)d_in[6], (const float4*)d_in[20],
                                (const float4*)d_in[12], (const float4*)d_in[22],
                                (const float4*)d_in[24]);
    alpha_fold<<<1, 256>>>(Wg, a_src, a_dst);
    build_w2comb<<<384, 256>>>();
    build_w3comb<<<8, 256>>>();
    round_x<<<12500, 256>>>((const float4*)x);
    cudaEventRecord(evXR, 0);
    tf32_gemm_ca<1><<<dim3(2, MB), 256, SMEMB>>>(
        xr, wW1, nullptr, h, nullptr, NN, 256, 256);   // h in fp16

    cudaStreamWaitEvent(s1, evFork, 0);
    detect_kernel<<<1, 1, 0, s1>>>(edges);
    zero_indeg<<<cdiv(NN, 256), 256, 0, s1>>>();
    csr_count<<<cdiv(NE, 256), 256, 0, s1>>>(edges);
    scan1<<<NB196, 256, 0, s1>>>();
    scan2<<<1, 256, 0, s1>>>();
    scan3<<<NB196, 256, 0, s1>>>();
    csr_place<<<cdiv(NE, 256), 256, 0, s1>>>(edges);
    cudaEventRecord(evCSR, s1);

    // ---- Stage 1: gather+BN on main; r1W GEMM concurrently on s1 ----
    cudaStreamWaitEvent(0, evCSR, 0);
    gcn_gather_bn256<<<GB1, 256>>>((const __half2*)h, b1, t);
    cudaStreamWaitEvent(s1, evXR, 0);
    tf32_gemm_ca<0><<<dim3(2, MB), 256, SMEMB, s1>>>(
        xr, wr1W, r1b, res, nullptr, NN, 256, 256);
    cudaEventRecord(evG1, s1);
    bn_reduce<256><<<256, 256>>>(GB1, invN);
    cudaStreamWaitEvent(0, evG1, 0);
    fuse_res<256, true><<<12500, 256>>>((const float4*)t, (const float4*)res, g1, be1,
                                        (float4*)x2, NN * 64);

    // ---- Stage 2: mega-GEMM [Wg|r2W|Ws|Wd] -> h(fp16), res, als, ald ----
    tf32_gemm_ca<2><<<dim3(3, MB), 256, SMEMB>>>(
        x2, w2c, r2b, h, res, NN, 384, 256);
    gat_gather_bn<<<GB1, 256>>>((const __half2*)h, bg, t);
    bn_reduce<64><<<64, 256>>>(GB1, invN);
    fuse_res<64, true><<<3125, 256>>>((const float4*)t, (const float4*)res, g2, be2,
                                      (float4*)x3, NN * 16);

    // ---- Stage 3: merged [W3|r3W] GEMM -> h16(float), res16 ----
    tf32_gemm_ca<3><<<dim3(1, MB), 256, SMEMB>>>(
        x3, w3c, r3b, h, res, NN, 32, 64);
    gcn_gather16_bn<<<GB3, 256>>>(h, b3, t);
    bn_reduce<16><<<16, 256>>>(GB3, invN);
    fuse_res<16, false><<<782, 256>>>((const float4*)t, (const float4*)res, g3, be3,
                                      (float4*)x4, NN * 4);

    // ---- Stage 4: GCN(16->64) fp16, then final linear ----
    gemm_k16<<<NB196, 256>>>(x4, W4, (__half2*)h);
    gcn_gather64<<<cdiv(NN * 32, 256), 256>>>((const __half2*)h, b4, t);
    tf32_gemm_ca<0><<<dim3(1, MB), 256, SMEMB>>>(
        t, wpW, pb, out, nullptr, NN, 64, 64);
}

// round 16
// speedup vs baseline: 3.0748x; 1.1052x over previous
#include <cuda_runtime.h>
#include <cuda_fp16.h>
#include <cstdint>

#define NN 50000
#define NE 800000
#define NB196 196   // ceil(NN/256)
#define GB1 6250    // gather blocks, stages 1/2 (NN*32/256)
#define GB3 782     // ceil(NN*4/256)
#define WRTOT 219136

// ---------------- device scratch (static, no runtime alloc) ----------------
__device__ float g_h  [NN * 256];   // stages 1-2 & 4: reinterpreted as __half
__device__ float g_t  [NN * 256];
__device__ float g_x2 [NN * 256];   // stage-2 A operand (fp16)
__device__ float g_xr [NN * 256];   // x as fp16
__device__ float g_res[NN * 256];   // residual fp32; stage-4: th fp16
__device__ float g_x3 [NN * 64];    // stage-3 A operand (fp16)
__device__ float g_x4 [NN * 16];
__device__ float g_wr [WRTOT];      // packed fp16 weights (half2)
__device__ float g_ws [256 * 4];
__device__ float g_wd [256 * 4];
__device__ float g_dinv[NN];
__device__ int   g_indeg[NN];
__device__ int   g_rowstart[NN + 1];
__device__ int   g_cursor[NN];
__device__ float2 g_epack[NE];
__device__ int   g_scanpart[NN];
__device__ int   g_blocksum[NB196];
__device__ int   g_blockoff[NB196];
__device__ float g_als[NN * 4];
__device__ float g_ald[NN * 4];
__device__ float g_bnp1[GB1 * 256];
__device__ float g_bnp2[GB1 * 256];
__device__ float g_mu  [256];
__device__ float g_rstd[256];
__device__ int   g_e64;

// ---------------- edge dtype detect ----------------
__global__ void detect_kernel(const void* edges) {
    const int2* q = (const int2*)edges;
    int all0 = 1;
    for (int k = 0; k < 64; k++) {
        if (q[k * 12497 + 3].y != 0) { all0 = 0; break; }
    }
    g_e64 = all0;
}

__global__ void zero_indeg() {
    int i = blockIdx.x * blockDim.x + threadIdx.x;
    if (i < NN) g_indeg[i] = 0;
}

__global__ void csr_count(const void* edges) {
    int e = blockIdx.x * blockDim.x + threadIdx.x;
    if (e >= NE) return;
    int d;
    if (g_e64) d = (int)((const long long*)edges)[NE + e];
    else       d = ((const int*)edges)[NE + e];
    atomicAdd(&g_indeg[d], 1);
}

// ---------------- parallel exclusive scan over indeg ------------------------
__global__ void scan1() {
    int b = blockIdx.x, t = threadIdx.x;
    int i = b * 256 + t;
    int d = (i < NN) ? g_indeg[i] : 0;
    int lane = t & 31, w = t >> 5;
    int v = d;
#pragma unroll
    for (int off = 1; off < 32; off <<= 1) {
        int u = __shfl_up_sync(0xffffffffu, v, off);
        if (lane >= off) v += u;
    }
    __shared__ int ws[8];
    if (lane == 31) ws[w] = v;
    __syncthreads();
    if (t == 0) {
        int run = 0;
        for (int j = 0; j < 8; j++) { int x = ws[j]; ws[j] = run; run += x; }
    }
    __syncthreads();
    v += ws[w];
    if (i < NN) g_scanpart[i] = v;
    if (t == 255) g_blocksum[b] = v;
}

__global__ void scan2() {
    int t = threadIdx.x;
    int d = (t < NB196) ? g_blocksum[t] : 0;
    int lane = t & 31, w = t >> 5;
    int v = d;
#pragma unroll
    for (int off = 1; off < 32; off <<= 1) {
        int u = __shfl_up_sync(0xffffffffu, v, off);
        if (lane >= off) v += u;
    }
    __shared__ int ws[8];
    if (lane == 31) ws[w] = v;
    __syncthreads();
    if (t == 0) {
        int run = 0;
        for (int j = 0; j < 8; j++) { int x = ws[j]; ws[j] = run; run += x; }
    }
    __syncthreads();
    v += ws[w];
    if (t < NB196) g_blockoff[t] = v - d;
}

__global__ void scan3() {
    int i = blockIdx.x * blockDim.x + threadIdx.x;
    if (i < NN) {
        int deg = g_indeg[i];
        int excl = g_blockoff[blockIdx.x] + g_scanpart[i] - deg;
        g_rowstart[i] = excl;
        g_cursor[i] = excl;
        g_dinv[i] = rsqrtf((float)deg + 1.0f);
    }
    if (i == 0) g_rowstart[NN] = NE;
}

__global__ void csr_place(const void* edges) {
    int e = blockIdx.x * blockDim.x + threadIdx.x;
    if (e >= NE) return;
    int s, d;
    if (g_e64) {
        s = (int)((const long long*)edges)[e];
        d = (int)((const long long*)edges)[NE + e];
    } else {
        s = ((const int*)edges)[e];
        d = ((const int*)edges)[NE + e];
    }
    int pos = atomicAdd(&g_cursor[d], 1);
    g_epack[pos] = make_float2(__int_as_float(s), g_dinv[s] * g_dinv[d]);
}

// ---------------- fp16 conversions / packed weights -------------------------
__global__ void x_tohalf(const float4* __restrict__ x) {
    int i = blockIdx.x * 256 + threadIdx.x;
    if (i >= NN * 64) return;
    float4 v = x[i];
    __half2* o = (__half2*)g_xr;
    o[i * 2]     = __floats2half2_rn(v.x, v.y);
    o[i * 2 + 1] = __floats2half2_rn(v.z, v.w);
}

// fold GAT attention vectors through Wg (exact)
__global__ void alpha_fold(const float* __restrict__ Wg, const float* __restrict__ a_s,
                           const float* __restrict__ a_d) {
    int k = threadIdx.x;  // 256
    const float* wrow = Wg + (size_t)k * 256;
#pragma unroll
    for (int hh = 0; hh < 4; hh++) {
        float s = 0.f, d = 0.f;
#pragma unroll 8
        for (int dd = 0; dd < 64; dd++) {
            float w = wrow[hh * 64 + dd];
            s = fmaf(w, a_s[hh * 64 + dd], s);
            d = fmaf(w, a_d[hh * 64 + dd], d);
        }
        g_ws[k * 4 + hh] = s;
        g_wd[k * 4 + hh] = d;
    }
}

__device__ __forceinline__ float w2val(const float* Wg, const float* r2W, int k, int c) {
    if (c < 256) return Wg[(size_t)k * 256 + c];
    if (c < 320) return r2W[(size_t)k * 64 + (c - 256)];
    if (c < 324) return g_ws[k * 4 + (c - 320)];
    if (c < 328) return g_wd[k * 4 + (c - 324)];
    return 0.f;
}

// pack all B weights as half2 k-pair interleaved: Bp[kp][c]=(W[2kp][c],W[2kp+1][c])
// offsets in half2: W1p=0, r1Wp=32768, w2p=65536, w3p=114688, pWp=115712; total 117760
__global__ void build_wpack(const float* W1, const float* r1W, const float* Wg,
                            const float* r2W, const float* W3, const float* r3W,
                            const float* pW) {
    int i = blockIdx.x * 256 + threadIdx.x;
    if (i >= 117760) return;
    __half2* out = (__half2*)g_wr;
    float lo, hi;
    if (i < 32768) {
        int kp = i >> 8, c = i & 255;
        lo = W1[(size_t)(2 * kp) * 256 + c]; hi = W1[(size_t)(2 * kp + 1) * 256 + c];
    } else if (i < 65536) {
        int j = i - 32768, kp = j >> 8, c = j & 255;
        lo = r1W[(size_t)(2 * kp) * 256 + c]; hi = r1W[(size_t)(2 * kp + 1) * 256 + c];
    } else if (i < 114688) {
        int j = i - 65536, kp = j / 384, c = j % 384;
        lo = w2val(Wg, r2W, 2 * kp, c); hi = w2val(Wg, r2W, 2 * kp + 1, c);
    } else if (i < 115712) {
        int j = i - 114688, kp = j >> 5, c = j & 31;
        lo = (c < 16) ? W3[(size_t)(2 * kp) * 16 + c] : r3W[(size_t)(2 * kp) * 16 + c - 16];
        hi = (c < 16) ? W3[(size_t)(2 * kp + 1) * 16 + c] : r3W[(size_t)(2 * kp + 1) * 16 + c - 16];
    } else {
        int j = i - 115712, kp = j >> 6, c = j & 63;
        lo = pW[(size_t)(2 * kp) * 64 + c]; hi = pW[(size_t)(2 * kp + 1) * 64 + c];
    }
    out[i] = __floats2half2_rn(lo, hi);
}

// ---------------- BN partial reduce ----------------------------------------
template <int C>
__global__ void bn_reduce(int nblocks, float invN) {
    int c = blockIdx.x, t = threadIdx.x;
    double s = 0.0, q = 0.0;
    for (int b = t; b < nblocks; b += 256) {
        s += (double)g_bnp1[(size_t)b * C + c];
        q += (double)g_bnp2[(size_t)b * C + c];
    }
    __shared__ double sh[256], sh2[256];
    sh[t] = s; sh2[t] = q;
    __syncthreads();
    for (int off = 128; off; off >>= 1) {
        if (t < off) { sh[t] += sh[t + off]; sh2[t] += sh2[t + off]; }
        __syncthreads();
    }
    if (t == 0) {
        double m = sh[0] * (double)invN;
        double v = sh2[0] * (double)invN - m * m;
        g_mu[c] = (float)m;
        g_rstd[c] = rsqrtf((float)v + 1e-5f);
    }
}

// ---------------- BN+leaky+residual fuse ------------------------------------
template <int C>
__global__ void fuse_res_h(const float4* __restrict__ t, const float4* __restrict__ res,
                           const float* __restrict__ g, const float* __restrict__ be,
                           __half2* __restrict__ out, int n4) {
    int i = blockIdx.x * 256 + threadIdx.x;
    if (i >= n4) return;
    int c0 = (i * 4) & (C - 1);
    float4 tv = t[i], rv = res[i];
    float u, ox, oy, oz, ow;
    u = (tv.x - g_mu[c0    ]) * g_rstd[c0    ] * g[c0    ] + be[c0    ];
    ox = (u > 0.f ? u : 0.01f * u) + rv.x;
    u = (tv.y - g_mu[c0 + 1]) * g_rstd[c0 + 1] * g[c0 + 1] + be[c0 + 1];
    oy = (u > 0.f ? u : 0.01f * u) + rv.y;
    u = (tv.z - g_mu[c0 + 2]) * g_rstd[c0 + 2] * g[c0 + 2] + be[c0 + 2];
    oz = (u > 0.f ? u : 0.01f * u) + rv.z;
    u = (tv.w - g_mu[c0 + 3]) * g_rstd[c0 + 3] * g[c0 + 3] + be[c0 + 3];
    ow = (u > 0.f ? u : 0.01f * u) + rv.w;
    out[i * 2]     = __floats2half2_rn(ox, oy);
    out[i * 2 + 1] = __floats2half2_rn(oz, ow);
}

template <int C>
__global__ void fuse_res_f(const float4* __restrict__ t, const float4* __restrict__ res,
                           const float* __restrict__ g, const float* __restrict__ be,
                           float4* __restrict__ out, int n4) {
    int i = blockIdx.x * 256 + threadIdx.x;
    if (i >= n4) return;
    int c0 = (i * 4) & (C - 1);
    float4 tv = t[i], rv = res[i];
    float4 o;
    float u;
    u = (tv.x - g_mu[c0    ]) * g_rstd[c0    ] * g[c0    ] + be[c0    ];
    o.x = (u > 0.f ? u : 0.01f * u) + rv.x;
    u = (tv.y - g_mu[c0 + 1]) * g_rstd[c0 + 1] * g[c0 + 1] + be[c0 + 1];
    o.y = (u > 0.f ? u : 0.01f * u) + rv.y;
    u = (tv.z - g_mu[c0 + 2]) * g_rstd[c0 + 2] * g[c0 + 2] + be[c0 + 2];
    o.z = (u > 0.f ? u : 0.01f * u) + rv.z;
    u = (tv.w - g_mu[c0 + 3]) * g_rstd[c0 + 3] * g[c0 + 3] + be[c0 + 3];
    o.w = (u > 0.f ? u : 0.01f * u) + rv.w;
    out[i] = o;
}

// ---------------- fp16 tensor-core GEMM (m16n8k16), 3-stage cp.async --------
// A: fp16 row-major [M][K]. Bp: half2 k-pair packed [K/2][Nn].
// K % 64 == 0. Block tile 128x128x64.
// EPI=0: float C + bias. EPI=1: fp16 C. EPI=2: stage-2 routing. EPI=3: stage-3 routing.
#define AS2 36
#define BS2 136
#define ASZW (128 * AS2)     // 4608 words (half2)
#define BSZW (32 * BS2)      // 4352 words
#define STGW (ASZW + BSZW)   // 8960 words per stage
#define SMEM_WORDS (3 * STGW)  // 107520 B

template <int EPI>
__global__ __launch_bounds__(256, 2)
void hgemm_ca(const __half* __restrict__ A, const __half2* __restrict__ Bp,
              const float* __restrict__ bias, float* __restrict__ C,
              float* __restrict__ D, int M, int Nn, int K) {
    extern __shared__ uint32_t sm[];
    const int tid = threadIdx.x;
    const int warp = tid >> 5, lane = tid & 31;
    const int wm = warp >> 1, wn = warp & 1;
    const int g = lane >> 2, t4 = lane & 3;
    const int rowBase = blockIdx.y * 128;
    const int colBase = blockIdx.x * 128;
    const uint32_t sbase = (uint32_t)__cvta_generic_to_shared(sm);

    float acc[2][8][4];
#pragma unroll
    for (int mi = 0; mi < 2; mi++)
#pragma unroll
        for (int ni = 0; ni < 8; ni++)
#pragma unroll
            for (int j = 0; j < 4; j++) acc[mi][ni][j] = 0.0f;

    const int nk = K >> 6;
    const int arow = tid >> 1, ahalf = tid & 1;    // A: 2 threads/row, 16 words each
    const int bkp = tid >> 3, bc0 = tid & 7;       // B: kp row, chunk base

    auto loadTile = [&](int k0i) {
        int buf = k0i % 3;
        int k0 = k0i << 6;
        uint32_t bufb = sbase + (uint32_t)(buf * STGW) * 4u;
        int szA = (rowBase + arow < M) ? 16 : 0;
        const __half* Arow = A + (size_t)(rowBase + arow) * K + k0;
#pragma unroll
        for (int q = 0; q < 4; q++) {
            int wofs = ahalf * 16 + q * 4;   // word offset 0..28
            const __half* src = Arow + wofs * 2;
            uint32_t dst = bufb + (uint32_t)(arow * AS2 + wofs) * 4u;
            asm volatile("cp.async.cg.shared.global [%0], [%1], 16, %2;\n"
                         :: "r"(dst), "l"(src), "r"(szA));
        }
        const __half2* Brow = Bp + (size_t)((k0 >> 1) + bkp) * Nn;
#pragma unroll
        for (int q = 0; q < 4; q++) {
            int ch = q * 8 + bc0;
            int col = colBase + ch * 4;
            const __half2* src = Brow + col;
            uint32_t dst = bufb + (uint32_t)(ASZW + bkp * BS2 + ch * 4) * 4u;
            int sz = (col + 4 <= Nn) ? 16 : 0;
            asm volatile("cp.async.cg.shared.global [%0], [%1], 16, %2;\n"
                         :: "r"(dst), "l"(src), "r"(sz));
        }
        asm volatile("cp.async.commit_group;\n");
    };

    loadTile(0);
    if (nk > 1) loadTile(1);

    for (int k0i = 0; k0i < nk; k0i++) {
        if (k0i + 1 < nk) asm volatile("cp.async.wait_group 1;\n");
        else              asm volatile("cp.async.wait_group 0;\n");
        __syncthreads();
        if (k0i + 2 < nk) loadTile(k0i + 2);

        const uint32_t* As = sm + (k0i % 3) * STGW;
        const uint32_t* Bs = As + ASZW;

#pragma unroll
        for (int ks = 0; ks < 4; ks++) {
            int ko = ks * 8;
            uint32_t af[2][4];
#pragma unroll
            for (int mi = 0; mi < 2; mi++) {
                int r = wm * 32 + mi * 16;
                af[mi][0] = As[(r + g) * AS2 + ko + t4];
                af[mi][1] = As[(r + g + 8) * AS2 + ko + t4];
                af[mi][2] = As[(r + g) * AS2 + ko + t4 + 4];
                af[mi][3] = As[(r + g + 8) * AS2 + ko + t4 + 4];
            }
            uint32_t bf[8][2];
#pragma unroll
            for (int ni = 0; ni < 8; ni++) {
                int c = wn * 64 + ni * 8 + g;
                bf[ni][0] = Bs[(ko + t4) * BS2 + c];
                bf[ni][1] = Bs[(ko + t4 + 4) * BS2 + c];
            }
#pragma unroll
            for (int mi = 0; mi < 2; mi++)
#pragma unroll
                for (int ni = 0; ni < 8; ni++) {
                    asm volatile(
                        "mma.sync.aligned.m16n8k16.row.col.f32.f16.f16.f32 "
                        "{%0,%1,%2,%3}, {%4,%5,%6,%7}, {%8,%9}, {%0,%1,%2,%3};"
                        : "+f"(acc[mi][ni][0]), "+f"(acc[mi][ni][1]),
                          "+f"(acc[mi][ni][2]), "+f"(acc[mi][ni][3])
                        : "r"(af[mi][0]), "r"(af[mi][1]), "r"(af[mi][2]), "r"(af[mi][3]),
                          "r"(bf[ni][0]), "r"(bf[ni][1]));
                }
        }
    }

#pragma unroll
    for (int mi = 0; mi < 2; mi++) {
#pragma unroll
        for (int ni = 0; ni < 8; ni++) {
            int r0 = rowBase + wm * 32 + mi * 16 + g;
            int c0 = colBase + wn * 64 + ni * 8 + t4 * 2;
#pragma unroll
            for (int half = 0; half < 2; half++) {
                int r = r0 + half * 8;
                if (r >= M) continue;
                float vx = acc[mi][ni][half * 2];
                float vy = acc[mi][ni][half * 2 + 1];
                if (EPI == 0) {
                    if (c0 >= Nn) continue;
                    if (bias) { vx += bias[c0]; vy += bias[c0 + 1]; }
                    *(float2*)(C + (size_t)r * Nn + c0) = make_float2(vx, vy);
                } else if (EPI == 1) {
                    if (c0 >= Nn) continue;
                    ((__half2*)C)[(size_t)r * 128 + (c0 >> 1)] = __floats2half2_rn(vx, vy);
                } else if (EPI == 2) {
                    if (c0 >= 328) continue;
                    if (c0 < 256) {
                        ((__half2*)C)[(size_t)r * 128 + (c0 >> 1)] = __floats2half2_rn(vx, vy);
                    } else if (c0 < 320) {
                        int cc = c0 - 256;
                        *(float2*)(D + (size_t)r * 64 + cc) =
                            make_float2(vx + bias[cc], vy + bias[cc + 1]);
                    } else if (c0 < 324) {
                        *(float2*)(g_als + (size_t)r * 4 + (c0 - 320)) = make_float2(vx, vy);
                    } else {
                        *(float2*)(g_ald + (size_t)r * 4 + (c0 - 324)) = make_float2(vx, vy);
                    }
                } else {  // EPI == 3
                    if (c0 >= 32) continue;
                    if (c0 < 16) {
                        *(float2*)(C + (size_t)r * 16 + c0) = make_float2(vx, vy);
                    } else {
                        int cc = c0 - 16;
                        *(float2*)(D + (size_t)r * 16 + cc) =
                            make_float2(vx + bias[cc], vy + bias[cc + 1]);
                    }
                }
            }
        }
    }
}

// ---------------- narrow FFMA GEMM: M x 64, K=16, fp16 out (stage-4 W4) -----
__global__ void gemm_k16(const float* __restrict__ A, const float* __restrict__ B,
                         __half2* __restrict__ C) {
    __shared__ float Bs[16 * 64];
    int tid = threadIdx.x;
    ((float4*)Bs)[tid] = ((const float4*)B)[tid];
    __syncthreads();
    int row = blockIdx.x * 256 + tid;
    if (row >= NN) return;
    float a[16];
#pragma unroll
    for (int q = 0; q < 4; q++) {
        float4 v = *(const float4*)(A + (size_t)row * 16 + q * 4);
        a[q * 4] = v.x; a[q * 4 + 1] = v.y; a[q * 4 + 2] = v.z; a[q * 4 + 3] = v.w;
    }
    float acc[64];
#pragma unroll
    for (int c = 0; c < 64; c++) acc[c] = 0.0f;
#pragma unroll
    for (int k = 0; k < 16; k++) {
        float av = a[k];
#pragma unroll
        for (int c = 0; c < 64; c++) acc[c] = fmaf(av, Bs[k * 64 + c], acc[c]);
    }
#pragma unroll
    for (int q = 0; q < 32; q++)
        C[(size_t)row * 32 + q] = __floats2half2_rn(acc[q * 2], acc[q * 2 + 1]);
}

// ---------------- GCN gather (fp16 h, 2-edge unrolled) + BN partials --------
__global__ void gcn_gather_bn256(const __half2* __restrict__ h, const float* __restrict__ bias,
                                 float* __restrict__ out) {
    __shared__ float ss[2048], sq[2048];
    int tid = threadIdx.x, w = tid >> 5, lane = tid & 31;
    int node = blockIdx.x * 8 + w;
    float2 acc[4];
#pragma unroll
    for (int q = 0; q < 4; q++) acc[q] = make_float2(0.f, 0.f);
    float dv = g_dinv[node];
    int s0 = g_rowstart[node], s1 = g_rowstart[node + 1];
    int p = s0;
    for (; p + 2 <= s1; p += 2) {
        float2 e0 = g_epack[p], e1 = g_epack[p + 1];
        const __half2* h0 = h + (size_t)__float_as_int(e0.x) * 128;
        const __half2* h1 = h + (size_t)__float_as_int(e1.x) * 128;
        __half2 v0[4], v1[4];
#pragma unroll
        for (int q = 0; q < 4; q++) { v0[q] = h0[q * 32 + lane]; v1[q] = h1[q * 32 + lane]; }
#pragma unroll
        for (int q = 0; q < 4; q++) {
            float2 f0 = __half22float2(v0[q]);
            acc[q].x = fmaf(e0.y, f0.x, acc[q].x);
            acc[q].y = fmaf(e0.y, f0.y, acc[q].y);
            float2 f1 = __half22float2(v1[q]);
            acc[q].x = fmaf(e1.y, f1.x, acc[q].x);
            acc[q].y = fmaf(e1.y, f1.y, acc[q].y);
        }
    }
    if (p < s1) {
        float2 e0 = g_epack[p];
        const __half2* h0 = h + (size_t)__float_as_int(e0.x) * 128;
#pragma unroll
        for (int q = 0; q < 4; q++) {
            float2 f0 = __half22float2(h0[q * 32 + lane]);
            acc[q].x = fmaf(e0.y, f0.x, acc[q].x);
            acc[q].y = fmaf(e0.y, f0.y, acc[q].y);
        }
    }
    const __half2* hd = h + (size_t)node * 128;
    float self = dv * dv;
#pragma unroll
    for (int q = 0; q < 4; q++) {
        int c = 2 * (q * 32 + lane);
        float2 fd = __half22float2(hd[q * 32 + lane]);
        float2 bv = *(const float2*)(bias + c);
        float vx = acc[q].x + self * fd.x + bv.x;
        float vy = acc[q].y + self * fd.y + bv.y;
        *(float2*)(out + (size_t)node * 256 + c) = make_float2(vx, vy);
        ss[w * 256 + c] = vx;     sq[w * 256 + c] = vx * vx;
        ss[w * 256 + c + 1] = vy; sq[w * 256 + c + 1] = vy * vy;
    }
    __syncthreads();
    float s = 0.f, q = 0.f;
#pragma unroll
    for (int w2 = 0; w2 < 8; w2++) { s += ss[w2 * 256 + tid]; q += sq[w2 * 256 + tid]; }
    g_bnp1[(size_t)blockIdx.x * 256 + tid] = s;
    g_bnp2[(size_t)blockIdx.x * 256 + tid] = q;
}

// stage-4 gather, C=64 (fp16 h); writes fp16 th for pW GEMM
__global__ void gcn_gather64(const __half2* __restrict__ h, const float* __restrict__ bias,
                             __half2* __restrict__ out) {
    int warp = (blockIdx.x * blockDim.x + threadIdx.x) >> 5;
    int lane = threadIdx.x & 31;
    if (warp >= NN) return;
    float a0 = 0.f, a1 = 0.f;
    float dv = g_dinv[warp];
    int s0 = g_rowstart[warp], s1 = g_rowstart[warp + 1];
    int p = s0;
    for (; p + 4 <= s1; p += 4) {
        float2 e0 = g_epack[p], e1 = g_epack[p + 1];
        float2 e2 = g_epack[p + 2], e3 = g_epack[p + 3];
        __half2 v0 = h[(size_t)__float_as_int(e0.x) * 32 + lane];
        __half2 v1 = h[(size_t)__float_as_int(e1.x) * 32 + lane];
        __half2 v2 = h[(size_t)__float_as_int(e2.x) * 32 + lane];
        __half2 v3 = h[(size_t)__float_as_int(e3.x) * 32 + lane];
        float2 f;
        f = __half22float2(v0); a0 = fmaf(e0.y, f.x, a0); a1 = fmaf(e0.y, f.y, a1);
        f = __half22float2(v1); a0 = fmaf(e1.y, f.x, a0); a1 = fmaf(e1.y, f.y, a1);
        f = __half22float2(v2); a0 = fmaf(e2.y, f.x, a0); a1 = fmaf(e2.y, f.y, a1);
        f = __half22float2(v3); a0 = fmaf(e3.y, f.x, a0); a1 = fmaf(e3.y, f.y, a1);
    }
    for (; p < s1; p++) {
        float2 e0 = g_epack[p];
        float2 f = __half22float2(h[(size_t)__float_as_int(e0.x) * 32 + lane]);
        a0 = fmaf(e0.y, f.x, a0);
        a1 = fmaf(e0.y, f.y, a1);
    }
    float2 fd = __half22float2(h[(size_t)warp * 32 + lane]);
    float self = dv * dv;
    int c = 2 * lane;
    out[(size_t)warp * 32 + lane] =
        __floats2half2_rn(a0 + self * fd.x + bias[c], a1 + self * fd.y + bias[c + 1]);
}

// C=16 gather (2-edge unrolled) + BN partials
__global__ void gcn_gather16_bn(const float* __restrict__ h, const float* __restrict__ bias,
                                float* __restrict__ out) {
    __shared__ float ss[1024], sq[1024];
    int tid = threadIdx.x;
    int idx = blockIdx.x * 256 + tid;
    int node = idx >> 2, q4 = idx & 3;
    float ox = 0.f, oy = 0.f, oz = 0.f, ow = 0.f;
    if (node < NN) {
        float ax = 0.f, ay = 0.f, az = 0.f, aw = 0.f;
        float dv = g_dinv[node];
        int s0 = g_rowstart[node], s1 = g_rowstart[node + 1];
        int p = s0;
        for (; p + 2 <= s1; p += 2) {
            float2 e0 = g_epack[p], e1 = g_epack[p + 1];
            float4 v0 = *(const float4*)(h + (size_t)__float_as_int(e0.x) * 16 + q4 * 4);
            float4 v1 = *(const float4*)(h + (size_t)__float_as_int(e1.x) * 16 + q4 * 4);
            ax = fmaf(e0.y, v0.x, ax); ay = fmaf(e0.y, v0.y, ay);
            az = fmaf(e0.y, v0.z, az); aw = fmaf(e0.y, v0.w, aw);
            ax = fmaf(e1.y, v1.x, ax); ay = fmaf(e1.y, v1.y, ay);
            az = fmaf(e1.y, v1.z, az); aw = fmaf(e1.y, v1.w, aw);
        }
        if (p < s1) {
            float2 e0 = g_epack[p];
            float4 v0 = *(const float4*)(h + (size_t)__float_as_int(e0.x) * 16 + q4 * 4);
            ax = fmaf(e0.y, v0.x, ax); ay = fmaf(e0.y, v0.y, ay);
            az = fmaf(e0.y, v0.z, az); aw = fmaf(e0.y, v0.w, aw);
        }
        float4 hv = *(const float4*)(h + (size_t)node * 16 + q4 * 4);
        float4 bv = *(const float4*)(bias + q4 * 4);
        float self = dv * dv;
        ox = ax + self * hv.x + bv.x;
        oy = ay + self * hv.y + bv.y;
        oz = az + self * hv.z + bv.z;
        ow = aw + self * hv.w + bv.w;
        *(float4*)(out + (size_t)node * 16 + q4 * 4) = make_float4(ox, oy, oz, ow);
    }
    ss[tid * 4 + 0] = ox; sq[tid * 4 + 0] = ox * ox;
    ss[tid * 4 + 1] = oy; sq[tid * 4 + 1] = oy * oy;
    ss[tid * 4 + 2] = oz; sq[tid * 4 + 2] = oz * oz;
    ss[tid * 4 + 3] = ow; sq[tid * 4 + 3] = ow * ow;
    __syncthreads();
    if (tid < 16) {
        int qq = tid >> 2, ii = tid & 3;
        float s = 0.f, q = 0.f;
        for (int nl = 0; nl < 64; nl++) {
            s += ss[(nl * 4 + qq) * 4 + ii];
            q += sq[(nl * 4 + qq) * 4 + ii];
        }
        g_bnp1[(size_t)blockIdx.x * 16 + tid] = s;
        g_bnp2[(size_t)blockIdx.x * 16 + tid] = q;
    }
}

// ---------------- GAT gather (fp16 h2, 2-edge unrolled) + BN partials -------
__global__ void gat_gather_bn(const __half2* __restrict__ h2, const float* __restrict__ bg,
                              float* __restrict__ out) {
    __shared__ float ss[512], sq[512];
    int tid = threadIdx.x, w = tid >> 5, lane = tid & 31;
    int node = blockIdx.x * 8 + w;
    float4 adv = *(const float4*)(g_ald + (size_t)node * 4);
    float4 asv = *(const float4*)(g_als + (size_t)node * 4);
    float ad[4] = {adv.x, adv.y, adv.z, adv.w};
    float eself[4];
    {
        float as_[4] = {asv.x, asv.y, asv.z, asv.w};
#pragma unroll
        for (int hh = 0; hh < 4; hh++) {
            float lg = as_[hh] + ad[hh];
            eself[hh] = lg > 0.f ? lg : 0.2f * lg;
        }
    }
    int s0 = g_rowstart[node], s1 = g_rowstart[node + 1];
    float m[4] = {eself[0], eself[1], eself[2], eself[3]};
    for (int p = s0 + lane; p < s1; p += 32) {
        int s = __float_as_int(g_epack[p].x);
        float4 a = *(const float4*)(g_als + (size_t)s * 4);
        float lg;
        lg = a.x + ad[0]; m[0] = fmaxf(m[0], lg > 0.f ? lg : 0.2f * lg);
        lg = a.y + ad[1]; m[1] = fmaxf(m[1], lg > 0.f ? lg : 0.2f * lg);
        lg = a.z + ad[2]; m[2] = fmaxf(m[2], lg > 0.f ? lg : 0.2f * lg);
        lg = a.w + ad[3]; m[3] = fmaxf(m[3], lg > 0.f ? lg : 0.2f * lg);
    }
#pragma unroll
    for (int hh = 0; hh < 4; hh++)
#pragma unroll
        for (int off = 16; off > 0; off >>= 1)
            m[hh] = fmaxf(m[hh], __shfl_xor_sync(0xffffffffu, m[hh], off));

    int h4 = lane & 3;
    float adL = ad[0], mL = m[0];
    if (h4 == 1) { adL = ad[1]; mL = m[1]; }
    else if (h4 == 2) { adL = ad[2]; mL = m[2]; }
    else if (h4 == 3) { adL = ad[3]; mL = m[3]; }

    float2 acc[4];
#pragma unroll
    for (int q = 0; q < 4; q++) acc[q] = make_float2(0.f, 0.f);
    float denL = 0.f;
    int p = s0;
    for (; p + 2 <= s1; p += 2) {
        int sA = __float_as_int(g_epack[p].x);
        int sB = __float_as_int(g_epack[p + 1].x);
        float ee = 0.f;
        if (lane < 8) {
            int sN = (lane < 4) ? sA : sB;
            float a = g_als[(size_t)sN * 4 + h4];
            float lg = a + adL;
            lg = lg > 0.f ? lg : 0.2f * lg;
            ee = __expf(lg - mL);
            denL += ee;
        }
        float ehA[4], ehB[4];
#pragma unroll
        for (int q = 0; q < 4; q++) {
            ehA[q] = __shfl_sync(0xffffffffu, ee, q);
            ehB[q] = __shfl_sync(0xffffffffu, ee, 4 + q);
        }
        const __half2* hpA = h2 + (size_t)sA * 128;
        const __half2* hpB = h2 + (size_t)sB * 128;
        __half2 vA[4], vB[4];
#pragma unroll
        for (int q = 0; q < 4; q++) { vA[q] = hpA[q * 32 + lane]; vB[q] = hpB[q * 32 + lane]; }
#pragma unroll
        for (int q = 0; q < 4; q++) {
            float2 fA = __half22float2(vA[q]);
            acc[q].x = fmaf(ehA[q], fA.x, acc[q].x);
            acc[q].y = fmaf(ehA[q], fA.y, acc[q].y);
            float2 fB = __half22float2(vB[q]);
            acc[q].x = fmaf(ehB[q], fB.x, acc[q].x);
            acc[q].y = fmaf(ehB[q], fB.y, acc[q].y);
        }
    }
    if (p < s1) {
        int sA = __float_as_int(g_epack[p].x);
        float ee = 0.f;
        if (lane < 4) {
            float a = g_als[(size_t)sA * 4 + h4];
            float lg = a + adL;
            lg = lg > 0.f ? lg : 0.2f * lg;
            ee = __expf(lg - mL);
            denL += ee;
        }
        float ehA[4];
#pragma unroll
        for (int q = 0; q < 4; q++) ehA[q] = __shfl_sync(0xffffffffu, ee, q);
        const __half2* hpA = h2 + (size_t)sA * 128;
#pragma unroll
        for (int q = 0; q < 4; q++) {
            float2 fA = __half22float2(hpA[q * 32 + lane]);
            acc[q].x = fmaf(ehA[q], fA.x, acc[q].x);
            acc[q].y = fmaf(ehA[q], fA.y, acc[q].y);
        }
    }
    float es[4], den[4];
#pragma unroll
    for (int hh = 0; hh < 4; hh++) {
        es[hh] = __expf(eself[hh] - m[hh]);
        den[hh] = __shfl_sync(0xffffffffu, denL, hh)
                + __shfl_sync(0xffffffffu, denL, hh + 4) + es[hh];
    }
    const __half2* hd = h2 + (size_t)node * 128;
    float o0 = 0.f, o1 = 0.f;
#pragma unroll
    for (int q = 0; q < 4; q++) {
        float2 fd = __half22float2(hd[q * 32 + lane]);
        float inv = 1.0f / den[q];
        o0 += (acc[q].x + es[q] * fd.x) * inv;
        o1 += (acc[q].y + es[q] * fd.y) * inv;
    }
    int c = 2 * lane;
    float t0 = 0.25f * o0 + bg[c];
    float t1 = 0.25f * o1 + bg[c + 1];
    *(float2*)(out + (size_t)node * 64 + c) = make_float2(t0, t1);
    ss[w * 64 + c] = t0;     sq[w * 64 + c] = t0 * t0;
    ss[w * 64 + c + 1] = t1; sq[w * 64 + c + 1] = t1 * t1;
    __syncthreads();
    if (tid < 64) {
        float s = 0.f, q = 0.f;
#pragma unroll
        for (int w2 = 0; w2 < 8; w2++) { s += ss[w2 * 64 + tid]; q += sq[w2 * 64 + tid]; }
        g_bnp1[(size_t)blockIdx.x * 64 + tid] = s;
        g_bnp2[(size_t)blockIdx.x * 64 + tid] = q;
    }
}

// ---------------- host ----------------
static inline int cdiv(int a, int b) { return (a + b - 1) / b; }

extern "C" void kernel_launch(void* const* d_in, const int* in_sizes, int n_in,
                              void* d_out, int out_size) {
    const float* x    = (const float*)d_in[0];
    const void*  edges = d_in[1];
    const float* b1   = (const float*)d_in[3];
    const float* g1   = (const float*)d_in[4];
    const float* be1  = (const float*)d_in[5];
    const float* Wg   = (const float*)d_in[6];
    const float* a_src = (const float*)d_in[7];
    const float* a_dst = (const float*)d_in[8];
    const float* bg   = (const float*)d_in[9];
    const float* g2   = (const float*)d_in[10];
    const float* be2  = (const float*)d_in[11];
    const float* b3   = (const float*)d_in[13];
    const float* g3   = (const float*)d_in[14];
    const float* be3  = (const float*)d_in[15];
    const float* W4   = (const float*)d_in[16];
    const float* b4   = (const float*)d_in[17];
    const float* r1b  = (const float*)d_in[19];
    const float* r2b  = (const float*)d_in[21];
    const float* r3b  = (const float*)d_in[23];
    const float* pb   = (const float*)d_in[25];
    float* out = (float*)d_out;

    float *h, *t, *x2, *xr, *res, *x3, *x4, *wr;
    cudaGetSymbolAddress((void**)&h,   g_h);
    cudaGetSymbolAddress((void**)&t,   g_t);
    cudaGetSymbolAddress((void**)&x2,  g_x2);
    cudaGetSymbolAddress((void**)&xr,  g_xr);
    cudaGetSymbolAddress((void**)&res, g_res);
    cudaGetSymbolAddress((void**)&x3,  g_x3);
    cudaGetSymbolAddress((void**)&x4,  g_x4);
    cudaGetSymbolAddress((void**)&wr,  g_wr);

    static cudaStream_t s1 = nullptr;
    static cudaEvent_t evFork = nullptr, evCSR = nullptr, evXR = nullptr, evG1 = nullptr;
    if (s1 == nullptr) {
        cudaStreamCreateWithFlags(&s1, cudaStreamNonBlocking);
        cudaEventCreateWithFlags(&evFork, cudaEventDisableTiming);
        cudaEventCreateWithFlags(&evCSR,  cudaEventDisableTiming);
        cudaEventCreateWithFlags(&evXR,   cudaEventDisableTiming);
        cudaEventCreateWithFlags(&evG1,   cudaEventDisableTiming);
        const int SMEMB_ = SMEM_WORDS * 4;
        cudaFuncSetAttribute(hgemm_ca<0>,
                             cudaFuncAttributeMaxDynamicSharedMemorySize, SMEMB_);
        cudaFuncSetAttribute(hgemm_ca<1>,
                             cudaFuncAttributeMaxDynamicSharedMemorySize, SMEMB_);
        cudaFuncSetAttribute(hgemm_ca<2>,
                             cudaFuncAttributeMaxDynamicSharedMemorySize, SMEMB_);
        cudaFuncSetAttribute(hgemm_ca<3>,
                             cudaFuncAttributeMaxDynamicSharedMemorySize, SMEMB_);
    }
    const int SMEMB = SMEM_WORDS * 4;  // 107520

    const float invN = 1.0f / (float)NN;
    const int MB = cdiv(NN, 128);  // 391

    // packed fp16 weights (half2 offsets)
    const __half2* wp = (const __half2*)wr;
    const __half2* W1p  = wp + 0;
    const __half2* r1Wp = wp + 32768;
    const __half2* w2p  = wp + 65536;
    const __half2* w3p  = wp + 114688;
    const __half2* pWp  = wp + 115712;
    const __half* xh  = (const __half*)xr;
    __half* x2h = (__half*)x2;
    __half* x3h = (__half*)x3;
    __half* th  = (__half*)res;

    // ---- main-stream prep; CSR chain concurrent on s1 ----
    cudaEventRecord(evFork, 0);
    alpha_fold<<<1, 256>>>(Wg, a_src, a_dst);
    build_wpack<<<460, 256>>>((const float*)d_in[2], (const float*)d_in[18], Wg,
                              (const float*)d_in[20], (const float*)d_in[12],
                              (const float*)d_in[22], (const float*)d_in[24]);
    x_tohalf<<<12500, 256>>>((const float4*)x);
    cudaEventRecord(evXR, 0);
    hgemm_ca<1><<<dim3(2, MB), 256, SMEMB>>>(
        xh, W1p, nullptr, h, nullptr, NN, 256, 256);   // h fp16

    cudaStreamWaitEvent(s1, evFork, 0);
    detect_kernel<<<1, 1, 0, s1>>>(edges);
    zero_indeg<<<cdiv(NN, 256), 256, 0, s1>>>();
    csr_count<<<cdiv(NE, 256), 256, 0, s1>>>(edges);
    scan1<<<NB196, 256, 0, s1>>>();
    scan2<<<1, 256, 0, s1>>>();
    scan3<<<NB196, 256, 0, s1>>>();
    csr_place<<<cdiv(NE, 256), 256, 0, s1>>>(edges);
    cudaEventRecord(evCSR, s1);

    // ---- Stage 1: gather+BN on main; r1W GEMM concurrently on s1 ----
    cudaStreamWaitEvent(0, evCSR, 0);
    gcn_gather_bn256<<<GB1, 256>>>((const __half2*)h, b1, t);
    cudaStreamWaitEvent(s1, evXR, 0);
    hgemm_ca<0><<<dim3(2, MB), 256, SMEMB, s1>>>(
        xh, r1Wp, r1b, res, nullptr, NN, 256, 256);
    cudaEventRecord(evG1, s1);
    bn_reduce<256><<<256, 256>>>(GB1, invN);
    cudaStreamWaitEvent(0, evG1, 0);
    fuse_res_h<256><<<12500, 256>>>((const float4*)t, (const float4*)res, g1, be1,
                                    (__half2*)x2h, NN * 64);

    // ---- Stage 2: mega-GEMM [Wg|r2W|Ws|Wd] -> h(fp16), res, als, ald ----
    hgemm_ca<2><<<dim3(3, MB), 256, SMEMB>>>(
        x2h, w2p, r2b, h, res, NN, 384, 256);
    gat_gather_bn<<<GB1, 256>>>((const __half2*)h, bg, t);
    bn_reduce<64><<<64, 256>>>(GB1, invN);
    fuse_res_h<64><<<3125, 256>>>((const float4*)t, (const float4*)res, g2, be2,
                                  (__half2*)x3h, NN * 16);

    // ---- Stage 3: merged [W3|r3W] GEMM -> h16(float), res16 ----
    hgemm_ca<3><<<dim3(1, MB), 256, SMEMB>>>(
        x3h, w3p, r3b, h, res, NN, 32, 64);
    gcn_gather16_bn<<<GB3, 256>>>(h, b3, t);
    bn_reduce<16><<<16, 256>>>(GB3, invN);
    fuse_res_f<16><<<782, 256>>>((const float4*)t, (const float4*)res, g3, be3,
                                 (float4*)x4, NN * 4);

    // ---- Stage 4: GCN(16->64) fp16, then final linear ----
    gemm_k16<<<NB196, 256>>>(x4, W4, (__half2*)h);
    gcn_gather64<<<cdiv(NN * 32, 256), 256>>>((const __half2*)h, b4, (__half2*)th);
    hgemm_ca<0><<<dim3(1, MB), 256, SMEMB>>>(
        th, pWp, pb, out, nullptr, NN, 64, 64);
}